// round 9
// baseline (speedup 1.0000x reference)
#include <cuda_runtime.h>
#include <cuda_fp16.h>
#include <math.h>
#include <stdint.h>

// ---------------------------------------------------------------------------
// Problem constants
// ---------------------------------------------------------------------------
namespace {
constexpr int BATCH = 128;
constexpr int LC    = 64;
constexpr int LQ    = 448;
constexpr int DIM   = 768;
constexpr int SEQ   = 512;
constexpr int C4    = 3072;

constexpr long long SZ_C1 = (long long)BATCH * LC;
constexpr long long SZ_Q2 = (long long)BATCH * LQ;
constexpr long long SZ_BD = (long long)BATCH * LC * DIM;
constexpr long long SZ_S  = (long long)BATCH * LC * LQ;
constexpr long long SZ_T  = (long long)BATCH * LC * LC;
constexpr long long SZ_Y  = (long long)BATCH * LC * C4;
constexpr long long SZ_E  = SZ_BD;
constexpr long long SZ_Q  = (long long)BATCH * LQ * DIM;
constexpr long long SE    = (long long)DIM * LC;
constexpr int SEi = DIM * LC;  // 49152

constexpr long long OFF_C1  = 0;
constexpr long long OFF_Q2  = OFF_C1 + SZ_C1;
constexpr long long OFF_CW3 = OFF_Q2 + SZ_Q2;    // cw3 fp16
constexpr long long OFF_S   = OFF_CW3 + SZ_BD;
constexpr long long OFF_S1  = OFF_S  + SZ_S;     // S1 fp16
constexpr long long OFF_S2  = OFF_S1 + SZ_S;     // S2 fp16
constexpr long long OFF_A   = OFF_S2 + SZ_S;
constexpr long long OFF_T   = OFF_A  + SZ_BD;
constexpr long long OFF_BT  = OFF_T  + SZ_T;
constexpr long long OFF_Y   = OFF_BT + SZ_BD;    // Y fp16
constexpr long long OFF_E0  = OFF_Y  + SZ_Y;
constexpr long long OFF_MEAN = OFF_E0 + 8 * SZ_E;
constexpr long long OFF_RSTD = OFF_MEAN + 128;
constexpr long long OFF_PE   = OFF_RSTD + 128;
constexpr long long OFF_ACT  = OFF_PE + (long long)DIM * LC;
constexpr long long OFF_WB   = OFF_ACT + 2 * SZ_BD;
constexpr long long WB_FLOATS = ((long long)DIM * C4 + 7LL * DIM * DIM) / 2 + 64;
constexpr long long OFF_QS   = OFF_WB + WB_FLOATS;   // Q fp16 (b,448,768)
constexpr long long OFF_QT   = OFF_QS + SZ_Q;        // Q^T fp16 (b,768,448)
constexpr long long POOL_SZ  = OFF_QT + SZ_Q;
} // namespace

__device__ float g_pool[POOL_SZ];

// ---------------------------------------------------------------------------
// Family-portable tensor-core primitives
// ---------------------------------------------------------------------------
__device__ __forceinline__ uint32_t smem_u32(const void* p) {
    uint32_t a;
    asm("{ .reg .u64 t; cvta.to.shared.u64 t, %1; cvt.u32.u64 %0, t; }" : "=r"(a) : "l"(p));
    return a;
}
#define SW128(o) ((o) ^ (((o) >> 3) & 0x70))

__device__ __forceinline__ void cpa16(uint32_t dst, const void* src) {
    asm volatile("cp.async.cg.shared.global [%0], [%1], 16;" :: "r"(dst), "l"(src) : "memory");
}
__device__ __forceinline__ void cp_commit() {
    asm volatile("cp.async.commit_group;" ::: "memory");
}
__device__ __forceinline__ void cp_wait1() {
    asm volatile("cp.async.wait_group 1;" ::: "memory");
}
__device__ __forceinline__ void cp_wait0() {
    asm volatile("cp.async.wait_group 0;" ::: "memory");
}
__device__ __forceinline__ void ldsm4(uint32_t* r, uint32_t a) {
    asm volatile("ldmatrix.sync.aligned.m8n8.x4.shared.b16 {%0,%1,%2,%3}, [%4];"
        : "=r"(r[0]), "=r"(r[1]), "=r"(r[2]), "=r"(r[3]) : "r"(a));
}
__device__ __forceinline__ void mma_f16(float* d, const uint32_t* a, uint32_t b0, uint32_t b1) {
    asm volatile("mma.sync.aligned.m16n8k16.row.col.f32.f16.f16.f32 "
        "{%0,%1,%2,%3}, {%4,%5,%6,%7}, {%8,%9}, {%0,%1,%2,%3};"
        : "+f"(d[0]), "+f"(d[1]), "+f"(d[2]), "+f"(d[3])
        : "r"(a[0]), "r"(a[1]), "r"(a[2]), "r"(a[3]), "r"(b0), "r"(b1));
}

// ---------------------------------------------------------------------------
// mgemm: batch-shared-B tensor GEMM (fp16 in, fp32 accum), 2 CTA/SM
// ---------------------------------------------------------------------------
namespace {
constexpr int MT_TILE = 16384;
constexpr int MT_SMEM = 3 * 2 * MT_TILE + 1024;
constexpr int PG_TILE = 8192;
constexpr int PG_SMEM = 2 * 2 * PG_TILE + 1024;
constexpr int LN_SMEM = (768 * 65 + 1024) * 4;   // padded slab + reduction
}

template<int OMODE>
__global__ void __launch_bounds__(256, 2) mgemm_k(
    const __half* __restrict__ Af,
    const __half* __restrict__ Bf,
    float* __restrict__ O, __half* __restrict__ Oh, long long sO, int ldo,
    const float* __restrict__ bias,
    const float* __restrict__ R, long long sR,
    const float* __restrict__ plane,
    int K, int relu)
{
    extern __shared__ char dsm[];
    const uint32_t tb = (smem_u32(dsm) + 1023u) & ~1023u;

    const int tid = threadIdx.x, lane = tid & 31, wid = tid >> 5;
    const int n0 = blockIdx.x * 128;
    const int rbase = blockIdx.y * 128;
    const int wm = wid & 1, wn = wid >> 1;

    float acc[4][4][4];
#pragma unroll
    for (int a = 0; a < 4; a++)
#pragma unroll
        for (int b = 0; b < 4; b++)
#pragma unroll
            for (int c = 0; c < 4; c++) acc[a][b][c] = 0.f;

    const int nch = K / 64;

    auto copy_chunk = [&](int ci, int s) {
        const int k0 = ci * 64;
        const uint32_t tA = tb + (s * 2 + 0) * MT_TILE;
        const uint32_t tB = tb + (s * 2 + 1) * MT_TILE;
#pragma unroll
        for (int it = 0; it < 4; it++) {
            int idx = tid + it * 256;
            int r = idx >> 3, c = idx & 7;
            uint32_t doff = SW128((uint32_t)(r * 128 + c * 16));
            cpa16(tA + doff, Af + (long long)(rbase + r) * K + k0 + c * 8);
            cpa16(tB + doff, Bf + (long long)(n0 + r) * K + k0 + c * 8);
        }
    };

    copy_chunk(0, 0); cp_commit();
    copy_chunk(1, 1); cp_commit();

    const int rl = lane & 15, chalf = lane >> 4;

    for (int i = 0; i < nch; i++) {
        if (i + 1 < nch) cp_wait1(); else cp_wait0();
        __syncthreads();
        if (i + 2 < nch) { copy_chunk(i + 2, (i + 2) % 3); cp_commit(); }

        const int s = i % 3;
        const uint32_t tA = tb + (s * 2 + 0) * MT_TILE;
        const uint32_t tB = tb + (s * 2 + 1) * MT_TILE;

#pragma unroll
        for (int ks = 0; ks < 4; ks++) {
            const uint32_t coff = (uint32_t)((ks * 2 + chalf) * 16);
            uint32_t af[4][4], bf[2][4];
#pragma unroll
            for (int mt = 0; mt < 4; mt++) {
                uint32_t off = SW128((uint32_t)((wm * 64 + mt * 16 + rl) * 128) + coff);
                ldsm4(af[mt], tA + off);
            }
#pragma unroll
            for (int np = 0; np < 2; np++) {
                uint32_t off = SW128((uint32_t)((wn * 32 + np * 16 + rl) * 128) + coff);
                ldsm4(bf[np], tB + off);
            }
#pragma unroll
            for (int mt = 0; mt < 4; mt++)
#pragma unroll
                for (int np = 0; np < 2; np++)
#pragma unroll
                    for (int j = 0; j < 2; j++)
                        mma_f16(acc[mt][np * 2 + j], af[mt], bf[np][j], bf[np][j + 2]);
        }
    }

    const int b0 = blockIdx.y * 2;
#pragma unroll
    for (int mt = 0; mt < 4; mt++) {
        int row0 = wm * 64 + mt * 16 + (lane >> 2);
#pragma unroll
        for (int half = 0; half < 2; half++) {
            int row = row0 + half * 8;
            int bi = b0 + (row >> 6), l = row & 63;
            float* Ob = O ? O + (long long)bi * sO : nullptr;
            __half* Ohb = Oh ? Oh + (long long)bi * sO : nullptr;
            const float* Rb = R ? R + (long long)bi * sR : nullptr;
#pragma unroll
            for (int nn = 0; nn < 4; nn++) {
                int n = n0 + wn * 32 + nn * 8 + (lane & 3) * 2;
#pragma unroll
                for (int e = 0; e < 2; e++) {
                    float v = acc[mt][nn][half * 2 + e];
                    int nc = n + e;
                    if (bias) v += bias[nc];
                    if (relu) v = fmaxf(v, 0.f);
                    long long o = (OMODE == 1) ? ((long long)nc * 64 + l)
                                               : ((long long)l * ldo + nc);
                    if (Rb)    v += Rb[o];
                    if (plane) v += plane[o];
                    if (Ohb) Ohb[o] = __float2half(v);
                    else     Ob[o]  = v;
                }
            }
        }
    }
}

// ---------------------------------------------------------------------------
// pgemm: per-batch GEMM, fp16 in, fp32 accum. Optional fp16 out.
// ---------------------------------------------------------------------------
__global__ void __launch_bounds__(256) pgemm_k(
    const __half* __restrict__ Af, long long sA, int lda,
    const __half* __restrict__ Bf, long long sB, int ldb,
    float* __restrict__ O, __half* __restrict__ Oh, long long sO, int ldo,
    const float* __restrict__ bM, long long sbM,
    const float* __restrict__ bN, long long sbN,
    float alpha, int K)
{
    extern __shared__ char dsm[];
    const uint32_t tb = (smem_u32(dsm) + 1023u) & ~1023u;

    const int tid = threadIdx.x, lane = tid & 31, wid = tid >> 5;
    const int n0 = blockIdx.x * 64;
    const int b  = blockIdx.y;
    const int wm = wid >> 1, wn = wid & 1;

    const __half* Afb = Af + (long long)b * sA;
    const __half* Bfb = Bf + (long long)b * sB + (long long)n0 * ldb;

    float acc[4][4];
#pragma unroll
    for (int a = 0; a < 4; a++)
#pragma unroll
        for (int c = 0; c < 4; c++) acc[a][c] = 0.f;

    const int nch = K / 64;

    auto copy_chunk = [&](int ci, int s) {
        const int k0 = ci * 64;
        const uint32_t tA = tb + (s * 2 + 0) * PG_TILE;
        const uint32_t tB = tb + (s * 2 + 1) * PG_TILE;
#pragma unroll
        for (int it = 0; it < 2; it++) {
            int idx = tid + it * 256;
            int r = idx >> 3, c = idx & 7;
            uint32_t doff = SW128((uint32_t)(r * 128 + c * 16));
            cpa16(tA + doff, Afb + (long long)r * lda + k0 + c * 8);
            cpa16(tB + doff, Bfb + (long long)r * ldb + k0 + c * 8);
        }
    };

    copy_chunk(0, 0); cp_commit();

    const int rl = lane & 15, chalf = lane >> 4;

    for (int i = 0; i < nch; i++) {
        cp_wait0();
        __syncthreads();
        if (i + 1 < nch) { copy_chunk(i + 1, (i + 1) & 1); cp_commit(); }

        const int s = i & 1;
        const uint32_t tA = tb + (s * 2 + 0) * PG_TILE;
        const uint32_t tB = tb + (s * 2 + 1) * PG_TILE;

#pragma unroll
        for (int ks = 0; ks < 4; ks++) {
            const uint32_t coff = (uint32_t)((ks * 2 + chalf) * 16);
            uint32_t af[4], bf[2][4];
            {
                uint32_t off = SW128((uint32_t)((wm * 16 + rl) * 128) + coff);
                ldsm4(af, tA + off);
            }
#pragma unroll
            for (int np = 0; np < 2; np++) {
                uint32_t off = SW128((uint32_t)((wn * 32 + np * 16 + rl) * 128) + coff);
                ldsm4(bf[np], tB + off);
            }
#pragma unroll
            for (int np = 0; np < 2; np++)
#pragma unroll
                for (int j = 0; j < 2; j++)
                    mma_f16(acc[np * 2 + j], af, bf[np][j], bf[np][j + 2]);
        }
    }

    float* Ob = O ? O + (long long)b * sO : nullptr;
    __half* Ohb = Oh ? Oh + (long long)b * sO : nullptr;
    const float* bMp = bM ? bM + (long long)b * sbM : nullptr;
    const float* bNp = bN ? bN + (long long)b * sbN : nullptr;
#pragma unroll
    for (int half = 0; half < 2; half++) {
        int row = wm * 16 + (lane >> 2) + half * 8;
#pragma unroll
        for (int nn = 0; nn < 4; nn++) {
            int n = n0 + wn * 32 + nn * 8 + (lane & 3) * 2;
#pragma unroll
            for (int e = 0; e < 2; e++) {
                float v = acc[nn][half * 2 + e] * alpha;
                int nc = n + e;
                if (bMp) v += bMp[row];
                if (bNp) v += bNp[nc];
                long long o = (long long)row * ldo + nc;
                if (Ohb) Ohb[o] = __float2half(v);
                else     Ob[o]  = v;
            }
        }
    }
}

// ---------------------------------------------------------------------------
// pgemm_sm: per-batch 64x64 GEMM + fused row softmax -> fp16 attn
// grid (1, BATCH). Computes scores = alpha * A @ B^T, softmax rows, fp16 out.
// ---------------------------------------------------------------------------
__global__ void __launch_bounds__(256) pgemm_sm_k(
    const __half* __restrict__ Af, long long sA, int lda,
    const __half* __restrict__ Bf, long long sB, int ldb,
    __half* __restrict__ Oh, long long sO,
    float alpha, int K)
{
    extern __shared__ char dsm[];
    const uint32_t tb = (smem_u32(dsm) + 1023u) & ~1023u;
    __shared__ float ss[64][65];
    __shared__ float rinv[64];

    const int tid = threadIdx.x, lane = tid & 31, wid = tid >> 5;
    const int b  = blockIdx.y;
    const int wm = wid >> 1, wn = wid & 1;

    const __half* Afb = Af + (long long)b * sA;
    const __half* Bfb = Bf + (long long)b * sB;

    float acc[4][4];
#pragma unroll
    for (int a = 0; a < 4; a++)
#pragma unroll
        for (int c = 0; c < 4; c++) acc[a][c] = 0.f;

    const int nch = K / 64;

    auto copy_chunk = [&](int ci, int s) {
        const int k0 = ci * 64;
        const uint32_t tA = tb + (s * 2 + 0) * PG_TILE;
        const uint32_t tB = tb + (s * 2 + 1) * PG_TILE;
#pragma unroll
        for (int it = 0; it < 2; it++) {
            int idx = tid + it * 256;
            int r = idx >> 3, c = idx & 7;
            uint32_t doff = SW128((uint32_t)(r * 128 + c * 16));
            cpa16(tA + doff, Afb + (long long)r * lda + k0 + c * 8);
            cpa16(tB + doff, Bfb + (long long)r * ldb + k0 + c * 8);
        }
    };

    copy_chunk(0, 0); cp_commit();

    const int rl = lane & 15, chalf = lane >> 4;

    for (int i = 0; i < nch; i++) {
        cp_wait0();
        __syncthreads();
        if (i + 1 < nch) { copy_chunk(i + 1, (i + 1) & 1); cp_commit(); }

        const int s = i & 1;
        const uint32_t tA = tb + (s * 2 + 0) * PG_TILE;
        const uint32_t tB = tb + (s * 2 + 1) * PG_TILE;

#pragma unroll
        for (int ks = 0; ks < 4; ks++) {
            const uint32_t coff = (uint32_t)((ks * 2 + chalf) * 16);
            uint32_t af[4], bf[2][4];
            {
                uint32_t off = SW128((uint32_t)((wm * 16 + rl) * 128) + coff);
                ldsm4(af, tA + off);
            }
#pragma unroll
            for (int np = 0; np < 2; np++) {
                uint32_t off = SW128((uint32_t)((wn * 32 + np * 16 + rl) * 128) + coff);
                ldsm4(bf[np], tB + off);
            }
#pragma unroll
            for (int np = 0; np < 2; np++)
#pragma unroll
                for (int j = 0; j < 2; j++)
                    mma_f16(acc[np * 2 + j], af, bf[np][j], bf[np][j + 2]);
        }
    }

    // stage scores into smem
#pragma unroll
    for (int half = 0; half < 2; half++) {
        int row = wm * 16 + (lane >> 2) + half * 8;
#pragma unroll
        for (int nn = 0; nn < 4; nn++) {
            int n = wn * 32 + nn * 8 + (lane & 3) * 2;
#pragma unroll
            for (int e = 0; e < 2; e++)
                ss[row][n + e] = acc[nn][half * 2 + e] * alpha;
        }
    }
    __syncthreads();

    // row softmax (64 threads, one row each)
    if (tid < 64) {
        float m = -1e30f;
#pragma unroll 8
        for (int c = 0; c < 64; c++) m = fmaxf(m, ss[tid][c]);
        float s = 0.f;
#pragma unroll 8
        for (int c = 0; c < 64; c++) { float e = expf(ss[tid][c] - m); ss[tid][c] = e; s += e; }
        rinv[tid] = 1.f / s;
    }
    __syncthreads();

    __half* Ohb = Oh + (long long)b * sO;
#pragma unroll
    for (int it = 0; it < 16; it++) {
        int idx = tid + it * 256;
        int r = idx >> 6, c = idx & 63;
        Ohb[idx] = __float2half(ss[r][c] * rinv[r]);
    }
}

// ---------------------------------------------------------------------------
// Fused LayerNorm: stats + apply (+conv3) + transpose + fp16 out.
// One CTA per batch; whole (768,64) slab cached in padded dynamic smem.
// in (b,d,l) fp32 -> out (b,l,d) fp16
// ---------------------------------------------------------------------------
template<bool CONV>
__global__ void __launch_bounds__(512) ln_fused_k(
    const float* __restrict__ in, const float* __restrict__ lw,
    const float* __restrict__ lb, const float* __restrict__ cw,
    const float* __restrict__ cb, __half* __restrict__ out)
{
    extern __shared__ float sbuf[];          // [768*65] padded + 1024 reduction
    float* red  = sbuf + 768 * 65;
    float* red2 = red + 512;

    const int b = blockIdx.x;
    const int t = threadIdx.x;
    const float* ib = in + (long long)b * SE;

    float s = 0.f, s2 = 0.f;
    for (int i = t; i < SEi; i += 512) {
        float v = ib[i];
        int d = i >> 6, l = i & 63;
        sbuf[d * 65 + l] = v;
        s += v; s2 += v * v;
    }
    red[t] = s; red2[t] = s2;
    __syncthreads();
    for (int o = 256; o > 0; o >>= 1) {
        if (t < o) { red[t] += red[t + o]; red2[t] += red2[t + o]; }
        __syncthreads();
    }
    const float mu = red[0] / (float)SEi;
    const float rs = rsqrtf(red2[0] / (float)SEi - mu * mu + 1e-5f);

    __half* ob = out + (long long)b * SE;
    for (int i = t; i < SEi; i += 512) {
        int l = i / 768, d = i % 768;
        float a;
        if (CONV) {
            a = cb[d];
#pragma unroll
            for (int tt = 0; tt < 3; tt++) {
                int l2 = l + tt - 1;
                if (l2 < 0 || l2 >= 64) continue;
                float v = (sbuf[d * 65 + l2] - mu) * rs * lw[d * 64 + l2] + lb[d * 64 + l2];
                a = fmaf(v, cw[d * 3 + tt], a);
            }
        } else {
            a = (sbuf[d * 65 + l] - mu) * rs * lw[d * 64 + l] + lb[d * 64 + l];
        }
        ob[i] = __float2half(a);
    }
}

// ---------------------------------------------------------------------------
// Small kernels
// ---------------------------------------------------------------------------
__global__ void wconv_k(const float* __restrict__ src, int ld, int trans,
                        long long total, int KK, __half* __restrict__ out)
{
    long long idx = (long long)blockIdx.x * 256 + threadIdx.x;
    if (idx >= total) return;
    int n = (int)(idx / KK), k = (int)(idx % KK);
    float v = trans ? src[(long long)k * ld + n] : src[(long long)n * ld + k];
    out[idx] = __float2half(v);
}

__global__ void rowdot_k(const float* __restrict__ x, const float* __restrict__ w,
                         float* __restrict__ out, int rowsPerB, int rowOff)
{
    int warp = (blockIdx.x * blockDim.x + threadIdx.x) >> 5;
    int lane = threadIdx.x & 31;
    int b = warp / rowsPerB;
    int i = warp % rowsPerB;
    if (b >= BATCH) return;
    const float* src = x + ((long long)b * SEQ + rowOff + i) * DIM;
    float s = 0.f;
    for (int d = lane; d < DIM; d += 32) s += src[d] * w[d];
#pragma unroll
    for (int o = 16; o > 0; o >>= 1) s += __shfl_down_sync(0xffffffffu, s, o);
    if (lane == 0) out[warp] = s;
}

// Q region: emit both Qs (b,448,768) and Q^T (b,768,448), single read of x
__global__ void qboth_k(const float* __restrict__ x,
                        __half* __restrict__ qs, __half* __restrict__ qt)
{
    __shared__ float sm[32][33];
    int j0 = blockIdx.x * 32, d0 = blockIdx.y * 32, b = blockIdx.z;
    int tx = threadIdx.x & 31, ty = threadIdx.x >> 5;
    __half* qsb = qs + (long long)b * LQ * DIM;
#pragma unroll
    for (int r = 0; r < 4; r++) {
        int j = j0 + ty + r * 8;
        float v = x[((long long)b * SEQ + LC + j) * DIM + d0 + tx];
        sm[ty + r * 8][tx] = v;
        qsb[(long long)j * DIM + d0 + tx] = __float2half(v);
    }
    __syncthreads();
    __half* qtb = qt + (long long)b * DIM * LQ;
#pragma unroll
    for (int r = 0; r < 4; r++) {
        int d = d0 + ty + r * 8;
        qtb[(long long)d * LQ + j0 + tx] = __float2half(sm[tx][ty + r * 8]);
    }
}

// C region: emit cw3 = C*w3 (b,64,768) and C^T (b,768,64), single read
__global__ void cboth_k(const float* __restrict__ x, const float* __restrict__ w3,
                        __half* __restrict__ cw3, __half* __restrict__ ct)
{
    __shared__ float sm[32][33];
    int l0 = blockIdx.x * 32, d0 = blockIdx.y * 32, b = blockIdx.z;
    int tx = threadIdx.x & 31, ty = threadIdx.x >> 5;
    __half* cwb = cw3 + (long long)b * LC * DIM;
    float w3v = w3[d0 + tx];
#pragma unroll
    for (int r = 0; r < 4; r++) {
        int l = l0 + ty + r * 8;
        float v = x[((long long)b * SEQ + l) * DIM + d0 + tx];
        sm[ty + r * 8][tx] = v;
        cwb[(long long)l * DIM + d0 + tx] = __float2half(v * w3v);
    }
    __syncthreads();
    __half* ctb = ct + (long long)b * SE;
#pragma unroll
    for (int r = 0; r < 4; r++) {
        int d = d0 + ty + r * 8;
        ctb[(long long)d * 64 + l0 + tx] = __float2half(sm[tx][ty + r * 8]);
    }
}

// row softmax, float in -> fp16 out (front-end S, len=448)
__global__ void softmax_rows_f16_k(const float* __restrict__ in,
                                   __half* __restrict__ out, int len)
{
    long long base = (long long)blockIdx.x * len;
    int t = threadIdx.x;
    __shared__ float sh[128];
    float m = -1e30f;
    for (int i = t; i < len; i += 128) m = fmaxf(m, in[base + i]);
    sh[t] = m; __syncthreads();
    for (int o = 64; o > 0; o >>= 1) { if (t < o) sh[t] = fmaxf(sh[t], sh[t + o]); __syncthreads(); }
    m = sh[0]; __syncthreads();
    float s = 0.f;
    float loc[4];
    for (int i = t, c = 0; i < len; i += 128, c++) { float e = expf(in[base + i] - m); loc[c] = e; s += e; }
    sh[t] = s; __syncthreads();
    for (int o = 64; o > 0; o >>= 1) { if (t < o) sh[t] += sh[t + o]; __syncthreads(); }
    float inv = 1.f / sh[0];
    for (int i = t, c = 0; i < len; i += 128, c++)
        out[base + i] = __float2half(loc[c] * inv);
}

// column softmax over i of S (B,64,448) -> fp16
__global__ void softmax_cols_f16_k(const float* __restrict__ S, __half* __restrict__ out)
{
    int idx = blockIdx.x * blockDim.x + threadIdx.x;
    if (idx >= BATCH * LQ) return;
    int b = idx / LQ, j = idx % LQ;
    long long base = (long long)b * LC * LQ + j;
    float m = -1e30f;
#pragma unroll 4
    for (int i = 0; i < LC; i++) m = fmaxf(m, S[base + (long long)i * LQ]);
    float s = 0.f;
    float e[LC];
#pragma unroll 4
    for (int i = 0; i < LC; i++) { e[i] = expf(S[base + (long long)i * LQ] - m); s += e[i]; }
    float inv = 1.f / s;
#pragma unroll 4
    for (int i = 0; i < LC; i++)
        out[base + (long long)i * LQ] = __float2half(e[i] * inv);
}

// fused concat-gather + depthwise k=5 -> Y fp16 (b,l,c)
__global__ void rz_dw_fuse_k(const float* __restrict__ x, const float* __restrict__ Abuf,
                             const float* __restrict__ Btbuf,
                             const float* __restrict__ dww, const float* __restrict__ dwb,
                             __half* __restrict__ Y)
{
    int c = blockIdx.x * 256 + threadIdx.x;
    int l = blockIdx.y;
    int b = blockIdx.z;
    int g = c / DIM;
    int d = c % DIM;
    float acc = dwb[c];
#pragma unroll
    for (int t = 0; t < 5; t++) {
        int l2 = l + t - 2;
        if (l2 < 0 || l2 >= LC) continue;
        float v;
        long long xo = ((long long)b * SEQ + l2) * DIM + d;
        long long ao = ((long long)b * LC + l2) * DIM + d;
        if (g == 0)      v = x[xo];
        else if (g == 1) v = Abuf[ao];
        else if (g == 2) v = x[xo] * Abuf[ao];
        else             v = x[xo] * Btbuf[ao];
        acc = fmaf(v, dww[c * 5 + t], acc);
    }
    Y[((long long)b * LC + l) * C4 + c] = __float2half(acc);
}

__global__ void pe_init_k(float* __restrict__ pe)
{
    int idx = blockIdx.x * 256 + threadIdx.x;
    if (idx >= DIM * LC) return;
    int d = idx / LC, l = idx % LC;
    float fd = (float)d;
    bool even = (d & 1) == 0;
    float freq = even ? powf(10000.f, -fd / 768.f)
                      : -powf(10000.f, (1.f - fd) / 768.f);
    float ph = even ? 0.f : 1.57079632679489662f;
    pe[idx] = sinf((float)l * freq + ph);
}

__global__ void final_head_k(const float* __restrict__ X, const float* __restrict__ w,
                             const float* __restrict__ bias, float* __restrict__ out)
{
    int b = blockIdx.x;
    const float* p = X + (long long)b * (DIM * LC);
    float s = 0.f;
    for (int i = threadIdx.x; i < DIM * LC; i += 256) s = fmaf(p[i], w[i], s);
    __shared__ float sh[256];
    sh[threadIdx.x] = s; __syncthreads();
    for (int o = 128; o > 0; o >>= 1) {
        if (threadIdx.x < o) sh[threadIdx.x] += sh[threadIdx.x + o];
        __syncthreads();
    }
    if (threadIdx.x == 0) out[b] = 1.f / (1.f + expf(-(sh[0] + bias[0])));
}

// ---------------------------------------------------------------------------
// Host-side helpers
// ---------------------------------------------------------------------------
template<int OMODE>
static inline void run_mgemm(const __half* Af, const __half* Bf,
                             float* O, __half* Oh, long long sO, int ldo,
                             const float* bias,
                             const float* R, long long sR,
                             const float* plane,
                             int N, int K, int relu)
{
    cudaFuncSetAttribute((const void*)mgemm_k<OMODE>,
                         cudaFuncAttributeMaxDynamicSharedMemorySize, MT_SMEM);
    dim3 grid(N / 128, BATCH / 2);
    mgemm_k<OMODE><<<grid, 256, MT_SMEM>>>(Af, Bf, O, Oh, sO, ldo, bias, R, sR, plane, K, relu);
}

static inline void run_pgemm(const __half* Af, long long sA, int lda,
                             const __half* Bf, long long sB, int ldb,
                             float* O, __half* Oh, long long sO, int ldo,
                             const float* bM, long long sbM,
                             const float* bN, long long sbN,
                             float alpha, int N, int K)
{
    cudaFuncSetAttribute((const void*)pgemm_k,
                         cudaFuncAttributeMaxDynamicSharedMemorySize, PG_SMEM);
    dim3 grid(N / 64, BATCH);
    pgemm_k<<<grid, 256, PG_SMEM>>>(Af, sA, lda, Bf, sB, ldb, O, Oh, sO, ldo,
                                    bM, sbM, bN, sbN, alpha, K);
}

static inline void run_pgemm_sm(const __half* Af, long long sA, int lda,
                                const __half* Bf, long long sB, int ldb,
                                __half* Oh, long long sO, float alpha, int K)
{
    cudaFuncSetAttribute((const void*)pgemm_sm_k,
                         cudaFuncAttributeMaxDynamicSharedMemorySize, PG_SMEM);
    dim3 grid(1, BATCH);
    pgemm_sm_k<<<grid, 256, PG_SMEM>>>(Af, sA, lda, Bf, sB, ldb, Oh, sO, alpha, K);
}

template<bool CONV>
static inline void run_ln(const float* in, const float* lw, const float* lb,
                          const float* cw, const float* cb, __half* out)
{
    cudaFuncSetAttribute((const void*)ln_fused_k<CONV>,
                         cudaFuncAttributeMaxDynamicSharedMemorySize, LN_SMEM);
    ln_fused_k<CONV><<<BATCH, 512, LN_SMEM>>>(in, lw, lb, cw, cb, out);
}

struct EncW {
    const float *c1dw, *c1db, *c1pw, *c1pb;
    const float *c2dw, *c2db, *c2pw, *c2pb;
    const float *wq, *wk, *wv, *wo;
    const float *fcw, *fcb;
    const float *nbw, *nbb, *n1w, *n1b, *n2w, *n2b, *nEw, *nEb;
};

struct HfW {
    __half *rz, *c1, *c2, *fc, *qkv, *wo;
};

static void enc_block(const float* Xin,
                      float* t2, float* t3,
                      __half* qkf, __half* vT, __half* attnf,
                      float* Xout, const float* outPlane,
                      const EncW& w, const HfW& hw,
                      __half* a1, __half* a2)
{
    const float scale = 0.03608439182435161f; // 1/sqrt(768)
    const long long SQK = 64LL * 1536;
    const long long SAT = 64LL * 64;

    // ln(normb) + dwconv c1 -> a1 fp16 (b,l,d)
    run_ln<true>(Xin, w.nbw, w.nbb, w.c1dw, w.c1db, a1);
    // pw c1 (mma): relu(W@x + b) + Xin -> t2 (b,d,l)
    run_mgemm<1>(a1, hw.c1, t2, nullptr, SE, 64, w.c1pb, Xin, SE, nullptr, DIM, DIM, 1);
    // ln(norm1) + dwconv c2 -> a1
    run_ln<true>(t2, w.n1w, w.n1b, w.c2dw, w.c2db, a1);
    // pw c2 (mma) -> t3
    run_mgemm<1>(a1, hw.c2, t3, nullptr, SE, 64, w.c2pb, t2, SE, nullptr, DIM, DIM, 1);
    // ln(norm2) -> a1
    run_ln<false>(t3, w.n2w, w.n2b, nullptr, nullptr, a1);
    // q|k (mma, N=1536) -> qkf fp16 (b,l,1536)
    run_mgemm<0>(a1, hw.qkv, nullptr, qkf, SQK, 1536, nullptr, nullptr, 0, nullptr, 1536, DIM, 0);
    // v (mma, N=768, transposed) -> vT fp16 (b,768,64)
    run_mgemm<1>(a1, hw.qkv + 2LL * DIM * DIM, nullptr, vT, SE, 64,
                 nullptr, nullptr, 0, nullptr, DIM, DIM, 0);
    // scores + softmax fused (tensor, per-batch) -> attn fp16
    run_pgemm_sm(qkf, SQK, 1536, qkf + DIM, SQK, 1536, attnf, SAT, scale, DIM);
    // av = attn @ v (tensor; B = v^T) -> a2 fp16 (b,l,768)
    run_pgemm(attnf, SAT, 64, vT, SE, 64,
              nullptr, a2, SE, DIM, nullptr, 0, nullptr, 0, 1.f, DIM, LC);
    // sa = (av @ wo)^T + t3 -> t2 (mma, transposed store)
    run_mgemm<1>(a2, hw.wo, t2, nullptr, SE, 64, nullptr, t3, SE, nullptr, DIM, DIM, 0);
    // ln(norme) -> a1
    run_ln<false>(t2, w.nEw, w.nEb, nullptr, nullptr, a1);
    // fc + relu + t2 (+pe) -> Xout (mma)
    run_mgemm<1>(a1, hw.fc, Xout, nullptr, SE, 64, w.fcb, t2, SE, outPlane, DIM, DIM, 1);
}

// ---------------------------------------------------------------------------
// Entry point
// ---------------------------------------------------------------------------
extern "C" void kernel_launch(void* const* d_in, const int* in_sizes, int n_in,
                              void* d_out, int out_size)
{
    (void)in_sizes; (void)n_in; (void)out_size;
    const float* x       = (const float*)d_in[0];
    const float* Wv      = (const float*)d_in[1];
    const float* rz_dw_w = (const float*)d_in[2];
    const float* rz_dw_b = (const float*)d_in[3];
    const float* rz_pw_w = (const float*)d_in[4];
    const float* rz_pw_b = (const float*)d_in[5];
    EncW w;
    w.c1dw = (const float*)d_in[6];  w.c1db = (const float*)d_in[7];
    w.c1pw = (const float*)d_in[8];  w.c1pb = (const float*)d_in[9];
    w.c2dw = (const float*)d_in[10]; w.c2db = (const float*)d_in[11];
    w.c2pw = (const float*)d_in[12]; w.c2pb = (const float*)d_in[13];
    w.wq   = (const float*)d_in[14]; w.wk   = (const float*)d_in[15];
    w.wv   = (const float*)d_in[16]; w.wo   = (const float*)d_in[17];
    w.fcw  = (const float*)d_in[18]; w.fcb  = (const float*)d_in[19];
    w.nbw  = (const float*)d_in[20]; w.nbb  = (const float*)d_in[21];
    w.n1w  = (const float*)d_in[22]; w.n1b  = (const float*)d_in[23];
    w.n2w  = (const float*)d_in[24]; w.n2b  = (const float*)d_in[25];
    w.nEw  = (const float*)d_in[26]; w.nEb  = (const float*)d_in[27];
    const float* fcf_w = (const float*)d_in[28];
    const float* fcf_b = (const float*)d_in[29];

    float* pool = nullptr;
    cudaGetSymbolAddress((void**)&pool, g_pool);

    float* c1s  = pool + OFF_C1;
    float* q2s  = pool + OFF_Q2;
    float* S    = pool + OFF_S;
    float* Abuf = pool + OFF_A;
    float* Btb  = pool + OFF_BT;
    float* E[8];
    for (int i = 0; i < 8; i++) E[i] = pool + OFF_E0 + (long long)i * SZ_E;
    float* pe   = pool + OFF_PE;

    __half* cw3f  = (__half*)(pool + OFF_CW3);
    __half* S1f   = (__half*)(pool + OFF_S1);
    __half* S2f   = (__half*)(pool + OFF_S2);
    __half* Yf    = (__half*)(pool + OFF_Y);
    __half* Qsf   = (__half*)(pool + OFF_QS);
    __half* Qtf   = (__half*)(pool + OFF_QT);
    __half* a1    = (__half*)(pool + OFF_ACT);
    __half* a2    = a1 + SZ_BD;
    __half* qkf   = (__half*)E[4];
    __half* vT    = (__half*)E[5];
    __half* attnf = (__half*)E[6];
    __half* Tf    = (__half*)E[6];
    __half* cTf   = (__half*)E[1];

    HfW hw;
    {
        __half* p = (__half*)(pool + OFF_WB);
        hw.rz  = p; p += (long long)DIM * C4;
        hw.c1  = p; p += (long long)DIM * DIM;
        hw.c2  = p; p += (long long)DIM * DIM;
        hw.fc  = p; p += (long long)DIM * DIM;
        hw.qkv = p; p += 3LL * DIM * DIM;
        hw.wo  = p;
    }

    const long long WDD = (long long)DIM * DIM;

    pe_init_k<<<(DIM * LC + 255) / 256, 256>>>(pe);
    rowdot_k<<<(BATCH * LC * 32) / 256, 256>>>(x, Wv, c1s, LC, 0);
    rowdot_k<<<(BATCH * LQ * 32) / 256, 256>>>(x, Wv + DIM, q2s, LQ, LC);
    cboth_k<<<dim3(2, DIM / 32, BATCH), 256>>>(x, Wv + 2 * DIM, cw3f, cTf);
    qboth_k<<<dim3(LQ / 32, DIM / 32, BATCH), 256>>>(x, Qsf, Qtf);

    // S = cw3 @ Q^T + c1[:,None] + q2[None,:]   (tensor, per-batch)
    run_pgemm(cw3f, 64LL * DIM, DIM, Qsf, (long long)LQ * DIM, DIM,
              S, nullptr, (long long)LC * LQ, LQ, c1s, LC, q2s, LQ, 1.f, LQ, DIM);

    softmax_rows_f16_k<<<BATCH * LC, 128>>>(S, S1f, LQ);
    softmax_cols_f16_k<<<(BATCH * LQ + 255) / 256, 256>>>(S, S2f);

    // A = S1 @ Q (tensor; B = Q^T) -> fp32
    run_pgemm(S1f, (long long)LC * LQ, LQ, Qtf, (long long)DIM * LQ, LQ,
              Abuf, nullptr, (long long)LC * DIM, DIM, nullptr, 0, nullptr, 0, 1.f, DIM, LQ);

    // T = S1 @ S2^T (tensor) -> fp16
    run_pgemm(S1f, (long long)LC * LQ, LQ, S2f, (long long)LC * LQ, LQ,
              nullptr, Tf, (long long)LC * LC, LC, nullptr, 0, nullptr, 0, 1.f, LC, LQ);

    // Bt = T @ C (tensor; B = C^T) -> fp32
    run_pgemm(Tf, (long long)LC * LC, LC, cTf, SE, LC,
              Btb, nullptr, (long long)LC * DIM, DIM, nullptr, 0, nullptr, 0, 1.f, DIM, LC);

    // fused concat-gather + depthwise k=5 -> Y fp16 (b,l,c)
    rz_dw_fuse_k<<<dim3(C4 / 256, LC, BATCH), 256>>>(x, Abuf, Btb, rz_dw_w, rz_dw_b, Yf);

    // ---- weight conversion (fp16, n x k, k-contiguous) ----
    {
        long long trz = (long long)DIM * C4;
        int gs = (int)((WDD + 255) / 256);
        wconv_k<<<(int)((trz + 255) / 256), 256>>>(rz_pw_w, C4, 0, trz, C4, hw.rz);
        wconv_k<<<gs, 256>>>(w.c1pw, DIM, 0, WDD, DIM, hw.c1);
        wconv_k<<<gs, 256>>>(w.c2pw, DIM, 0, WDD, DIM, hw.c2);
        wconv_k<<<gs, 256>>>(w.fcw,  DIM, 0, WDD, DIM, hw.fc);
        wconv_k<<<gs, 256>>>(w.wq,   DIM, 1, WDD, DIM, hw.qkv);
        wconv_k<<<gs, 256>>>(w.wk,   DIM, 1, WDD, DIM, hw.qkv + WDD);
        wconv_k<<<gs, 256>>>(w.wv,   DIM, 1, WDD, DIM, hw.qkv + 2 * WDD);
        wconv_k<<<gs, 256>>>(w.wo,   DIM, 1, WDD, DIM, hw.wo);
    }

    // pointwise 3072 -> 768 (mma): +bias +pe -> E0 (b,d,l)
    run_mgemm<1>(Yf, hw.rz, E[0], nullptr, SE, 64, rz_pw_b, nullptr, 0, pe, DIM, C4, 0);

    // ---- two encoder blocks ----
    enc_block(E[0], E[2], E[3], qkf, vT, attnf, E[7], pe, w, hw, a1, a2);
    enc_block(E[7], E[2], E[3], qkf, vT, attnf, E[0], nullptr, w, hw, a1, a2);

    // ---- final sigmoid head ----
    final_head_k<<<BATCH, 256>>>(E[0], fcf_w, fcf_b, (float*)d_out);
}

// round 10
// speedup vs baseline: 1.9423x; 1.9423x over previous
#include <cuda_runtime.h>
#include <cuda_fp16.h>
#include <math.h>
#include <stdint.h>

// ---------------------------------------------------------------------------
// Problem constants
// ---------------------------------------------------------------------------
namespace {
constexpr int BATCH = 128;
constexpr int LC    = 64;
constexpr int LQ    = 448;
constexpr int DIM   = 768;
constexpr int SEQ   = 512;
constexpr int C4    = 3072;

constexpr long long SZ_C1 = (long long)BATCH * LC;
constexpr long long SZ_Q2 = (long long)BATCH * LQ;
constexpr long long SZ_BD = (long long)BATCH * LC * DIM;
constexpr long long SZ_S  = (long long)BATCH * LC * LQ;
constexpr long long SZ_T  = (long long)BATCH * LC * LC;
constexpr long long SZ_Y  = (long long)BATCH * LC * C4;
constexpr long long SZ_E  = SZ_BD;
constexpr long long SZ_Q  = (long long)BATCH * LQ * DIM;
constexpr long long SE    = (long long)DIM * LC;

constexpr long long OFF_C1  = 0;
constexpr long long OFF_Q2  = OFF_C1 + SZ_C1;
constexpr long long OFF_CW3 = OFF_Q2 + SZ_Q2;    // cw3 fp16
constexpr long long OFF_S   = OFF_CW3 + SZ_BD;
constexpr long long OFF_S1  = OFF_S  + SZ_S;     // S1 fp16
constexpr long long OFF_S2  = OFF_S1 + SZ_S;     // S2 fp16
constexpr long long OFF_A   = OFF_S2 + SZ_S;
constexpr long long OFF_T   = OFF_A  + SZ_BD;
constexpr long long OFF_BT  = OFF_T  + SZ_T;
constexpr long long OFF_Y   = OFF_BT + SZ_BD;    // Y fp16
constexpr long long OFF_E0  = OFF_Y  + SZ_Y;
constexpr long long OFF_MEAN = OFF_E0 + 8 * SZ_E;
constexpr long long OFF_RSTD = OFF_MEAN + 128;
constexpr long long OFF_PE   = OFF_RSTD + 128;
constexpr long long OFF_ACT  = OFF_PE + (long long)DIM * LC;
constexpr long long OFF_WB   = OFF_ACT + 2 * SZ_BD;
constexpr long long WB_FLOATS = ((long long)DIM * C4 + 7LL * DIM * DIM) / 2 + 64;
constexpr long long OFF_QS   = OFF_WB + WB_FLOATS;   // Q fp16 (b,448,768)
constexpr long long OFF_QT   = OFF_QS + SZ_Q;        // Q^T fp16 (b,768,448)
constexpr long long POOL_SZ  = OFF_QT + SZ_Q;
} // namespace

__device__ float g_pool[POOL_SZ];

// ---------------------------------------------------------------------------
// Family-portable tensor-core primitives
// ---------------------------------------------------------------------------
__device__ __forceinline__ uint32_t smem_u32(const void* p) {
    uint32_t a;
    asm("{ .reg .u64 t; cvta.to.shared.u64 t, %1; cvt.u32.u64 %0, t; }" : "=r"(a) : "l"(p));
    return a;
}
#define SW128(o) ((o) ^ (((o) >> 3) & 0x70))

__device__ __forceinline__ void cpa16(uint32_t dst, const void* src) {
    asm volatile("cp.async.cg.shared.global [%0], [%1], 16;" :: "r"(dst), "l"(src) : "memory");
}
__device__ __forceinline__ void cp_commit() {
    asm volatile("cp.async.commit_group;" ::: "memory");
}
__device__ __forceinline__ void cp_wait1() {
    asm volatile("cp.async.wait_group 1;" ::: "memory");
}
__device__ __forceinline__ void cp_wait0() {
    asm volatile("cp.async.wait_group 0;" ::: "memory");
}
__device__ __forceinline__ void ldsm4(uint32_t* r, uint32_t a) {
    asm volatile("ldmatrix.sync.aligned.m8n8.x4.shared.b16 {%0,%1,%2,%3}, [%4];"
        : "=r"(r[0]), "=r"(r[1]), "=r"(r[2]), "=r"(r[3]) : "r"(a));
}
__device__ __forceinline__ void mma_f16(float* d, const uint32_t* a, uint32_t b0, uint32_t b1) {
    asm volatile("mma.sync.aligned.m16n8k16.row.col.f32.f16.f16.f32 "
        "{%0,%1,%2,%3}, {%4,%5,%6,%7}, {%8,%9}, {%0,%1,%2,%3};"
        : "+f"(d[0]), "+f"(d[1]), "+f"(d[2]), "+f"(d[3])
        : "r"(a[0]), "r"(a[1]), "r"(a[2]), "r"(a[3]), "r"(b0), "r"(b1));
}

// ---------------------------------------------------------------------------
// mgemm: batch-shared-B tensor GEMM (fp16 in, fp32 accum), 2 CTA/SM
// ---------------------------------------------------------------------------
namespace {
constexpr int MT_TILE = 16384;
constexpr int MT_SMEM = 3 * 2 * MT_TILE + 1024;
constexpr int PG_TILE = 8192;
constexpr int PG_SMEM = 2 * 2 * PG_TILE + 1024;
}

template<int OMODE>
__global__ void __launch_bounds__(256, 2) mgemm_k(
    const __half* __restrict__ Af,
    const __half* __restrict__ Bf,
    float* __restrict__ O, __half* __restrict__ Oh, long long sO, int ldo,
    const float* __restrict__ bias,
    const float* __restrict__ R, long long sR,
    const float* __restrict__ plane,
    int K, int relu)
{
    extern __shared__ char dsm[];
    const uint32_t tb = (smem_u32(dsm) + 1023u) & ~1023u;

    const int tid = threadIdx.x, lane = tid & 31, wid = tid >> 5;
    const int n0 = blockIdx.x * 128;
    const int rbase = blockIdx.y * 128;
    const int wm = wid & 1, wn = wid >> 1;

    float acc[4][4][4];
#pragma unroll
    for (int a = 0; a < 4; a++)
#pragma unroll
        for (int b = 0; b < 4; b++)
#pragma unroll
            for (int c = 0; c < 4; c++) acc[a][b][c] = 0.f;

    const int nch = K / 64;

    auto copy_chunk = [&](int ci, int s) {
        const int k0 = ci * 64;
        const uint32_t tA = tb + (s * 2 + 0) * MT_TILE;
        const uint32_t tB = tb + (s * 2 + 1) * MT_TILE;
#pragma unroll
        for (int it = 0; it < 4; it++) {
            int idx = tid + it * 256;
            int r = idx >> 3, c = idx & 7;
            uint32_t doff = SW128((uint32_t)(r * 128 + c * 16));
            cpa16(tA + doff, Af + (long long)(rbase + r) * K + k0 + c * 8);
            cpa16(tB + doff, Bf + (long long)(n0 + r) * K + k0 + c * 8);
        }
    };

    copy_chunk(0, 0); cp_commit();
    copy_chunk(1, 1); cp_commit();

    const int rl = lane & 15, chalf = lane >> 4;

    for (int i = 0; i < nch; i++) {
        if (i + 1 < nch) cp_wait1(); else cp_wait0();
        __syncthreads();
        if (i + 2 < nch) { copy_chunk(i + 2, (i + 2) % 3); cp_commit(); }

        const int s = i % 3;
        const uint32_t tA = tb + (s * 2 + 0) * MT_TILE;
        const uint32_t tB = tb + (s * 2 + 1) * MT_TILE;

#pragma unroll
        for (int ks = 0; ks < 4; ks++) {
            const uint32_t coff = (uint32_t)((ks * 2 + chalf) * 16);
            uint32_t af[4][4], bf[2][4];
#pragma unroll
            for (int mt = 0; mt < 4; mt++) {
                uint32_t off = SW128((uint32_t)((wm * 64 + mt * 16 + rl) * 128) + coff);
                ldsm4(af[mt], tA + off);
            }
#pragma unroll
            for (int np = 0; np < 2; np++) {
                uint32_t off = SW128((uint32_t)((wn * 32 + np * 16 + rl) * 128) + coff);
                ldsm4(bf[np], tB + off);
            }
#pragma unroll
            for (int mt = 0; mt < 4; mt++)
#pragma unroll
                for (int np = 0; np < 2; np++)
#pragma unroll
                    for (int j = 0; j < 2; j++)
                        mma_f16(acc[mt][np * 2 + j], af[mt], bf[np][j], bf[np][j + 2]);
        }
    }

    const int b0 = blockIdx.y * 2;
#pragma unroll
    for (int mt = 0; mt < 4; mt++) {
        int row0 = wm * 64 + mt * 16 + (lane >> 2);
#pragma unroll
        for (int half = 0; half < 2; half++) {
            int row = row0 + half * 8;
            int bi = b0 + (row >> 6), l = row & 63;
            float* Ob = O ? O + (long long)bi * sO : nullptr;
            __half* Ohb = Oh ? Oh + (long long)bi * sO : nullptr;
            const float* Rb = R ? R + (long long)bi * sR : nullptr;
#pragma unroll
            for (int nn = 0; nn < 4; nn++) {
                int n = n0 + wn * 32 + nn * 8 + (lane & 3) * 2;
#pragma unroll
                for (int e = 0; e < 2; e++) {
                    float v = acc[mt][nn][half * 2 + e];
                    int nc = n + e;
                    if (bias) v += bias[nc];
                    if (relu) v = fmaxf(v, 0.f);
                    long long o = (OMODE == 1) ? ((long long)nc * 64 + l)
                                               : ((long long)l * ldo + nc);
                    if (Rb)    v += Rb[o];
                    if (plane) v += plane[o];
                    if (Ohb) Ohb[o] = __float2half(v);
                    else     Ob[o]  = v;
                }
            }
        }
    }
}

// ---------------------------------------------------------------------------
// pgemm: per-batch GEMM, fp16 in, fp32 accum. Optional fp16 out.
// ---------------------------------------------------------------------------
__global__ void __launch_bounds__(256) pgemm_k(
    const __half* __restrict__ Af, long long sA, int lda,
    const __half* __restrict__ Bf, long long sB, int ldb,
    float* __restrict__ O, __half* __restrict__ Oh, long long sO, int ldo,
    const float* __restrict__ bM, long long sbM,
    const float* __restrict__ bN, long long sbN,
    float alpha, int K)
{
    extern __shared__ char dsm[];
    const uint32_t tb = (smem_u32(dsm) + 1023u) & ~1023u;

    const int tid = threadIdx.x, lane = tid & 31, wid = tid >> 5;
    const int n0 = blockIdx.x * 64;
    const int b  = blockIdx.y;
    const int wm = wid >> 1, wn = wid & 1;

    const __half* Afb = Af + (long long)b * sA;
    const __half* Bfb = Bf + (long long)b * sB + (long long)n0 * ldb;

    float acc[4][4];
#pragma unroll
    for (int a = 0; a < 4; a++)
#pragma unroll
        for (int c = 0; c < 4; c++) acc[a][c] = 0.f;

    const int nch = K / 64;

    auto copy_chunk = [&](int ci, int s) {
        const int k0 = ci * 64;
        const uint32_t tA = tb + (s * 2 + 0) * PG_TILE;
        const uint32_t tB = tb + (s * 2 + 1) * PG_TILE;
#pragma unroll
        for (int it = 0; it < 2; it++) {
            int idx = tid + it * 256;
            int r = idx >> 3, c = idx & 7;
            uint32_t doff = SW128((uint32_t)(r * 128 + c * 16));
            cpa16(tA + doff, Afb + (long long)r * lda + k0 + c * 8);
            cpa16(tB + doff, Bfb + (long long)r * ldb + k0 + c * 8);
        }
    };

    copy_chunk(0, 0); cp_commit();

    const int rl = lane & 15, chalf = lane >> 4;

    for (int i = 0; i < nch; i++) {
        cp_wait0();
        __syncthreads();
        if (i + 1 < nch) { copy_chunk(i + 1, (i + 1) & 1); cp_commit(); }

        const int s = i & 1;
        const uint32_t tA = tb + (s * 2 + 0) * PG_TILE;
        const uint32_t tB = tb + (s * 2 + 1) * PG_TILE;

#pragma unroll
        for (int ks = 0; ks < 4; ks++) {
            const uint32_t coff = (uint32_t)((ks * 2 + chalf) * 16);
            uint32_t af[4], bf[2][4];
            {
                uint32_t off = SW128((uint32_t)((wm * 16 + rl) * 128) + coff);
                ldsm4(af, tA + off);
            }
#pragma unroll
            for (int np = 0; np < 2; np++) {
                uint32_t off = SW128((uint32_t)((wn * 32 + np * 16 + rl) * 128) + coff);
                ldsm4(bf[np], tB + off);
            }
#pragma unroll
            for (int np = 0; np < 2; np++)
#pragma unroll
                for (int j = 0; j < 2; j++)
                    mma_f16(acc[np * 2 + j], af, bf[np][j], bf[np][j + 2]);
        }
    }

    float* Ob = O ? O + (long long)b * sO : nullptr;
    __half* Ohb = Oh ? Oh + (long long)b * sO : nullptr;
    const float* bMp = bM ? bM + (long long)b * sbM : nullptr;
    const float* bNp = bN ? bN + (long long)b * sbN : nullptr;
#pragma unroll
    for (int half = 0; half < 2; half++) {
        int row = wm * 16 + (lane >> 2) + half * 8;
#pragma unroll
        for (int nn = 0; nn < 4; nn++) {
            int n = n0 + wn * 32 + nn * 8 + (lane & 3) * 2;
#pragma unroll
            for (int e = 0; e < 2; e++) {
                float v = acc[nn][half * 2 + e] * alpha;
                int nc = n + e;
                if (bMp) v += bMp[row];
                if (bNp) v += bNp[nc];
                long long o = (long long)row * ldo + nc;
                if (Ohb) Ohb[o] = __float2half(v);
                else     Ob[o]  = v;
            }
        }
    }
}

// ---------------------------------------------------------------------------
// pgemm_sm: per-batch 64x64 GEMM + fused row softmax -> fp16 attn
// ---------------------------------------------------------------------------
__global__ void __launch_bounds__(256) pgemm_sm_k(
    const __half* __restrict__ Af, long long sA, int lda,
    const __half* __restrict__ Bf, long long sB, int ldb,
    __half* __restrict__ Oh, long long sO,
    float alpha, int K)
{
    extern __shared__ char dsm[];
    const uint32_t tb = (smem_u32(dsm) + 1023u) & ~1023u;
    __shared__ float ss[64][65];
    __shared__ float rinv[64];

    const int tid = threadIdx.x, lane = tid & 31, wid = tid >> 5;
    const int b  = blockIdx.y;
    const int wm = wid >> 1, wn = wid & 1;

    const __half* Afb = Af + (long long)b * sA;
    const __half* Bfb = Bf + (long long)b * sB;

    float acc[4][4];
#pragma unroll
    for (int a = 0; a < 4; a++)
#pragma unroll
        for (int c = 0; c < 4; c++) acc[a][c] = 0.f;

    const int nch = K / 64;

    auto copy_chunk = [&](int ci, int s) {
        const int k0 = ci * 64;
        const uint32_t tA = tb + (s * 2 + 0) * PG_TILE;
        const uint32_t tB = tb + (s * 2 + 1) * PG_TILE;
#pragma unroll
        for (int it = 0; it < 2; it++) {
            int idx = tid + it * 256;
            int r = idx >> 3, c = idx & 7;
            uint32_t doff = SW128((uint32_t)(r * 128 + c * 16));
            cpa16(tA + doff, Afb + (long long)r * lda + k0 + c * 8);
            cpa16(tB + doff, Bfb + (long long)r * ldb + k0 + c * 8);
        }
    };

    copy_chunk(0, 0); cp_commit();

    const int rl = lane & 15, chalf = lane >> 4;

    for (int i = 0; i < nch; i++) {
        cp_wait0();
        __syncthreads();
        if (i + 1 < nch) { copy_chunk(i + 1, (i + 1) & 1); cp_commit(); }

        const int s = i & 1;
        const uint32_t tA = tb + (s * 2 + 0) * PG_TILE;
        const uint32_t tB = tb + (s * 2 + 1) * PG_TILE;

#pragma unroll
        for (int ks = 0; ks < 4; ks++) {
            const uint32_t coff = (uint32_t)((ks * 2 + chalf) * 16);
            uint32_t af[4], bf[2][4];
            {
                uint32_t off = SW128((uint32_t)((wm * 16 + rl) * 128) + coff);
                ldsm4(af, tA + off);
            }
#pragma unroll
            for (int np = 0; np < 2; np++) {
                uint32_t off = SW128((uint32_t)((wn * 32 + np * 16 + rl) * 128) + coff);
                ldsm4(bf[np], tB + off);
            }
#pragma unroll
            for (int np = 0; np < 2; np++)
#pragma unroll
                for (int j = 0; j < 2; j++)
                    mma_f16(acc[np * 2 + j], af, bf[np][j], bf[np][j + 2]);
        }
    }

#pragma unroll
    for (int half = 0; half < 2; half++) {
        int row = wm * 16 + (lane >> 2) + half * 8;
#pragma unroll
        for (int nn = 0; nn < 4; nn++) {
            int n = wn * 32 + nn * 8 + (lane & 3) * 2;
#pragma unroll
            for (int e = 0; e < 2; e++)
                ss[row][n + e] = acc[nn][half * 2 + e] * alpha;
        }
    }
    __syncthreads();

    if (tid < 64) {
        float m = -1e30f;
#pragma unroll 8
        for (int c = 0; c < 64; c++) m = fmaxf(m, ss[tid][c]);
        float s = 0.f;
#pragma unroll 8
        for (int c = 0; c < 64; c++) { float e = expf(ss[tid][c] - m); ss[tid][c] = e; s += e; }
        rinv[tid] = 1.f / s;
    }
    __syncthreads();

    __half* Ohb = Oh + (long long)b * sO;
#pragma unroll
    for (int it = 0; it < 16; it++) {
        int idx = tid + it * 256;
        int r = idx >> 6, c = idx & 63;
        Ohb[idx] = __float2half(ss[r][c] * rinv[r]);
    }
}

// ---------------------------------------------------------------------------
// LayerNorm (R8 proven-fast scheme): stats kernel + coalesced apply kernels
// ---------------------------------------------------------------------------
__global__ void ln_stats_k(const float* __restrict__ in, float* __restrict__ mean,
                           float* __restrict__ rstd)
{
    int b = blockIdx.x;
    const float4* p = reinterpret_cast<const float4*>(in + (long long)b * (DIM * LC));
    float s = 0.f, s2 = 0.f;
    for (int i = threadIdx.x; i < DIM * LC / 4; i += 512) {
        float4 v = p[i];
        s += v.x + v.y + v.z + v.w;
        s2 += v.x * v.x + v.y * v.y + v.z * v.z + v.w * v.w;
    }
    __shared__ float sh[512], sh2[512];
    sh[threadIdx.x] = s; sh2[threadIdx.x] = s2; __syncthreads();
    for (int o = 256; o > 0; o >>= 1) {
        if (threadIdx.x < o) { sh[threadIdx.x] += sh[threadIdx.x + o]; sh2[threadIdx.x] += sh2[threadIdx.x + o]; }
        __syncthreads();
    }
    if (threadIdx.x == 0) {
        float m = sh[0] / (float)(DIM * LC);
        float var = sh2[0] / (float)(DIM * LC) - m * m;
        mean[b] = m;
        rstd[b] = rsqrtf(var + 1e-5f);
    }
}

// fused ln + dwconv3 + transpose-convert: (b,d,l) float -> (b,l,d) fp16
__global__ void ln_conv_t_k(const float* __restrict__ in, const float* __restrict__ mean,
                            const float* __restrict__ rstd, const float* __restrict__ lw,
                            const float* __restrict__ lb, const float* __restrict__ cw,
                            const float* __restrict__ cb,
                            __half* __restrict__ out)
{
    __shared__ float sm[32][65];
    int b = blockIdx.x, d0 = blockIdx.y * 32;
    float mu = mean[b], rs = rstd[b];
    const float* ib = in + (long long)b * (DIM * LC);
#pragma unroll
    for (int it = 0; it < 8; it++) {
        int idx = threadIdx.x + it * 256;
        int dd = idx >> 6, l = idx & 63;
        int d = d0 + dd;
        const float* rowp = ib + (long long)d * 64;
        int wb = d * 64;
        float a = cb[d];
#pragma unroll
        for (int t = 0; t < 3; t++) {
            int l2 = l + t - 1;
            if (l2 < 0 || l2 >= 64) continue;
            float v = (rowp[l2] - mu) * rs * lw[wb + l2] + lb[wb + l2];
            a = fmaf(v, cw[d * 3 + t], a);
        }
        sm[dd][l] = a;
    }
    __syncthreads();
    __half* ob = out + (long long)b * 64 * 768;
#pragma unroll
    for (int it = 0; it < 8; it++) {
        int idx = threadIdx.x + it * 256;
        int l = idx >> 5, dd = idx & 31;
        ob[(long long)l * 768 + d0 + dd] = __float2half(sm[dd][l]);
    }
}

// fused ln + transpose-convert (no conv)
__global__ void ln_apply_t_k(const float* __restrict__ in, const float* __restrict__ mean,
                             const float* __restrict__ rstd, const float* __restrict__ lw,
                             const float* __restrict__ lb,
                             __half* __restrict__ out)
{
    __shared__ float sm[32][65];
    int b = blockIdx.x, d0 = blockIdx.y * 32;
    float mu = mean[b], rs = rstd[b];
    const float* ib = in + (long long)b * (DIM * LC);
#pragma unroll
    for (int it = 0; it < 8; it++) {
        int idx = threadIdx.x + it * 256;
        int dd = idx >> 6, l = idx & 63;
        int d = d0 + dd;
        float v = (ib[(long long)d * 64 + l] - mu) * rs * lw[d * 64 + l] + lb[d * 64 + l];
        sm[dd][l] = v;
    }
    __syncthreads();
    __half* ob = out + (long long)b * 64 * 768;
#pragma unroll
    for (int it = 0; it < 8; it++) {
        int idx = threadIdx.x + it * 256;
        int l = idx >> 5, dd = idx & 31;
        ob[(long long)l * 768 + d0 + dd] = __float2half(sm[dd][l]);
    }
}

// ---------------------------------------------------------------------------
// Small kernels
// ---------------------------------------------------------------------------
__global__ void wconv_k(const float* __restrict__ src, int ld, int trans,
                        long long total, int KK, __half* __restrict__ out)
{
    long long idx = (long long)blockIdx.x * 256 + threadIdx.x;
    if (idx >= total) return;
    int n = (int)(idx / KK), k = (int)(idx % KK);
    float v = trans ? src[(long long)k * ld + n] : src[(long long)n * ld + k];
    out[idx] = __float2half(v);
}

__global__ void rowdot_k(const float* __restrict__ x, const float* __restrict__ w,
                         float* __restrict__ out, int rowsPerB, int rowOff)
{
    int warp = (blockIdx.x * blockDim.x + threadIdx.x) >> 5;
    int lane = threadIdx.x & 31;
    int b = warp / rowsPerB;
    int i = warp % rowsPerB;
    if (b >= BATCH) return;
    const float* src = x + ((long long)b * SEQ + rowOff + i) * DIM;
    float s = 0.f;
    for (int d = lane; d < DIM; d += 32) s += src[d] * w[d];
#pragma unroll
    for (int o = 16; o > 0; o >>= 1) s += __shfl_down_sync(0xffffffffu, s, o);
    if (lane == 0) out[warp] = s;
}

// Q region: emit both Qs (b,448,768) and Q^T (b,768,448), single read of x
__global__ void qboth_k(const float* __restrict__ x,
                        __half* __restrict__ qs, __half* __restrict__ qt)
{
    __shared__ float sm[32][33];
    int j0 = blockIdx.x * 32, d0 = blockIdx.y * 32, b = blockIdx.z;
    int tx = threadIdx.x & 31, ty = threadIdx.x >> 5;
    __half* qsb = qs + (long long)b * LQ * DIM;
#pragma unroll
    for (int r = 0; r < 4; r++) {
        int j = j0 + ty + r * 8;
        float v = x[((long long)b * SEQ + LC + j) * DIM + d0 + tx];
        sm[ty + r * 8][tx] = v;
        qsb[(long long)j * DIM + d0 + tx] = __float2half(v);
    }
    __syncthreads();
    __half* qtb = qt + (long long)b * DIM * LQ;
#pragma unroll
    for (int r = 0; r < 4; r++) {
        int d = d0 + ty + r * 8;
        qtb[(long long)d * LQ + j0 + tx] = __float2half(sm[tx][ty + r * 8]);
    }
}

// C region: emit cw3 = C*w3 (b,64,768) and C^T (b,768,64), single read
__global__ void cboth_k(const float* __restrict__ x, const float* __restrict__ w3,
                        __half* __restrict__ cw3, __half* __restrict__ ct)
{
    __shared__ float sm[32][33];
    int l0 = blockIdx.x * 32, d0 = blockIdx.y * 32, b = blockIdx.z;
    int tx = threadIdx.x & 31, ty = threadIdx.x >> 5;
    __half* cwb = cw3 + (long long)b * LC * DIM;
    float w3v = w3[d0 + tx];
#pragma unroll
    for (int r = 0; r < 4; r++) {
        int l = l0 + ty + r * 8;
        float v = x[((long long)b * SEQ + l) * DIM + d0 + tx];
        sm[ty + r * 8][tx] = v;
        cwb[(long long)l * DIM + d0 + tx] = __float2half(v * w3v);
    }
    __syncthreads();
    __half* ctb = ct + (long long)b * SE;
#pragma unroll
    for (int r = 0; r < 4; r++) {
        int d = d0 + ty + r * 8;
        ctb[(long long)d * 64 + l0 + tx] = __float2half(sm[tx][ty + r * 8]);
    }
}

// row softmax, float in -> fp16 out (front-end S, len=448)
__global__ void softmax_rows_f16_k(const float* __restrict__ in,
                                   __half* __restrict__ out, int len)
{
    long long base = (long long)blockIdx.x * len;
    int t = threadIdx.x;
    __shared__ float sh[128];
    float m = -1e30f;
    for (int i = t; i < len; i += 128) m = fmaxf(m, in[base + i]);
    sh[t] = m; __syncthreads();
    for (int o = 64; o > 0; o >>= 1) { if (t < o) sh[t] = fmaxf(sh[t], sh[t + o]); __syncthreads(); }
    m = sh[0]; __syncthreads();
    float s = 0.f;
    float loc[4];
    for (int i = t, c = 0; i < len; i += 128, c++) { float e = expf(in[base + i] - m); loc[c] = e; s += e; }
    sh[t] = s; __syncthreads();
    for (int o = 64; o > 0; o >>= 1) { if (t < o) sh[t] += sh[t + o]; __syncthreads(); }
    float inv = 1.f / sh[0];
    for (int i = t, c = 0; i < len; i += 128, c++)
        out[base + i] = __float2half(loc[c] * inv);
}

// column softmax over i of S (B,64,448) -> fp16
__global__ void softmax_cols_f16_k(const float* __restrict__ S, __half* __restrict__ out)
{
    int idx = blockIdx.x * blockDim.x + threadIdx.x;
    if (idx >= BATCH * LQ) return;
    int b = idx / LQ, j = idx % LQ;
    long long base = (long long)b * LC * LQ + j;
    float m = -1e30f;
#pragma unroll 4
    for (int i = 0; i < LC; i++) m = fmaxf(m, S[base + (long long)i * LQ]);
    float s = 0.f;
    float e[LC];
#pragma unroll 4
    for (int i = 0; i < LC; i++) { e[i] = expf(S[base + (long long)i * LQ] - m); s += e[i]; }
    float inv = 1.f / s;
#pragma unroll 4
    for (int i = 0; i < LC; i++)
        out[base + (long long)i * LQ] = __float2half(e[i] * inv);
}

// fused concat-gather + depthwise k=5 -> Y fp16 (b,l,c)
__global__ void rz_dw_fuse_k(const float* __restrict__ x, const float* __restrict__ Abuf,
                             const float* __restrict__ Btbuf,
                             const float* __restrict__ dww, const float* __restrict__ dwb,
                             __half* __restrict__ Y)
{
    int c = blockIdx.x * 256 + threadIdx.x;
    int l = blockIdx.y;
    int b = blockIdx.z;
    int g = c / DIM;
    int d = c % DIM;
    float acc = dwb[c];
#pragma unroll
    for (int t = 0; t < 5; t++) {
        int l2 = l + t - 2;
        if (l2 < 0 || l2 >= LC) continue;
        float v;
        long long xo = ((long long)b * SEQ + l2) * DIM + d;
        long long ao = ((long long)b * LC + l2) * DIM + d;
        if (g == 0)      v = x[xo];
        else if (g == 1) v = Abuf[ao];
        else if (g == 2) v = x[xo] * Abuf[ao];
        else             v = x[xo] * Btbuf[ao];
        acc = fmaf(v, dww[c * 5 + t], acc);
    }
    Y[((long long)b * LC + l) * C4 + c] = __float2half(acc);
}

__global__ void pe_init_k(float* __restrict__ pe)
{
    int idx = blockIdx.x * 256 + threadIdx.x;
    if (idx >= DIM * LC) return;
    int d = idx / LC, l = idx % LC;
    float fd = (float)d;
    bool even = (d & 1) == 0;
    float freq = even ? powf(10000.f, -fd / 768.f)
                      : -powf(10000.f, (1.f - fd) / 768.f);
    float ph = even ? 0.f : 1.57079632679489662f;
    pe[idx] = sinf((float)l * freq + ph);
}

__global__ void final_head_k(const float* __restrict__ X, const float* __restrict__ w,
                             const float* __restrict__ bias, float* __restrict__ out)
{
    int b = blockIdx.x;
    const float* p = X + (long long)b * (DIM * LC);
    float s = 0.f;
    for (int i = threadIdx.x; i < DIM * LC; i += 256) s = fmaf(p[i], w[i], s);
    __shared__ float sh[256];
    sh[threadIdx.x] = s; __syncthreads();
    for (int o = 128; o > 0; o >>= 1) {
        if (threadIdx.x < o) sh[threadIdx.x] += sh[threadIdx.x + o];
        __syncthreads();
    }
    if (threadIdx.x == 0) out[b] = 1.f / (1.f + expf(-(sh[0] + bias[0])));
}

// ---------------------------------------------------------------------------
// Host-side helpers
// ---------------------------------------------------------------------------
template<int OMODE>
static inline void run_mgemm(const __half* Af, const __half* Bf,
                             float* O, __half* Oh, long long sO, int ldo,
                             const float* bias,
                             const float* R, long long sR,
                             const float* plane,
                             int N, int K, int relu)
{
    cudaFuncSetAttribute((const void*)mgemm_k<OMODE>,
                         cudaFuncAttributeMaxDynamicSharedMemorySize, MT_SMEM);
    dim3 grid(N / 128, BATCH / 2);
    mgemm_k<OMODE><<<grid, 256, MT_SMEM>>>(Af, Bf, O, Oh, sO, ldo, bias, R, sR, plane, K, relu);
}

static inline void run_pgemm(const __half* Af, long long sA, int lda,
                             const __half* Bf, long long sB, int ldb,
                             float* O, __half* Oh, long long sO, int ldo,
                             const float* bM, long long sbM,
                             const float* bN, long long sbN,
                             float alpha, int N, int K)
{
    cudaFuncSetAttribute((const void*)pgemm_k,
                         cudaFuncAttributeMaxDynamicSharedMemorySize, PG_SMEM);
    dim3 grid(N / 64, BATCH);
    pgemm_k<<<grid, 256, PG_SMEM>>>(Af, sA, lda, Bf, sB, ldb, O, Oh, sO, ldo,
                                    bM, sbM, bN, sbN, alpha, K);
}

static inline void run_pgemm_sm(const __half* Af, long long sA, int lda,
                                const __half* Bf, long long sB, int ldb,
                                __half* Oh, long long sO, float alpha, int K)
{
    cudaFuncSetAttribute((const void*)pgemm_sm_k,
                         cudaFuncAttributeMaxDynamicSharedMemorySize, PG_SMEM);
    dim3 grid(1, BATCH);
    pgemm_sm_k<<<grid, 256, PG_SMEM>>>(Af, sA, lda, Bf, sB, ldb, Oh, sO, alpha, K);
}

struct EncW {
    const float *c1dw, *c1db, *c1pw, *c1pb;
    const float *c2dw, *c2db, *c2pw, *c2pb;
    const float *wq, *wk, *wv, *wo;
    const float *fcw, *fcb;
    const float *nbw, *nbb, *n1w, *n1b, *n2w, *n2b, *nEw, *nEb;
};

struct HfW {
    __half *rz, *c1, *c2, *fc, *qkv, *wo;
};

static void enc_block(const float* Xin,
                      float* t2, float* t3,
                      __half* qkf, __half* vT, __half* attnf,
                      float* Xout, const float* outPlane,
                      float* mean, float* rstd,
                      const EncW& w, const HfW& hw,
                      __half* a1, __half* a2)
{
    const float scale = 0.03608439182435161f; // 1/sqrt(768)
    const long long SQK = 64LL * 1536;
    const long long SAT = 64LL * 64;

    // ln(normb) + dwconv c1 -> a1 fp16 (b,l,d)
    ln_stats_k<<<BATCH, 512>>>(Xin, mean, rstd);
    ln_conv_t_k<<<dim3(BATCH, 24), 256>>>(Xin, mean, rstd, w.nbw, w.nbb, w.c1dw, w.c1db, a1);
    // pw c1 (mma): relu(W@x + b) + Xin -> t2 (b,d,l)
    run_mgemm<1>(a1, hw.c1, t2, nullptr, SE, 64, w.c1pb, Xin, SE, nullptr, DIM, DIM, 1);
    // ln(norm1) + dwconv c2 -> a1
    ln_stats_k<<<BATCH, 512>>>(t2, mean, rstd);
    ln_conv_t_k<<<dim3(BATCH, 24), 256>>>(t2, mean, rstd, w.n1w, w.n1b, w.c2dw, w.c2db, a1);
    // pw c2 (mma) -> t3
    run_mgemm<1>(a1, hw.c2, t3, nullptr, SE, 64, w.c2pb, t2, SE, nullptr, DIM, DIM, 1);
    // ln(norm2) -> a1
    ln_stats_k<<<BATCH, 512>>>(t3, mean, rstd);
    ln_apply_t_k<<<dim3(BATCH, 24), 256>>>(t3, mean, rstd, w.n2w, w.n2b, a1);
    // q|k (mma, N=1536) -> qkf fp16 (b,l,1536)
    run_mgemm<0>(a1, hw.qkv, nullptr, qkf, SQK, 1536, nullptr, nullptr, 0, nullptr, 1536, DIM, 0);
    // v (mma, N=768, transposed) -> vT fp16 (b,768,64)
    run_mgemm<1>(a1, hw.qkv + 2LL * DIM * DIM, nullptr, vT, SE, 64,
                 nullptr, nullptr, 0, nullptr, DIM, DIM, 0);
    // scores + softmax fused (tensor, per-batch) -> attn fp16
    run_pgemm_sm(qkf, SQK, 1536, qkf + DIM, SQK, 1536, attnf, SAT, scale, DIM);
    // av = attn @ v (tensor; B = v^T) -> a2 fp16 (b,l,768)
    run_pgemm(attnf, SAT, 64, vT, SE, 64,
              nullptr, a2, SE, DIM, nullptr, 0, nullptr, 0, 1.f, DIM, LC);
    // sa = (av @ wo)^T + t3 -> t2 (mma, transposed store)
    run_mgemm<1>(a2, hw.wo, t2, nullptr, SE, 64, nullptr, t3, SE, nullptr, DIM, DIM, 0);
    // ln(norme) -> a1
    ln_stats_k<<<BATCH, 512>>>(t2, mean, rstd);
    ln_apply_t_k<<<dim3(BATCH, 24), 256>>>(t2, mean, rstd, w.nEw, w.nEb, a1);
    // fc + relu + t2 (+pe) -> Xout (mma)
    run_mgemm<1>(a1, hw.fc, Xout, nullptr, SE, 64, w.fcb, t2, SE, outPlane, DIM, DIM, 1);
}

// ---------------------------------------------------------------------------
// Entry point
// ---------------------------------------------------------------------------
extern "C" void kernel_launch(void* const* d_in, const int* in_sizes, int n_in,
                              void* d_out, int out_size)
{
    (void)in_sizes; (void)n_in; (void)out_size;
    const float* x       = (const float*)d_in[0];
    const float* Wv      = (const float*)d_in[1];
    const float* rz_dw_w = (const float*)d_in[2];
    const float* rz_dw_b = (const float*)d_in[3];
    const float* rz_pw_w = (const float*)d_in[4];
    const float* rz_pw_b = (const float*)d_in[5];
    EncW w;
    w.c1dw = (const float*)d_in[6];  w.c1db = (const float*)d_in[7];
    w.c1pw = (const float*)d_in[8];  w.c1pb = (const float*)d_in[9];
    w.c2dw = (const float*)d_in[10]; w.c2db = (const float*)d_in[11];
    w.c2pw = (const float*)d_in[12]; w.c2pb = (const float*)d_in[13];
    w.wq   = (const float*)d_in[14]; w.wk   = (const float*)d_in[15];
    w.wv   = (const float*)d_in[16]; w.wo   = (const float*)d_in[17];
    w.fcw  = (const float*)d_in[18]; w.fcb  = (const float*)d_in[19];
    w.nbw  = (const float*)d_in[20]; w.nbb  = (const float*)d_in[21];
    w.n1w  = (const float*)d_in[22]; w.n1b  = (const float*)d_in[23];
    w.n2w  = (const float*)d_in[24]; w.n2b  = (const float*)d_in[25];
    w.nEw  = (const float*)d_in[26]; w.nEb  = (const float*)d_in[27];
    const float* fcf_w = (const float*)d_in[28];
    const float* fcf_b = (const float*)d_in[29];

    float* pool = nullptr;
    cudaGetSymbolAddress((void**)&pool, g_pool);

    float* c1s  = pool + OFF_C1;
    float* q2s  = pool + OFF_Q2;
    float* S    = pool + OFF_S;
    float* Abuf = pool + OFF_A;
    float* Btb  = pool + OFF_BT;
    float* E[8];
    for (int i = 0; i < 8; i++) E[i] = pool + OFF_E0 + (long long)i * SZ_E;
    float* mean = pool + OFF_MEAN;
    float* rstd = pool + OFF_RSTD;
    float* pe   = pool + OFF_PE;

    __half* cw3f  = (__half*)(pool + OFF_CW3);
    __half* S1f   = (__half*)(pool + OFF_S1);
    __half* S2f   = (__half*)(pool + OFF_S2);
    __half* Yf    = (__half*)(pool + OFF_Y);
    __half* Qsf   = (__half*)(pool + OFF_QS);
    __half* Qtf   = (__half*)(pool + OFF_QT);
    __half* a1    = (__half*)(pool + OFF_ACT);
    __half* a2    = a1 + SZ_BD;
    __half* qkf   = (__half*)E[4];
    __half* vT    = (__half*)E[5];
    __half* attnf = (__half*)E[6];
    __half* Tf    = (__half*)E[6];
    __half* cTf   = (__half*)E[1];

    HfW hw;
    {
        __half* p = (__half*)(pool + OFF_WB);
        hw.rz  = p; p += (long long)DIM * C4;
        hw.c1  = p; p += (long long)DIM * DIM;
        hw.c2  = p; p += (long long)DIM * DIM;
        hw.fc  = p; p += (long long)DIM * DIM;
        hw.qkv = p; p += 3LL * DIM * DIM;
        hw.wo  = p;
    }

    const long long WDD = (long long)DIM * DIM;

    pe_init_k<<<(DIM * LC + 255) / 256, 256>>>(pe);
    rowdot_k<<<(BATCH * LC * 32) / 256, 256>>>(x, Wv, c1s, LC, 0);
    rowdot_k<<<(BATCH * LQ * 32) / 256, 256>>>(x, Wv + DIM, q2s, LQ, LC);
    cboth_k<<<dim3(2, DIM / 32, BATCH), 256>>>(x, Wv + 2 * DIM, cw3f, cTf);
    qboth_k<<<dim3(LQ / 32, DIM / 32, BATCH), 256>>>(x, Qsf, Qtf);

    // S = cw3 @ Q^T + c1[:,None] + q2[None,:]   (tensor, per-batch)
    run_pgemm(cw3f, 64LL * DIM, DIM, Qsf, (long long)LQ * DIM, DIM,
              S, nullptr, (long long)LC * LQ, LQ, c1s, LC, q2s, LQ, 1.f, LQ, DIM);

    softmax_rows_f16_k<<<BATCH * LC, 128>>>(S, S1f, LQ);
    softmax_cols_f16_k<<<(BATCH * LQ + 255) / 256, 256>>>(S, S2f);

    // A = S1 @ Q (tensor; B = Q^T) -> fp32
    run_pgemm(S1f, (long long)LC * LQ, LQ, Qtf, (long long)DIM * LQ, LQ,
              Abuf, nullptr, (long long)LC * DIM, DIM, nullptr, 0, nullptr, 0, 1.f, DIM, LQ);

    // T = S1 @ S2^T (tensor) -> fp16
    run_pgemm(S1f, (long long)LC * LQ, LQ, S2f, (long long)LC * LQ, LQ,
              nullptr, Tf, (long long)LC * LC, LC, nullptr, 0, nullptr, 0, 1.f, LC, LQ);

    // Bt = T @ C (tensor; B = C^T) -> fp32
    run_pgemm(Tf, (long long)LC * LC, LC, cTf, SE, LC,
              Btb, nullptr, (long long)LC * DIM, DIM, nullptr, 0, nullptr, 0, 1.f, DIM, LC);

    // fused concat-gather + depthwise k=5 -> Y fp16 (b,l,c)
    rz_dw_fuse_k<<<dim3(C4 / 256, LC, BATCH), 256>>>(x, Abuf, Btb, rz_dw_w, rz_dw_b, Yf);

    // ---- weight conversion (fp16, n x k, k-contiguous) ----
    {
        long long trz = (long long)DIM * C4;
        int gs = (int)((WDD + 255) / 256);
        wconv_k<<<(int)((trz + 255) / 256), 256>>>(rz_pw_w, C4, 0, trz, C4, hw.rz);
        wconv_k<<<gs, 256>>>(w.c1pw, DIM, 0, WDD, DIM, hw.c1);
        wconv_k<<<gs, 256>>>(w.c2pw, DIM, 0, WDD, DIM, hw.c2);
        wconv_k<<<gs, 256>>>(w.fcw,  DIM, 0, WDD, DIM, hw.fc);
        wconv_k<<<gs, 256>>>(w.wq,   DIM, 1, WDD, DIM, hw.qkv);
        wconv_k<<<gs, 256>>>(w.wk,   DIM, 1, WDD, DIM, hw.qkv + WDD);
        wconv_k<<<gs, 256>>>(w.wv,   DIM, 1, WDD, DIM, hw.qkv + 2 * WDD);
        wconv_k<<<gs, 256>>>(w.wo,   DIM, 1, WDD, DIM, hw.wo);
    }

    // pointwise 3072 -> 768 (mma): +bias +pe -> E0 (b,d,l)
    run_mgemm<1>(Yf, hw.rz, E[0], nullptr, SE, 64, rz_pw_b, nullptr, 0, pe, DIM, C4, 0);

    // ---- two encoder blocks ----
    enc_block(E[0], E[2], E[3], qkf, vT, attnf, E[7], pe, mean, rstd, w, hw, a1, a2);
    enc_block(E[7], E[2], E[3], qkf, vT, attnf, E[0], nullptr, mean, rstd, w, hw, a1, a2);

    // ---- final sigmoid head ----
    final_head_k<<<BATCH, 256>>>(E[0], fcf_w, fcf_b, (float*)d_out);
}

// round 11
// speedup vs baseline: 2.2037x; 1.1346x over previous
#include <cuda_runtime.h>
#include <cuda_fp16.h>
#include <math.h>
#include <stdint.h>

// ---------------------------------------------------------------------------
// Problem constants
// ---------------------------------------------------------------------------
namespace {
constexpr int BATCH = 128;
constexpr int LC    = 64;
constexpr int LQ    = 448;
constexpr int DIM   = 768;
constexpr int SEQ   = 512;
constexpr int C4    = 3072;

constexpr long long SZ_C1 = (long long)BATCH * LC;
constexpr long long SZ_Q2 = (long long)BATCH * LQ;
constexpr long long SZ_BD = (long long)BATCH * LC * DIM;
constexpr long long SZ_S  = (long long)BATCH * LC * LQ;
constexpr long long SZ_T  = (long long)BATCH * LC * LC;
constexpr long long SZ_Y  = (long long)BATCH * LC * C4;
constexpr long long SZ_E  = SZ_BD;
constexpr long long SZ_Q  = (long long)BATCH * LQ * DIM;
constexpr long long SE    = (long long)DIM * LC;

constexpr long long OFF_C1  = 0;
constexpr long long OFF_Q2  = OFF_C1 + SZ_C1;
constexpr long long OFF_CW3 = OFF_Q2 + SZ_Q2;    // cw3 fp16
constexpr long long OFF_S   = OFF_CW3 + SZ_BD;
constexpr long long OFF_S1  = OFF_S  + SZ_S;     // S1 fp16
constexpr long long OFF_S2  = OFF_S1 + SZ_S;     // S2 fp16
constexpr long long OFF_A   = OFF_S2 + SZ_S;
constexpr long long OFF_T   = OFF_A  + SZ_BD;
constexpr long long OFF_BT  = OFF_T  + SZ_T;
constexpr long long OFF_Y   = OFF_BT + SZ_BD;    // Y fp16 / early fp32 scratch
constexpr long long OFF_E0  = OFF_Y  + SZ_Y;
constexpr long long OFF_MEAN = OFF_E0 + 8 * SZ_E;
constexpr long long OFF_RSTD = OFF_MEAN + 128;
constexpr long long OFF_PE   = OFF_RSTD + 128;
constexpr long long OFF_ACT  = OFF_PE + (long long)DIM * LC;
constexpr long long OFF_WB   = OFF_ACT + 2 * SZ_BD;
constexpr long long WB_FLOATS = ((long long)DIM * C4 + 7LL * DIM * DIM) / 2 + 64;
constexpr long long OFF_QS   = OFF_WB + WB_FLOATS;   // Q fp16 (b,448,768)
constexpr long long OFF_QT   = OFF_QS + SZ_Q;        // Q^T fp16 (b,768,448)
constexpr long long POOL_SZ  = OFF_QT + SZ_Q;

constexpr int NCHUNK = DIM / 32;   // 24 partial chunks for q2
} // namespace

__device__ float g_pool[POOL_SZ];

// ---------------------------------------------------------------------------
// Family-portable tensor-core primitives
// ---------------------------------------------------------------------------
__device__ __forceinline__ uint32_t smem_u32(const void* p) {
    uint32_t a;
    asm("{ .reg .u64 t; cvta.to.shared.u64 t, %1; cvt.u32.u64 %0, t; }" : "=r"(a) : "l"(p));
    return a;
}
#define SW128(o) ((o) ^ (((o) >> 3) & 0x70))

__device__ __forceinline__ void cpa16(uint32_t dst, const void* src) {
    asm volatile("cp.async.cg.shared.global [%0], [%1], 16;" :: "r"(dst), "l"(src) : "memory");
}
__device__ __forceinline__ void cp_commit() {
    asm volatile("cp.async.commit_group;" ::: "memory");
}
__device__ __forceinline__ void cp_wait1() {
    asm volatile("cp.async.wait_group 1;" ::: "memory");
}
__device__ __forceinline__ void cp_wait0() {
    asm volatile("cp.async.wait_group 0;" ::: "memory");
}
__device__ __forceinline__ void ldsm4(uint32_t* r, uint32_t a) {
    asm volatile("ldmatrix.sync.aligned.m8n8.x4.shared.b16 {%0,%1,%2,%3}, [%4];"
        : "=r"(r[0]), "=r"(r[1]), "=r"(r[2]), "=r"(r[3]) : "r"(a));
}
__device__ __forceinline__ void mma_f16(float* d, const uint32_t* a, uint32_t b0, uint32_t b1) {
    asm volatile("mma.sync.aligned.m16n8k16.row.col.f32.f16.f16.f32 "
        "{%0,%1,%2,%3}, {%4,%5,%6,%7}, {%8,%9}, {%0,%1,%2,%3};"
        : "+f"(d[0]), "+f"(d[1]), "+f"(d[2]), "+f"(d[3])
        : "r"(a[0]), "r"(a[1]), "r"(a[2]), "r"(a[3]), "r"(b0), "r"(b1));
}

// ---------------------------------------------------------------------------
// mgemm: batch-shared-B tensor GEMM (fp16 in, fp32 accum), 2 CTA/SM
// ---------------------------------------------------------------------------
namespace {
constexpr int MT_TILE = 16384;
constexpr int MT_SMEM = 3 * 2 * MT_TILE + 1024;
constexpr int PG_TILE = 8192;
constexpr int PG_SMEM = 2 * 2 * PG_TILE + 1024;
constexpr int RZ_SMEM = 3 * 64 * 128 * 4 + 16;   // x/A/Bt slabs, 96 KB
}

template<int OMODE>
__global__ void __launch_bounds__(256, 2) mgemm_k(
    const __half* __restrict__ Af,
    const __half* __restrict__ Bf,
    float* __restrict__ O, __half* __restrict__ Oh, long long sO, int ldo,
    const float* __restrict__ bias,
    const float* __restrict__ R, long long sR,
    const float* __restrict__ plane,
    int K, int relu)
{
    extern __shared__ char dsm[];
    const uint32_t tb = (smem_u32(dsm) + 1023u) & ~1023u;

    const int tid = threadIdx.x, lane = tid & 31, wid = tid >> 5;
    const int n0 = blockIdx.x * 128;
    const int rbase = blockIdx.y * 128;
    const int wm = wid & 1, wn = wid >> 1;

    float acc[4][4][4];
#pragma unroll
    for (int a = 0; a < 4; a++)
#pragma unroll
        for (int b = 0; b < 4; b++)
#pragma unroll
            for (int c = 0; c < 4; c++) acc[a][b][c] = 0.f;

    const int nch = K / 64;

    auto copy_chunk = [&](int ci, int s) {
        const int k0 = ci * 64;
        const uint32_t tA = tb + (s * 2 + 0) * MT_TILE;
        const uint32_t tB = tb + (s * 2 + 1) * MT_TILE;
#pragma unroll
        for (int it = 0; it < 4; it++) {
            int idx = tid + it * 256;
            int r = idx >> 3, c = idx & 7;
            uint32_t doff = SW128((uint32_t)(r * 128 + c * 16));
            cpa16(tA + doff, Af + (long long)(rbase + r) * K + k0 + c * 8);
            cpa16(tB + doff, Bf + (long long)(n0 + r) * K + k0 + c * 8);
        }
    };

    copy_chunk(0, 0); cp_commit();
    copy_chunk(1, 1); cp_commit();

    const int rl = lane & 15, chalf = lane >> 4;

    for (int i = 0; i < nch; i++) {
        if (i + 1 < nch) cp_wait1(); else cp_wait0();
        __syncthreads();
        if (i + 2 < nch) { copy_chunk(i + 2, (i + 2) % 3); cp_commit(); }

        const int s = i % 3;
        const uint32_t tA = tb + (s * 2 + 0) * MT_TILE;
        const uint32_t tB = tb + (s * 2 + 1) * MT_TILE;

#pragma unroll
        for (int ks = 0; ks < 4; ks++) {
            const uint32_t coff = (uint32_t)((ks * 2 + chalf) * 16);
            uint32_t af[4][4], bf[2][4];
#pragma unroll
            for (int mt = 0; mt < 4; mt++) {
                uint32_t off = SW128((uint32_t)((wm * 64 + mt * 16 + rl) * 128) + coff);
                ldsm4(af[mt], tA + off);
            }
#pragma unroll
            for (int np = 0; np < 2; np++) {
                uint32_t off = SW128((uint32_t)((wn * 32 + np * 16 + rl) * 128) + coff);
                ldsm4(bf[np], tB + off);
            }
#pragma unroll
            for (int mt = 0; mt < 4; mt++)
#pragma unroll
                for (int np = 0; np < 2; np++)
#pragma unroll
                    for (int j = 0; j < 2; j++)
                        mma_f16(acc[mt][np * 2 + j], af[mt], bf[np][j], bf[np][j + 2]);
        }
    }

    const int b0 = blockIdx.y * 2;
#pragma unroll
    for (int mt = 0; mt < 4; mt++) {
        int row0 = wm * 64 + mt * 16 + (lane >> 2);
#pragma unroll
        for (int half = 0; half < 2; half++) {
            int row = row0 + half * 8;
            int bi = b0 + (row >> 6), l = row & 63;
            float* Ob = O ? O + (long long)bi * sO : nullptr;
            __half* Ohb = Oh ? Oh + (long long)bi * sO : nullptr;
            const float* Rb = R ? R + (long long)bi * sR : nullptr;
#pragma unroll
            for (int nn = 0; nn < 4; nn++) {
                int n = n0 + wn * 32 + nn * 8 + (lane & 3) * 2;
#pragma unroll
                for (int e = 0; e < 2; e++) {
                    float v = acc[mt][nn][half * 2 + e];
                    int nc = n + e;
                    if (bias) v += bias[nc];
                    if (relu) v = fmaxf(v, 0.f);
                    long long o = (OMODE == 1) ? ((long long)nc * 64 + l)
                                               : ((long long)l * ldo + nc);
                    if (Rb)    v += Rb[o];
                    if (plane) v += plane[o];
                    if (Ohb) Ohb[o] = __float2half(v);
                    else     Ob[o]  = v;
                }
            }
        }
    }
}

// ---------------------------------------------------------------------------
// pgemm: per-batch GEMM, fp16 in, fp32 accum. Optional fp16 out.
// ---------------------------------------------------------------------------
__global__ void __launch_bounds__(256) pgemm_k(
    const __half* __restrict__ Af, long long sA, int lda,
    const __half* __restrict__ Bf, long long sB, int ldb,
    float* __restrict__ O, __half* __restrict__ Oh, long long sO, int ldo,
    const float* __restrict__ bM, long long sbM,
    const float* __restrict__ bN, long long sbN,
    float alpha, int K)
{
    extern __shared__ char dsm[];
    const uint32_t tb = (smem_u32(dsm) + 1023u) & ~1023u;

    const int tid = threadIdx.x, lane = tid & 31, wid = tid >> 5;
    const int n0 = blockIdx.x * 64;
    const int b  = blockIdx.y;
    const int wm = wid >> 1, wn = wid & 1;

    const __half* Afb = Af + (long long)b * sA;
    const __half* Bfb = Bf + (long long)b * sB + (long long)n0 * ldb;

    float acc[4][4];
#pragma unroll
    for (int a = 0; a < 4; a++)
#pragma unroll
        for (int c = 0; c < 4; c++) acc[a][c] = 0.f;

    const int nch = K / 64;

    auto copy_chunk = [&](int ci, int s) {
        const int k0 = ci * 64;
        const uint32_t tA = tb + (s * 2 + 0) * PG_TILE;
        const uint32_t tB = tb + (s * 2 + 1) * PG_TILE;
#pragma unroll
        for (int it = 0; it < 2; it++) {
            int idx = tid + it * 256;
            int r = idx >> 3, c = idx & 7;
            uint32_t doff = SW128((uint32_t)(r * 128 + c * 16));
            cpa16(tA + doff, Afb + (long long)r * lda + k0 + c * 8);
            cpa16(tB + doff, Bfb + (long long)r * ldb + k0 + c * 8);
        }
    };

    copy_chunk(0, 0); cp_commit();

    const int rl = lane & 15, chalf = lane >> 4;

    for (int i = 0; i < nch; i++) {
        cp_wait0();
        __syncthreads();
        if (i + 1 < nch) { copy_chunk(i + 1, (i + 1) & 1); cp_commit(); }

        const int s = i & 1;
        const uint32_t tA = tb + (s * 2 + 0) * PG_TILE;
        const uint32_t tB = tb + (s * 2 + 1) * PG_TILE;

#pragma unroll
        for (int ks = 0; ks < 4; ks++) {
            const uint32_t coff = (uint32_t)((ks * 2 + chalf) * 16);
            uint32_t af[4], bf[2][4];
            {
                uint32_t off = SW128((uint32_t)((wm * 16 + rl) * 128) + coff);
                ldsm4(af, tA + off);
            }
#pragma unroll
            for (int np = 0; np < 2; np++) {
                uint32_t off = SW128((uint32_t)((wn * 32 + np * 16 + rl) * 128) + coff);
                ldsm4(bf[np], tB + off);
            }
#pragma unroll
            for (int np = 0; np < 2; np++)
#pragma unroll
                for (int j = 0; j < 2; j++)
                    mma_f16(acc[np * 2 + j], af, bf[np][j], bf[np][j + 2]);
        }
    }

    float* Ob = O ? O + (long long)b * sO : nullptr;
    __half* Ohb = Oh ? Oh + (long long)b * sO : nullptr;
    const float* bMp = bM ? bM + (long long)b * sbM : nullptr;
    const float* bNp = bN ? bN + (long long)b * sbN : nullptr;
#pragma unroll
    for (int half = 0; half < 2; half++) {
        int row = wm * 16 + (lane >> 2) + half * 8;
#pragma unroll
        for (int nn = 0; nn < 4; nn++) {
            int n = n0 + wn * 32 + nn * 8 + (lane & 3) * 2;
#pragma unroll
            for (int e = 0; e < 2; e++) {
                float v = acc[nn][half * 2 + e] * alpha;
                int nc = n + e;
                if (bMp) v += bMp[row];
                if (bNp) v += bNp[nc];
                long long o = (long long)row * ldo + nc;
                if (Ohb) Ohb[o] = __float2half(v);
                else     Ob[o]  = v;
            }
        }
    }
}

// ---------------------------------------------------------------------------
// pgemm_sm: per-batch 64x64 GEMM + fused row softmax -> fp16 attn
// ---------------------------------------------------------------------------
__global__ void __launch_bounds__(256) pgemm_sm_k(
    const __half* __restrict__ Af, long long sA, int lda,
    const __half* __restrict__ Bf, long long sB, int ldb,
    __half* __restrict__ Oh, long long sO,
    float alpha, int K)
{
    extern __shared__ char dsm[];
    const uint32_t tb = (smem_u32(dsm) + 1023u) & ~1023u;
    __shared__ float ss[64][65];
    __shared__ float rinv[64];

    const int tid = threadIdx.x, lane = tid & 31, wid = tid >> 5;
    const int b  = blockIdx.y;
    const int wm = wid >> 1, wn = wid & 1;

    const __half* Afb = Af + (long long)b * sA;
    const __half* Bfb = Bf + (long long)b * sB;

    float acc[4][4];
#pragma unroll
    for (int a = 0; a < 4; a++)
#pragma unroll
        for (int c = 0; c < 4; c++) acc[a][c] = 0.f;

    const int nch = K / 64;

    auto copy_chunk = [&](int ci, int s) {
        const int k0 = ci * 64;
        const uint32_t tA = tb + (s * 2 + 0) * PG_TILE;
        const uint32_t tB = tb + (s * 2 + 1) * PG_TILE;
#pragma unroll
        for (int it = 0; it < 2; it++) {
            int idx = tid + it * 256;
            int r = idx >> 3, c = idx & 7;
            uint32_t doff = SW128((uint32_t)(r * 128 + c * 16));
            cpa16(tA + doff, Afb + (long long)r * lda + k0 + c * 8);
            cpa16(tB + doff, Bfb + (long long)r * ldb + k0 + c * 8);
        }
    };

    copy_chunk(0, 0); cp_commit();

    const int rl = lane & 15, chalf = lane >> 4;

    for (int i = 0; i < nch; i++) {
        cp_wait0();
        __syncthreads();
        if (i + 1 < nch) { copy_chunk(i + 1, (i + 1) & 1); cp_commit(); }

        const int s = i & 1;
        const uint32_t tA = tb + (s * 2 + 0) * PG_TILE;
        const uint32_t tB = tb + (s * 2 + 1) * PG_TILE;

#pragma unroll
        for (int ks = 0; ks < 4; ks++) {
            const uint32_t coff = (uint32_t)((ks * 2 + chalf) * 16);
            uint32_t af[4], bf[2][4];
            {
                uint32_t off = SW128((uint32_t)((wm * 16 + rl) * 128) + coff);
                ldsm4(af, tA + off);
            }
#pragma unroll
            for (int np = 0; np < 2; np++) {
                uint32_t off = SW128((uint32_t)((wn * 32 + np * 16 + rl) * 128) + coff);
                ldsm4(bf[np], tB + off);
            }
#pragma unroll
            for (int np = 0; np < 2; np++)
#pragma unroll
                for (int j = 0; j < 2; j++)
                    mma_f16(acc[np * 2 + j], af, bf[np][j], bf[np][j + 2]);
        }
    }

#pragma unroll
    for (int half = 0; half < 2; half++) {
        int row = wm * 16 + (lane >> 2) + half * 8;
#pragma unroll
        for (int nn = 0; nn < 4; nn++) {
            int n = wn * 32 + nn * 8 + (lane & 3) * 2;
#pragma unroll
            for (int e = 0; e < 2; e++)
                ss[row][n + e] = acc[nn][half * 2 + e] * alpha;
        }
    }
    __syncthreads();

    if (tid < 64) {
        float m = -1e30f;
#pragma unroll 8
        for (int c = 0; c < 64; c++) m = fmaxf(m, ss[tid][c]);
        float s = 0.f;
#pragma unroll 8
        for (int c = 0; c < 64; c++) { float e = expf(ss[tid][c] - m); ss[tid][c] = e; s += e; }
        rinv[tid] = 1.f / s;
    }
    __syncthreads();

    __half* Ohb = Oh + (long long)b * sO;
#pragma unroll
    for (int it = 0; it < 16; it++) {
        int idx = tid + it * 256;
        int r = idx >> 6, c = idx & 63;
        Ohb[idx] = __float2half(ss[r][c] * rinv[r]);
    }
}

// ---------------------------------------------------------------------------
// LayerNorm (proven-fast scheme): stats kernel + coalesced apply kernels
// ---------------------------------------------------------------------------
__global__ void ln_stats_k(const float* __restrict__ in, float* __restrict__ mean,
                           float* __restrict__ rstd)
{
    int b = blockIdx.x;
    const float4* p = reinterpret_cast<const float4*>(in + (long long)b * (DIM * LC));
    float s = 0.f, s2 = 0.f;
    for (int i = threadIdx.x; i < DIM * LC / 4; i += 512) {
        float4 v = p[i];
        s += v.x + v.y + v.z + v.w;
        s2 += v.x * v.x + v.y * v.y + v.z * v.z + v.w * v.w;
    }
    __shared__ float sh[512], sh2[512];
    sh[threadIdx.x] = s; sh2[threadIdx.x] = s2; __syncthreads();
    for (int o = 256; o > 0; o >>= 1) {
        if (threadIdx.x < o) { sh[threadIdx.x] += sh[threadIdx.x + o]; sh2[threadIdx.x] += sh2[threadIdx.x + o]; }
        __syncthreads();
    }
    if (threadIdx.x == 0) {
        float m = sh[0] / (float)(DIM * LC);
        float var = sh2[0] / (float)(DIM * LC) - m * m;
        mean[b] = m;
        rstd[b] = rsqrtf(var + 1e-5f);
    }
}

// fused ln + dwconv3 + transpose-convert: (b,d,l) float -> (b,l,d) fp16
__global__ void ln_conv_t_k(const float* __restrict__ in, const float* __restrict__ mean,
                            const float* __restrict__ rstd, const float* __restrict__ lw,
                            const float* __restrict__ lb, const float* __restrict__ cw,
                            const float* __restrict__ cb,
                            __half* __restrict__ out)
{
    __shared__ float sm[32][65];
    int b = blockIdx.x, d0 = blockIdx.y * 32;
    float mu = mean[b], rs = rstd[b];
    const float* ib = in + (long long)b * (DIM * LC);
#pragma unroll
    for (int it = 0; it < 8; it++) {
        int idx = threadIdx.x + it * 256;
        int dd = idx >> 6, l = idx & 63;
        int d = d0 + dd;
        const float* rowp = ib + (long long)d * 64;
        int wb = d * 64;
        float a = cb[d];
#pragma unroll
        for (int t = 0; t < 3; t++) {
            int l2 = l + t - 1;
            if (l2 < 0 || l2 >= 64) continue;
            float v = (rowp[l2] - mu) * rs * lw[wb + l2] + lb[wb + l2];
            a = fmaf(v, cw[d * 3 + t], a);
        }
        sm[dd][l] = a;
    }
    __syncthreads();
    __half* ob = out + (long long)b * 64 * 768;
#pragma unroll
    for (int it = 0; it < 8; it++) {
        int idx = threadIdx.x + it * 256;
        int l = idx >> 5, dd = idx & 31;
        ob[(long long)l * 768 + d0 + dd] = __float2half(sm[dd][l]);
    }
}

// fused ln + transpose-convert (no conv)
__global__ void ln_apply_t_k(const float* __restrict__ in, const float* __restrict__ mean,
                             const float* __restrict__ rstd, const float* __restrict__ lw,
                             const float* __restrict__ lb,
                             __half* __restrict__ out)
{
    __shared__ float sm[32][65];
    int b = blockIdx.x, d0 = blockIdx.y * 32;
    float mu = mean[b], rs = rstd[b];
    const float* ib = in + (long long)b * (DIM * LC);
#pragma unroll
    for (int it = 0; it < 8; it++) {
        int idx = threadIdx.x + it * 256;
        int dd = idx >> 6, l = idx & 63;
        int d = d0 + dd;
        float v = (ib[(long long)d * 64 + l] - mu) * rs * lw[d * 64 + l] + lb[d * 64 + l];
        sm[dd][l] = v;
    }
    __syncthreads();
    __half* ob = out + (long long)b * 64 * 768;
#pragma unroll
    for (int it = 0; it < 8; it++) {
        int idx = threadIdx.x + it * 256;
        int l = idx >> 5, dd = idx & 31;
        ob[(long long)l * 768 + d0 + dd] = __float2half(sm[dd][l]);
    }
}

// ---------------------------------------------------------------------------
// Small kernels
// ---------------------------------------------------------------------------
__global__ void wconv_k(const float* __restrict__ src, int ld, int trans,
                        long long total, int KK, __half* __restrict__ out)
{
    long long idx = (long long)blockIdx.x * 256 + threadIdx.x;
    if (idx >= total) return;
    int n = (int)(idx / KK), k = (int)(idx % KK);
    float v = trans ? src[(long long)k * ld + n] : src[(long long)n * ld + k];
    out[idx] = __float2half(v);
}

__global__ void rowdot_k(const float* __restrict__ x, const float* __restrict__ w,
                         float* __restrict__ out, int rowsPerB, int rowOff)
{
    int warp = (blockIdx.x * blockDim.x + threadIdx.x) >> 5;
    int lane = threadIdx.x & 31;
    int b = warp / rowsPerB;
    int i = warp % rowsPerB;
    if (b >= BATCH) return;
    const float* src = x + ((long long)b * SEQ + rowOff + i) * DIM;
    float s = 0.f;
    for (int d = lane; d < DIM; d += 32) s += src[d] * w[d];
#pragma unroll
    for (int o = 16; o > 0; o >>= 1) s += __shfl_down_sync(0xffffffffu, s, o);
    if (lane == 0) out[warp] = s;
}

// Q region: emit Qs (b,448,768), Q^T (b,768,448), and q2 partial dots, one read
__global__ void qboth_k(const float* __restrict__ x, const float* __restrict__ w2,
                        __half* __restrict__ qs, __half* __restrict__ qt,
                        float* __restrict__ qpart)
{
    __shared__ float sm[32][33];
    int j0 = blockIdx.x * 32, d0 = blockIdx.y * 32, b = blockIdx.z;
    int tx = threadIdx.x & 31, ty = threadIdx.x >> 5;
    __half* qsb = qs + (long long)b * LQ * DIM;
    const float w2v = w2[d0 + tx];
#pragma unroll
    for (int r = 0; r < 4; r++) {
        int j = j0 + ty + r * 8;
        float v = x[((long long)b * SEQ + LC + j) * DIM + d0 + tx];
        sm[ty + r * 8][tx] = v;
        qsb[(long long)j * DIM + d0 + tx] = __float2half(v);
        // q2 partial: warp-reduce v*w2 over the 32 d-lanes (deterministic)
        float s = v * w2v;
#pragma unroll
        for (int o = 16; o > 0; o >>= 1) s += __shfl_down_sync(0xffffffffu, s, o);
        if (tx == 0)
            qpart[(long long)(d0 >> 5) * (BATCH * LQ) + (long long)b * LQ + j] = s;
    }
    __syncthreads();
    __half* qtb = qt + (long long)b * DIM * LQ;
#pragma unroll
    for (int r = 0; r < 4; r++) {
        int d = d0 + ty + r * 8;
        qtb[(long long)d * LQ + j0 + tx] = __float2half(sm[tx][ty + r * 8]);
    }
}

// reduce q2 partials (24 chunks)
__global__ void q2red_k(const float* __restrict__ qpart, float* __restrict__ q2)
{
    int i = blockIdx.x * 256 + threadIdx.x;
    if (i >= BATCH * LQ) return;
    float s = 0.f;
#pragma unroll
    for (int c = 0; c < NCHUNK; c++)
        s += qpart[(long long)c * (BATCH * LQ) + i];
    q2[i] = s;
}

// C region: emit cw3 = C*w3 (b,64,768) and C^T (b,768,64), single read
__global__ void cboth_k(const float* __restrict__ x, const float* __restrict__ w3,
                        __half* __restrict__ cw3, __half* __restrict__ ct)
{
    __shared__ float sm[32][33];
    int l0 = blockIdx.x * 32, d0 = blockIdx.y * 32, b = blockIdx.z;
    int tx = threadIdx.x & 31, ty = threadIdx.x >> 5;
    __half* cwb = cw3 + (long long)b * LC * DIM;
    float w3v = w3[d0 + tx];
#pragma unroll
    for (int r = 0; r < 4; r++) {
        int l = l0 + ty + r * 8;
        float v = x[((long long)b * SEQ + l) * DIM + d0 + tx];
        sm[ty + r * 8][tx] = v;
        cwb[(long long)l * DIM + d0 + tx] = __float2half(v * w3v);
    }
    __syncthreads();
    __half* ctb = ct + (long long)b * SE;
#pragma unroll
    for (int r = 0; r < 4; r++) {
        int d = d0 + ty + r * 8;
        ctb[(long long)d * 64 + l0 + tx] = __float2half(sm[tx][ty + r * 8]);
    }
}

// row softmax, float in -> fp16 out (front-end S, len=448)
__global__ void softmax_rows_f16_k(const float* __restrict__ in,
                                   __half* __restrict__ out, int len)
{
    long long base = (long long)blockIdx.x * len;
    int t = threadIdx.x;
    __shared__ float sh[128];
    float m = -1e30f;
    for (int i = t; i < len; i += 128) m = fmaxf(m, in[base + i]);
    sh[t] = m; __syncthreads();
    for (int o = 64; o > 0; o >>= 1) { if (t < o) sh[t] = fmaxf(sh[t], sh[t + o]); __syncthreads(); }
    m = sh[0]; __syncthreads();
    float s = 0.f;
    float loc[4];
    for (int i = t, c = 0; i < len; i += 128, c++) { float e = expf(in[base + i] - m); loc[c] = e; s += e; }
    sh[t] = s; __syncthreads();
    for (int o = 64; o > 0; o >>= 1) { if (t < o) sh[t] += sh[t + o]; __syncthreads(); }
    float inv = 1.f / sh[0];
    for (int i = t, c = 0; i < len; i += 128, c++)
        out[base + i] = __float2half(loc[c] * inv);
}

// column softmax over i of S (B,64,448) -> fp16
__global__ void softmax_cols_f16_k(const float* __restrict__ S, __half* __restrict__ out)
{
    int idx = blockIdx.x * blockDim.x + threadIdx.x;
    if (idx >= BATCH * LQ) return;
    int b = idx / LQ, j = idx % LQ;
    long long base = (long long)b * LC * LQ + j;
    float m = -1e30f;
#pragma unroll 4
    for (int i = 0; i < LC; i++) m = fmaxf(m, S[base + (long long)i * LQ]);
    float s = 0.f;
    float e[LC];
#pragma unroll 4
    for (int i = 0; i < LC; i++) { e[i] = expf(S[base + (long long)i * LQ] - m); s += e[i]; }
    float inv = 1.f / s;
#pragma unroll 4
    for (int i = 0; i < LC; i++)
        out[base + (long long)i * LQ] = __float2half(e[i] * inv);
}

// smem-tiled concat-gather + depthwise k=5 -> Y fp16 (b,l,c)
// grid (DIM/128, BATCH); caches x/A/Bt 64x128 slabs, reads each input once.
__global__ void __launch_bounds__(256) rz_dw_tile_k(
    const float* __restrict__ x, const float* __restrict__ Abuf,
    const float* __restrict__ Btbuf,
    const float* __restrict__ dww, const float* __restrict__ dwb,
    __half* __restrict__ Y)
{
    extern __shared__ float sb[];
    float* xs = sb;                 // [64][128]
    float* as = sb + 64 * 128;      // [64][128]
    float* bs = sb + 2 * 64 * 128;  // [64][128]

    const int d0 = blockIdx.x * 128;
    const int b  = blockIdx.y;
    const int tid = threadIdx.x;

    // load slabs (float4, fully coalesced)
    {
        const float4* xp = reinterpret_cast<const float4*>(x + ((long long)b * SEQ) * DIM);
        const float4* ap = reinterpret_cast<const float4*>(Abuf + (long long)b * LC * DIM);
        const float4* bp = reinterpret_cast<const float4*>(Btbuf + (long long)b * LC * DIM);
        const int d04 = d0 >> 2;
#pragma unroll
        for (int it = 0; it < 8; it++) {
            int idx = tid + it * 256;            // 0..2047 float4 slots
            int l = idx >> 5, c4 = idx & 31;     // 32 float4 per row
            reinterpret_cast<float4*>(xs)[idx] = xp[(long long)l * (DIM / 4) + d04 + c4];
            reinterpret_cast<float4*>(as)[idx] = ap[(long long)l * (DIM / 4) + d04 + c4];
            reinterpret_cast<float4*>(bs)[idx] = bp[(long long)l * (DIM / 4) + d04 + c4];
        }
    }
    __syncthreads();

    const int dd = tid & 127;          // fixed per thread
    const int lbase = tid >> 7;        // 0 or 1
    __half* Yb = Y + (long long)b * LC * C4;

#pragma unroll
    for (int g = 0; g < 4; g++) {
        const int c = g * DIM + d0 + dd;
        const float bias = dwb[c];
        float wv[5];
#pragma unroll
        for (int t = 0; t < 5; t++) wv[t] = dww[c * 5 + t];

#pragma unroll
        for (int it = 0; it < 32; it++) {
            const int l = lbase + it * 2;
            float acc = bias;
#pragma unroll
            for (int t = 0; t < 5; t++) {
                int l2 = l + t - 2;
                if (l2 < 0 || l2 >= LC) continue;
                float v;
                int o = l2 * 128 + dd;
                if (g == 0)      v = xs[o];
                else if (g == 1) v = as[o];
                else if (g == 2) v = xs[o] * as[o];
                else             v = xs[o] * bs[o];
                acc = fmaf(v, wv[t], acc);
            }
            Yb[(long long)l * C4 + c] = __float2half(acc);
        }
    }
}

__global__ void pe_init_k(float* __restrict__ pe)
{
    int idx = blockIdx.x * 256 + threadIdx.x;
    if (idx >= DIM * LC) return;
    int d = idx / LC, l = idx % LC;
    float fd = (float)d;
    bool even = (d & 1) == 0;
    float freq = even ? powf(10000.f, -fd / 768.f)
                      : -powf(10000.f, (1.f - fd) / 768.f);
    float ph = even ? 0.f : 1.57079632679489662f;
    pe[idx] = sinf((float)l * freq + ph);
}

__global__ void final_head_k(const float* __restrict__ X, const float* __restrict__ w,
                             const float* __restrict__ bias, float* __restrict__ out)
{
    int b = blockIdx.x;
    const float* p = X + (long long)b * (DIM * LC);
    float s = 0.f;
    for (int i = threadIdx.x; i < DIM * LC; i += 256) s = fmaf(p[i], w[i], s);
    __shared__ float sh[256];
    sh[threadIdx.x] = s; __syncthreads();
    for (int o = 128; o > 0; o >>= 1) {
        if (threadIdx.x < o) sh[threadIdx.x] += sh[threadIdx.x + o];
        __syncthreads();
    }
    if (threadIdx.x == 0) out[b] = 1.f / (1.f + expf(-(sh[0] + bias[0])));
}

// ---------------------------------------------------------------------------
// Host-side helpers
// ---------------------------------------------------------------------------
template<int OMODE>
static inline void run_mgemm(const __half* Af, const __half* Bf,
                             float* O, __half* Oh, long long sO, int ldo,
                             const float* bias,
                             const float* R, long long sR,
                             const float* plane,
                             int N, int K, int relu)
{
    cudaFuncSetAttribute((const void*)mgemm_k<OMODE>,
                         cudaFuncAttributeMaxDynamicSharedMemorySize, MT_SMEM);
    dim3 grid(N / 128, BATCH / 2);
    mgemm_k<OMODE><<<grid, 256, MT_SMEM>>>(Af, Bf, O, Oh, sO, ldo, bias, R, sR, plane, K, relu);
}

static inline void run_pgemm(const __half* Af, long long sA, int lda,
                             const __half* Bf, long long sB, int ldb,
                             float* O, __half* Oh, long long sO, int ldo,
                             const float* bM, long long sbM,
                             const float* bN, long long sbN,
                             float alpha, int N, int K)
{
    cudaFuncSetAttribute((const void*)pgemm_k,
                         cudaFuncAttributeMaxDynamicSharedMemorySize, PG_SMEM);
    dim3 grid(N / 64, BATCH);
    pgemm_k<<<grid, 256, PG_SMEM>>>(Af, sA, lda, Bf, sB, ldb, O, Oh, sO, ldo,
                                    bM, sbM, bN, sbN, alpha, K);
}

static inline void run_pgemm_sm(const __half* Af, long long sA, int lda,
                                const __half* Bf, long long sB, int ldb,
                                __half* Oh, long long sO, float alpha, int K)
{
    cudaFuncSetAttribute((const void*)pgemm_sm_k,
                         cudaFuncAttributeMaxDynamicSharedMemorySize, PG_SMEM);
    dim3 grid(1, BATCH);
    pgemm_sm_k<<<grid, 256, PG_SMEM>>>(Af, sA, lda, Bf, sB, ldb, Oh, sO, alpha, K);
}

struct EncW {
    const float *c1dw, *c1db, *c1pw, *c1pb;
    const float *c2dw, *c2db, *c2pw, *c2pb;
    const float *wq, *wk, *wv, *wo;
    const float *fcw, *fcb;
    const float *nbw, *nbb, *n1w, *n1b, *n2w, *n2b, *nEw, *nEb;
};

struct HfW {
    __half *rz, *c1, *c2, *fc, *qkv, *wo;
};

static void enc_block(const float* Xin,
                      float* t2, float* t3,
                      __half* qkf, __half* vT, __half* attnf,
                      float* Xout, const float* outPlane,
                      float* mean, float* rstd,
                      const EncW& w, const HfW& hw,
                      __half* a1, __half* a2)
{
    const float scale = 0.03608439182435161f; // 1/sqrt(768)
    const long long SQK = 64LL * 1536;
    const long long SAT = 64LL * 64;

    ln_stats_k<<<BATCH, 512>>>(Xin, mean, rstd);
    ln_conv_t_k<<<dim3(BATCH, 24), 256>>>(Xin, mean, rstd, w.nbw, w.nbb, w.c1dw, w.c1db, a1);
    run_mgemm<1>(a1, hw.c1, t2, nullptr, SE, 64, w.c1pb, Xin, SE, nullptr, DIM, DIM, 1);
    ln_stats_k<<<BATCH, 512>>>(t2, mean, rstd);
    ln_conv_t_k<<<dim3(BATCH, 24), 256>>>(t2, mean, rstd, w.n1w, w.n1b, w.c2dw, w.c2db, a1);
    run_mgemm<1>(a1, hw.c2, t3, nullptr, SE, 64, w.c2pb, t2, SE, nullptr, DIM, DIM, 1);
    ln_stats_k<<<BATCH, 512>>>(t3, mean, rstd);
    ln_apply_t_k<<<dim3(BATCH, 24), 256>>>(t3, mean, rstd, w.n2w, w.n2b, a1);
    run_mgemm<0>(a1, hw.qkv, nullptr, qkf, SQK, 1536, nullptr, nullptr, 0, nullptr, 1536, DIM, 0);
    run_mgemm<1>(a1, hw.qkv + 2LL * DIM * DIM, nullptr, vT, SE, 64,
                 nullptr, nullptr, 0, nullptr, DIM, DIM, 0);
    run_pgemm_sm(qkf, SQK, 1536, qkf + DIM, SQK, 1536, attnf, SAT, scale, DIM);
    run_pgemm(attnf, SAT, 64, vT, SE, 64,
              nullptr, a2, SE, DIM, nullptr, 0, nullptr, 0, 1.f, DIM, LC);
    run_mgemm<1>(a2, hw.wo, t2, nullptr, SE, 64, nullptr, t3, SE, nullptr, DIM, DIM, 0);
    ln_stats_k<<<BATCH, 512>>>(t2, mean, rstd);
    ln_apply_t_k<<<dim3(BATCH, 24), 256>>>(t2, mean, rstd, w.nEw, w.nEb, a1);
    run_mgemm<1>(a1, hw.fc, Xout, nullptr, SE, 64, w.fcb, t2, SE, outPlane, DIM, DIM, 1);
}

// ---------------------------------------------------------------------------
// Entry point
// ---------------------------------------------------------------------------
extern "C" void kernel_launch(void* const* d_in, const int* in_sizes, int n_in,
                              void* d_out, int out_size)
{
    (void)in_sizes; (void)n_in; (void)out_size;
    const float* x       = (const float*)d_in[0];
    const float* Wv      = (const float*)d_in[1];
    const float* rz_dw_w = (const float*)d_in[2];
    const float* rz_dw_b = (const float*)d_in[3];
    const float* rz_pw_w = (const float*)d_in[4];
    const float* rz_pw_b = (const float*)d_in[5];
    EncW w;
    w.c1dw = (const float*)d_in[6];  w.c1db = (const float*)d_in[7];
    w.c1pw = (const float*)d_in[8];  w.c1pb = (const float*)d_in[9];
    w.c2dw = (const float*)d_in[10]; w.c2db = (const float*)d_in[11];
    w.c2pw = (const float*)d_in[12]; w.c2pb = (const float*)d_in[13];
    w.wq   = (const float*)d_in[14]; w.wk   = (const float*)d_in[15];
    w.wv   = (const float*)d_in[16]; w.wo   = (const float*)d_in[17];
    w.fcw  = (const float*)d_in[18]; w.fcb  = (const float*)d_in[19];
    w.nbw  = (const float*)d_in[20]; w.nbb  = (const float*)d_in[21];
    w.n1w  = (const float*)d_in[22]; w.n1b  = (const float*)d_in[23];
    w.n2w  = (const float*)d_in[24]; w.n2b  = (const float*)d_in[25];
    w.nEw  = (const float*)d_in[26]; w.nEb  = (const float*)d_in[27];
    const float* fcf_w = (const float*)d_in[28];
    const float* fcf_b = (const float*)d_in[29];

    float* pool = nullptr;
    cudaGetSymbolAddress((void**)&pool, g_pool);

    float* c1s  = pool + OFF_C1;
    float* q2s  = pool + OFF_Q2;
    float* S    = pool + OFF_S;
    float* Abuf = pool + OFF_A;
    float* Btb  = pool + OFF_BT;
    float* E[8];
    for (int i = 0; i < 8; i++) E[i] = pool + OFF_E0 + (long long)i * SZ_E;
    float* mean = pool + OFF_MEAN;
    float* rstd = pool + OFF_RSTD;
    float* pe   = pool + OFF_PE;
    float* qpart = pool + OFF_Y;      // fp32 scratch before Yf exists (24 chunks x B*LQ)

    __half* cw3f  = (__half*)(pool + OFF_CW3);
    __half* S1f   = (__half*)(pool + OFF_S1);
    __half* S2f   = (__half*)(pool + OFF_S2);
    __half* Yf    = (__half*)(pool + OFF_Y);
    __half* Qsf   = (__half*)(pool + OFF_QS);
    __half* Qtf   = (__half*)(pool + OFF_QT);
    __half* a1    = (__half*)(pool + OFF_ACT);
    __half* a2    = a1 + SZ_BD;
    __half* qkf   = (__half*)E[4];
    __half* vT    = (__half*)E[5];
    __half* attnf = (__half*)E[6];
    __half* Tf    = (__half*)E[6];
    __half* cTf   = (__half*)E[1];

    HfW hw;
    {
        __half* p = (__half*)(pool + OFF_WB);
        hw.rz  = p; p += (long long)DIM * C4;
        hw.c1  = p; p += (long long)DIM * DIM;
        hw.c2  = p; p += (long long)DIM * DIM;
        hw.fc  = p; p += (long long)DIM * DIM;
        hw.qkv = p; p += 3LL * DIM * DIM;
        hw.wo  = p;
    }

    const long long WDD = (long long)DIM * DIM;

    pe_init_k<<<(DIM * LC + 255) / 256, 256>>>(pe);
    rowdot_k<<<(BATCH * LC * 32) / 256, 256>>>(x, Wv, c1s, LC, 0);
    cboth_k<<<dim3(2, DIM / 32, BATCH), 256>>>(x, Wv + 2 * DIM, cw3f, cTf);
    qboth_k<<<dim3(LQ / 32, DIM / 32, BATCH), 256>>>(x, Wv + DIM, Qsf, Qtf, qpart);
    q2red_k<<<(BATCH * LQ + 255) / 256, 256>>>(qpart, q2s);

    // S = cw3 @ Q^T + c1[:,None] + q2[None,:]   (tensor, per-batch)
    run_pgemm(cw3f, 64LL * DIM, DIM, Qsf, (long long)LQ * DIM, DIM,
              S, nullptr, (long long)LC * LQ, LQ, c1s, LC, q2s, LQ, 1.f, LQ, DIM);

    softmax_rows_f16_k<<<BATCH * LC, 128>>>(S, S1f, LQ);
    softmax_cols_f16_k<<<(BATCH * LQ + 255) / 256, 256>>>(S, S2f);

    // A = S1 @ Q (tensor; B = Q^T) -> fp32
    run_pgemm(S1f, (long long)LC * LQ, LQ, Qtf, (long long)DIM * LQ, LQ,
              Abuf, nullptr, (long long)LC * DIM, DIM, nullptr, 0, nullptr, 0, 1.f, DIM, LQ);

    // T = S1 @ S2^T (tensor) -> fp16
    run_pgemm(S1f, (long long)LC * LQ, LQ, S2f, (long long)LC * LQ, LQ,
              nullptr, Tf, (long long)LC * LC, LC, nullptr, 0, nullptr, 0, 1.f, LC, LQ);

    // Bt = T @ C (tensor; B = C^T) -> fp32
    run_pgemm(Tf, (long long)LC * LC, LC, cTf, SE, LC,
              Btb, nullptr, (long long)LC * DIM, DIM, nullptr, 0, nullptr, 0, 1.f, DIM, LC);

    // smem-tiled concat-gather + depthwise k=5 -> Y fp16 (b,l,c)
    cudaFuncSetAttribute((const void*)rz_dw_tile_k,
                         cudaFuncAttributeMaxDynamicSharedMemorySize, RZ_SMEM);
    rz_dw_tile_k<<<dim3(DIM / 128, BATCH), 256, RZ_SMEM>>>(x, Abuf, Btb, rz_dw_w, rz_dw_b, Yf);

    // ---- weight conversion (fp16, n x k, k-contiguous) ----
    {
        long long trz = (long long)DIM * C4;
        int gs = (int)((WDD + 255) / 256);
        wconv_k<<<(int)((trz + 255) / 256), 256>>>(rz_pw_w, C4, 0, trz, C4, hw.rz);
        wconv_k<<<gs, 256>>>(w.c1pw, DIM, 0, WDD, DIM, hw.c1);
        wconv_k<<<gs, 256>>>(w.c2pw, DIM, 0, WDD, DIM, hw.c2);
        wconv_k<<<gs, 256>>>(w.fcw,  DIM, 0, WDD, DIM, hw.fc);
        wconv_k<<<gs, 256>>>(w.wq,   DIM, 1, WDD, DIM, hw.qkv);
        wconv_k<<<gs, 256>>>(w.wk,   DIM, 1, WDD, DIM, hw.qkv + WDD);
        wconv_k<<<gs, 256>>>(w.wv,   DIM, 1, WDD, DIM, hw.qkv + 2 * WDD);
        wconv_k<<<gs, 256>>>(w.wo,   DIM, 1, WDD, DIM, hw.wo);
    }

    // pointwise 3072 -> 768 (mma): +bias +pe -> E0 (b,d,l)
    run_mgemm<1>(Yf, hw.rz, E[0], nullptr, SE, 64, rz_pw_b, nullptr, 0, pe, DIM, C4, 0);

    // ---- two encoder blocks ----
    enc_block(E[0], E[2], E[3], qkf, vT, attnf, E[7], pe, mean, rstd, w, hw, a1, a2);
    enc_block(E[7], E[2], E[3], qkf, vT, attnf, E[0], nullptr, mean, rstd, w, hw, a1, a2);

    // ---- final sigmoid head ----
    final_head_k<<<BATCH, 256>>>(E[0], fcf_w, fcf_b, (float*)d_out);
}

// round 12
// speedup vs baseline: 2.2159x; 1.0055x over previous
#include <cuda_runtime.h>
#include <cuda_fp16.h>
#include <math.h>
#include <stdint.h>

// ---------------------------------------------------------------------------
// Problem constants
// ---------------------------------------------------------------------------
namespace {
constexpr int BATCH = 128;
constexpr int LC    = 64;
constexpr int LQ    = 448;
constexpr int DIM   = 768;
constexpr int SEQ   = 512;
constexpr int C4    = 3072;

constexpr long long SZ_C1 = (long long)BATCH * LC;
constexpr long long SZ_Q2 = (long long)BATCH * LQ;
constexpr long long SZ_BD = (long long)BATCH * LC * DIM;
constexpr long long SZ_S  = (long long)BATCH * LC * LQ;
constexpr long long SZ_Y  = (long long)BATCH * LC * C4;
constexpr long long SZ_E  = SZ_BD;
constexpr long long SZ_Q  = (long long)BATCH * LQ * DIM;
constexpr long long SE    = (long long)DIM * LC;

constexpr long long OFF_C1  = 0;
constexpr long long OFF_Q2  = OFF_C1 + SZ_C1;
constexpr long long OFF_CW3 = OFF_Q2 + SZ_Q2;    // cw3 fp16
constexpr long long OFF_S   = OFF_CW3 + SZ_BD;
constexpr long long OFF_S1  = OFF_S  + SZ_S;     // S1 fp16
constexpr long long OFF_S2  = OFF_S1 + SZ_S;     // S2 fp16
constexpr long long OFF_A   = OFF_S2 + SZ_S;
constexpr long long OFF_T   = OFF_A  + SZ_BD;
constexpr long long OFF_BT  = OFF_T  + (long long)BATCH * LC * LC;
constexpr long long OFF_Y   = OFF_BT + SZ_BD;    // Y fp16 / early fp32 scratch
constexpr long long OFF_E0  = OFF_Y  + SZ_Y;
constexpr long long OFF_MEAN = OFF_E0 + 8 * SZ_E;
constexpr long long OFF_RSTD = OFF_MEAN + 128;
constexpr long long OFF_PE   = OFF_RSTD + 128;
constexpr long long OFF_PS   = OFF_PE + (long long)DIM * LC;   // LN partials 128*6*2
constexpr long long OFF_ACT  = OFF_PS + 2048;
constexpr long long OFF_WB   = OFF_ACT + 2 * SZ_BD;
constexpr long long WB_FLOATS = ((long long)DIM * C4 + 7LL * DIM * DIM) / 2 + 64;
constexpr long long OFF_QS   = OFF_WB + WB_FLOATS;   // Q fp16 (b,448,768)
constexpr long long OFF_QT   = OFF_QS + SZ_Q;        // Q^T fp16 (b,768,448)
constexpr long long POOL_SZ  = OFF_QT + SZ_Q;

constexpr int NCHUNK = DIM / 64;   // 12 partial chunks (q2 / c1)
} // namespace

__device__ float g_pool[POOL_SZ];

// ---------------------------------------------------------------------------
// Family-portable tensor-core primitives
// ---------------------------------------------------------------------------
__device__ __forceinline__ uint32_t smem_u32(const void* p) {
    uint32_t a;
    asm("{ .reg .u64 t; cvta.to.shared.u64 t, %1; cvt.u32.u64 %0, t; }" : "=r"(a) : "l"(p));
    return a;
}
#define SW128(o) ((o) ^ (((o) >> 3) & 0x70))

__device__ __forceinline__ void cpa16(uint32_t dst, const void* src) {
    asm volatile("cp.async.cg.shared.global [%0], [%1], 16;" :: "r"(dst), "l"(src) : "memory");
}
__device__ __forceinline__ void cp_commit() {
    asm volatile("cp.async.commit_group;" ::: "memory");
}
__device__ __forceinline__ void cp_wait1() {
    asm volatile("cp.async.wait_group 1;" ::: "memory");
}
__device__ __forceinline__ void cp_wait0() {
    asm volatile("cp.async.wait_group 0;" ::: "memory");
}
__device__ __forceinline__ void ldsm4(uint32_t* r, uint32_t a) {
    asm volatile("ldmatrix.sync.aligned.m8n8.x4.shared.b16 {%0,%1,%2,%3}, [%4];"
        : "=r"(r[0]), "=r"(r[1]), "=r"(r[2]), "=r"(r[3]) : "r"(a));
}
__device__ __forceinline__ void mma_f16(float* d, const uint32_t* a, uint32_t b0, uint32_t b1) {
    asm volatile("mma.sync.aligned.m16n8k16.row.col.f32.f16.f16.f32 "
        "{%0,%1,%2,%3}, {%4,%5,%6,%7}, {%8,%9}, {%0,%1,%2,%3};"
        : "+f"(d[0]), "+f"(d[1]), "+f"(d[2]), "+f"(d[3])
        : "r"(a[0]), "r"(a[1]), "r"(a[2]), "r"(a[3]), "r"(b0), "r"(b1));
}

// ---------------------------------------------------------------------------
// mgemm: batch-shared-B tensor GEMM (fp16 in, fp32 accum), 2 CTA/SM
// Optional psum: per-(batch, blockIdx.x) [sum, sumsq] of the stored outputs.
// ---------------------------------------------------------------------------
namespace {
constexpr int MT_TILE = 16384;
constexpr int MT_SMEM = 3 * 2 * MT_TILE + 1024;
constexpr int PG_TILE = 8192;
constexpr int PG_SMEM = 2 * 2 * PG_TILE + 1024;
constexpr int RZ_SMEM = 3 * 64 * 128 * 4 + 16;
}

template<int OMODE>
__global__ void __launch_bounds__(256, 2) mgemm_k(
    const __half* __restrict__ Af,
    const __half* __restrict__ Bf,
    float* __restrict__ O, __half* __restrict__ Oh, long long sO, int ldo,
    const float* __restrict__ bias,
    const float* __restrict__ R, long long sR,
    const float* __restrict__ plane,
    float* __restrict__ psum,
    int K, int relu)
{
    extern __shared__ char dsm[];
    const uint32_t tb = (smem_u32(dsm) + 1023u) & ~1023u;

    const int tid = threadIdx.x, lane = tid & 31, wid = tid >> 5;
    const int n0 = blockIdx.x * 128;
    const int rbase = blockIdx.y * 128;
    const int wm = wid & 1, wn = wid >> 1;

    float acc[4][4][4];
#pragma unroll
    for (int a = 0; a < 4; a++)
#pragma unroll
        for (int b = 0; b < 4; b++)
#pragma unroll
            for (int c = 0; c < 4; c++) acc[a][b][c] = 0.f;

    const int nch = K / 64;

    auto copy_chunk = [&](int ci, int s) {
        const int k0 = ci * 64;
        const uint32_t tA = tb + (s * 2 + 0) * MT_TILE;
        const uint32_t tB = tb + (s * 2 + 1) * MT_TILE;
#pragma unroll
        for (int it = 0; it < 4; it++) {
            int idx = tid + it * 256;
            int r = idx >> 3, c = idx & 7;
            uint32_t doff = SW128((uint32_t)(r * 128 + c * 16));
            cpa16(tA + doff, Af + (long long)(rbase + r) * K + k0 + c * 8);
            cpa16(tB + doff, Bf + (long long)(n0 + r) * K + k0 + c * 8);
        }
    };

    copy_chunk(0, 0); cp_commit();
    copy_chunk(1, 1); cp_commit();

    const int rl = lane & 15, chalf = lane >> 4;

    for (int i = 0; i < nch; i++) {
        if (i + 1 < nch) cp_wait1(); else cp_wait0();
        __syncthreads();
        if (i + 2 < nch) { copy_chunk(i + 2, (i + 2) % 3); cp_commit(); }

        const int s = i % 3;
        const uint32_t tA = tb + (s * 2 + 0) * MT_TILE;
        const uint32_t tB = tb + (s * 2 + 1) * MT_TILE;

#pragma unroll
        for (int ks = 0; ks < 4; ks++) {
            const uint32_t coff = (uint32_t)((ks * 2 + chalf) * 16);
            uint32_t af[4][4], bf[2][4];
#pragma unroll
            for (int mt = 0; mt < 4; mt++) {
                uint32_t off = SW128((uint32_t)((wm * 64 + mt * 16 + rl) * 128) + coff);
                ldsm4(af[mt], tA + off);
            }
#pragma unroll
            for (int np = 0; np < 2; np++) {
                uint32_t off = SW128((uint32_t)((wn * 32 + np * 16 + rl) * 128) + coff);
                ldsm4(bf[np], tB + off);
            }
#pragma unroll
            for (int mt = 0; mt < 4; mt++)
#pragma unroll
                for (int np = 0; np < 2; np++)
#pragma unroll
                    for (int j = 0; j < 2; j++)
                        mma_f16(acc[mt][np * 2 + j], af[mt], bf[np][j], bf[np][j + 2]);
        }
    }

    const int b0 = blockIdx.y * 2;
    float ls = 0.f, ls2 = 0.f;
#pragma unroll
    for (int mt = 0; mt < 4; mt++) {
        int row0 = wm * 64 + mt * 16 + (lane >> 2);
#pragma unroll
        for (int half = 0; half < 2; half++) {
            int row = row0 + half * 8;
            int bi = b0 + (row >> 6), l = row & 63;
            float* Ob = O ? O + (long long)bi * sO : nullptr;
            __half* Ohb = Oh ? Oh + (long long)bi * sO : nullptr;
            const float* Rb = R ? R + (long long)bi * sR : nullptr;
#pragma unroll
            for (int nn = 0; nn < 4; nn++) {
                int n = n0 + wn * 32 + nn * 8 + (lane & 3) * 2;
#pragma unroll
                for (int e = 0; e < 2; e++) {
                    float v = acc[mt][nn][half * 2 + e];
                    int nc = n + e;
                    if (bias) v += bias[nc];
                    if (relu) v = fmaxf(v, 0.f);
                    long long o = (OMODE == 1) ? ((long long)nc * 64 + l)
                                               : ((long long)l * ldo + nc);
                    if (Rb)    v += Rb[o];
                    if (plane) v += plane[o];
                    if (Ohb) Ohb[o] = __float2half(v);
                    else     Ob[o]  = v;
                    if (psum) { ls += v; ls2 += v * v; }
                }
            }
        }
    }

    if (psum) {
        // each thread's outputs belong to batch b0 + wm (rows stay within one 64-block)
#pragma unroll
        for (int o = 16; o > 0; o >>= 1) {
            ls  += __shfl_down_sync(0xffffffffu, ls, o);
            ls2 += __shfl_down_sync(0xffffffffu, ls2, o);
        }
        __shared__ float wsum[8], wsum2[8];
        if (lane == 0) { wsum[wid] = ls; wsum2[wid] = ls2; }
        __syncthreads();
        if (tid < 2) {
            float a  = wsum[tid]  + wsum[tid + 2]  + wsum[tid + 4]  + wsum[tid + 6];
            float a2 = wsum2[tid] + wsum2[tid + 2] + wsum2[tid + 4] + wsum2[tid + 6];
            long long o = ((long long)(b0 + tid) * gridDim.x + blockIdx.x) * 2;
            psum[o] = a; psum[o + 1] = a2;
        }
    }
}

// ---------------------------------------------------------------------------
// pgemm: per-batch GEMM, fp16 in, fp32 accum. Optional fp16 out.
// ---------------------------------------------------------------------------
__global__ void __launch_bounds__(256) pgemm_k(
    const __half* __restrict__ Af, long long sA, int lda,
    const __half* __restrict__ Bf, long long sB, int ldb,
    float* __restrict__ O, __half* __restrict__ Oh, long long sO, int ldo,
    const float* __restrict__ bM, long long sbM,
    const float* __restrict__ bN, long long sbN,
    float alpha, int K)
{
    extern __shared__ char dsm[];
    const uint32_t tb = (smem_u32(dsm) + 1023u) & ~1023u;

    const int tid = threadIdx.x, lane = tid & 31, wid = tid >> 5;
    const int n0 = blockIdx.x * 64;
    const int b  = blockIdx.y;
    const int wm = wid >> 1, wn = wid & 1;

    const __half* Afb = Af + (long long)b * sA;
    const __half* Bfb = Bf + (long long)b * sB + (long long)n0 * ldb;

    float acc[4][4];
#pragma unroll
    for (int a = 0; a < 4; a++)
#pragma unroll
        for (int c = 0; c < 4; c++) acc[a][c] = 0.f;

    const int nch = K / 64;

    auto copy_chunk = [&](int ci, int s) {
        const int k0 = ci * 64;
        const uint32_t tA = tb + (s * 2 + 0) * PG_TILE;
        const uint32_t tB = tb + (s * 2 + 1) * PG_TILE;
#pragma unroll
        for (int it = 0; it < 2; it++) {
            int idx = tid + it * 256;
            int r = idx >> 3, c = idx & 7;
            uint32_t doff = SW128((uint32_t)(r * 128 + c * 16));
            cpa16(tA + doff, Afb + (long long)r * lda + k0 + c * 8);
            cpa16(tB + doff, Bfb + (long long)r * ldb + k0 + c * 8);
        }
    };

    copy_chunk(0, 0); cp_commit();

    const int rl = lane & 15, chalf = lane >> 4;

    for (int i = 0; i < nch; i++) {
        cp_wait0();
        __syncthreads();
        if (i + 1 < nch) { copy_chunk(i + 1, (i + 1) & 1); cp_commit(); }

        const int s = i & 1;
        const uint32_t tA = tb + (s * 2 + 0) * PG_TILE;
        const uint32_t tB = tb + (s * 2 + 1) * PG_TILE;

#pragma unroll
        for (int ks = 0; ks < 4; ks++) {
            const uint32_t coff = (uint32_t)((ks * 2 + chalf) * 16);
            uint32_t af[4], bf[2][4];
            {
                uint32_t off = SW128((uint32_t)((wm * 16 + rl) * 128) + coff);
                ldsm4(af, tA + off);
            }
#pragma unroll
            for (int np = 0; np < 2; np++) {
                uint32_t off = SW128((uint32_t)((wn * 32 + np * 16 + rl) * 128) + coff);
                ldsm4(bf[np], tB + off);
            }
#pragma unroll
            for (int np = 0; np < 2; np++)
#pragma unroll
                for (int j = 0; j < 2; j++)
                    mma_f16(acc[np * 2 + j], af, bf[np][j], bf[np][j + 2]);
        }
    }

    float* Ob = O ? O + (long long)b * sO : nullptr;
    __half* Ohb = Oh ? Oh + (long long)b * sO : nullptr;
    const float* bMp = bM ? bM + (long long)b * sbM : nullptr;
    const float* bNp = bN ? bN + (long long)b * sbN : nullptr;
#pragma unroll
    for (int half = 0; half < 2; half++) {
        int row = wm * 16 + (lane >> 2) + half * 8;
#pragma unroll
        for (int nn = 0; nn < 4; nn++) {
            int n = n0 + wn * 32 + nn * 8 + (lane & 3) * 2;
#pragma unroll
            for (int e = 0; e < 2; e++) {
                float v = acc[nn][half * 2 + e] * alpha;
                int nc = n + e;
                if (bMp) v += bMp[row];
                if (bNp) v += bNp[nc];
                long long o = (long long)row * ldo + nc;
                if (Ohb) Ohb[o] = __float2half(v);
                else     Ob[o]  = v;
            }
        }
    }
}

// ---------------------------------------------------------------------------
// pgemm_sm: per-batch 64x64 GEMM + fused row softmax -> fp16 attn
// ---------------------------------------------------------------------------
__global__ void __launch_bounds__(256) pgemm_sm_k(
    const __half* __restrict__ Af, long long sA, int lda,
    const __half* __restrict__ Bf, long long sB, int ldb,
    __half* __restrict__ Oh, long long sO,
    float alpha, int K)
{
    extern __shared__ char dsm[];
    const uint32_t tb = (smem_u32(dsm) + 1023u) & ~1023u;
    __shared__ float ss[64][65];
    __shared__ float rinv[64];

    const int tid = threadIdx.x, lane = tid & 31, wid = tid >> 5;
    const int b  = blockIdx.y;
    const int wm = wid >> 1, wn = wid & 1;

    const __half* Afb = Af + (long long)b * sA;
    const __half* Bfb = Bf + (long long)b * sB;

    float acc[4][4];
#pragma unroll
    for (int a = 0; a < 4; a++)
#pragma unroll
        for (int c = 0; c < 4; c++) acc[a][c] = 0.f;

    const int nch = K / 64;

    auto copy_chunk = [&](int ci, int s) {
        const int k0 = ci * 64;
        const uint32_t tA = tb + (s * 2 + 0) * PG_TILE;
        const uint32_t tB = tb + (s * 2 + 1) * PG_TILE;
#pragma unroll
        for (int it = 0; it < 2; it++) {
            int idx = tid + it * 256;
            int r = idx >> 3, c = idx & 7;
            uint32_t doff = SW128((uint32_t)(r * 128 + c * 16));
            cpa16(tA + doff, Afb + (long long)r * lda + k0 + c * 8);
            cpa16(tB + doff, Bfb + (long long)r * ldb + k0 + c * 8);
        }
    };

    copy_chunk(0, 0); cp_commit();

    const int rl = lane & 15, chalf = lane >> 4;

    for (int i = 0; i < nch; i++) {
        cp_wait0();
        __syncthreads();
        if (i + 1 < nch) { copy_chunk(i + 1, (i + 1) & 1); cp_commit(); }

        const int s = i & 1;
        const uint32_t tA = tb + (s * 2 + 0) * PG_TILE;
        const uint32_t tB = tb + (s * 2 + 1) * PG_TILE;

#pragma unroll
        for (int ks = 0; ks < 4; ks++) {
            const uint32_t coff = (uint32_t)((ks * 2 + chalf) * 16);
            uint32_t af[4], bf[2][4];
            {
                uint32_t off = SW128((uint32_t)((wm * 16 + rl) * 128) + coff);
                ldsm4(af, tA + off);
            }
#pragma unroll
            for (int np = 0; np < 2; np++) {
                uint32_t off = SW128((uint32_t)((wn * 32 + np * 16 + rl) * 128) + coff);
                ldsm4(bf[np], tB + off);
            }
#pragma unroll
            for (int np = 0; np < 2; np++)
#pragma unroll
                for (int j = 0; j < 2; j++)
                    mma_f16(acc[np * 2 + j], af, bf[np][j], bf[np][j + 2]);
        }
    }

#pragma unroll
    for (int half = 0; half < 2; half++) {
        int row = wm * 16 + (lane >> 2) + half * 8;
#pragma unroll
        for (int nn = 0; nn < 4; nn++) {
            int n = wn * 32 + nn * 8 + (lane & 3) * 2;
#pragma unroll
            for (int e = 0; e < 2; e++)
                ss[row][n + e] = acc[nn][half * 2 + e] * alpha;
        }
    }
    __syncthreads();

    if (tid < 64) {
        float m = -1e30f;
#pragma unroll 8
        for (int c = 0; c < 64; c++) m = fmaxf(m, ss[tid][c]);
        float s = 0.f;
#pragma unroll 8
        for (int c = 0; c < 64; c++) { float e = expf(ss[tid][c] - m); ss[tid][c] = e; s += e; }
        rinv[tid] = 1.f / s;
    }
    __syncthreads();

    __half* Ohb = Oh + (long long)b * sO;
#pragma unroll
    for (int it = 0; it < 16; it++) {
        int idx = tid + it * 256;
        int r = idx >> 6, c = idx & 63;
        Ohb[idx] = __float2half(ss[r][c] * rinv[r]);
    }
}

// ---------------------------------------------------------------------------
// LN finalize from mgemm partials + coalesced apply kernels
// ---------------------------------------------------------------------------
__global__ void ln_fin_k(const float* __restrict__ ps, float* __restrict__ mean,
                         float* __restrict__ rstd)
{
    int b = threadIdx.x;
    if (b >= BATCH) return;
    float s = 0.f, s2 = 0.f;
#pragma unroll
    for (int i = 0; i < 6; i++) {
        s  += ps[((long long)b * 6 + i) * 2];
        s2 += ps[((long long)b * 6 + i) * 2 + 1];
    }
    float m = s / (float)(DIM * LC);
    float var = s2 / (float)(DIM * LC) - m * m;
    mean[b] = m;
    rstd[b] = rsqrtf(var + 1e-5f);
}

// fused ln + dwconv3 + transpose-convert: (b,d,l) float -> (b,l,d) fp16
__global__ void ln_conv_t_k(const float* __restrict__ in, const float* __restrict__ mean,
                            const float* __restrict__ rstd, const float* __restrict__ lw,
                            const float* __restrict__ lb, const float* __restrict__ cw,
                            const float* __restrict__ cb,
                            __half* __restrict__ out)
{
    __shared__ float sm[32][65];
    int b = blockIdx.x, d0 = blockIdx.y * 32;
    float mu = mean[b], rs = rstd[b];
    const float* ib = in + (long long)b * (DIM * LC);
#pragma unroll
    for (int it = 0; it < 8; it++) {
        int idx = threadIdx.x + it * 256;
        int dd = idx >> 6, l = idx & 63;
        int d = d0 + dd;
        const float* rowp = ib + (long long)d * 64;
        int wb = d * 64;
        float a = cb[d];
#pragma unroll
        for (int t = 0; t < 3; t++) {
            int l2 = l + t - 1;
            if (l2 < 0 || l2 >= 64) continue;
            float v = (rowp[l2] - mu) * rs * lw[wb + l2] + lb[wb + l2];
            a = fmaf(v, cw[d * 3 + t], a);
        }
        sm[dd][l] = a;
    }
    __syncthreads();
    __half* ob = out + (long long)b * 64 * 768;
#pragma unroll
    for (int it = 0; it < 8; it++) {
        int idx = threadIdx.x + it * 256;
        int l = idx >> 5, dd = idx & 31;
        ob[(long long)l * 768 + d0 + dd] = __float2half(sm[dd][l]);
    }
}

// fused ln + transpose-convert (no conv)
__global__ void ln_apply_t_k(const float* __restrict__ in, const float* __restrict__ mean,
                             const float* __restrict__ rstd, const float* __restrict__ lw,
                             const float* __restrict__ lb,
                             __half* __restrict__ out)
{
    __shared__ float sm[32][65];
    int b = blockIdx.x, d0 = blockIdx.y * 32;
    float mu = mean[b], rs = rstd[b];
    const float* ib = in + (long long)b * (DIM * LC);
#pragma unroll
    for (int it = 0; it < 8; it++) {
        int idx = threadIdx.x + it * 256;
        int dd = idx >> 6, l = idx & 63;
        int d = d0 + dd;
        float v = (ib[(long long)d * 64 + l] - mu) * rs * lw[d * 64 + l] + lb[d * 64 + l];
        sm[dd][l] = v;
    }
    __syncthreads();
    __half* ob = out + (long long)b * 64 * 768;
#pragma unroll
    for (int it = 0; it < 8; it++) {
        int idx = threadIdx.x + it * 256;
        int l = idx >> 5, dd = idx & 31;
        ob[(long long)l * 768 + d0 + dd] = __float2half(sm[dd][l]);
    }
}

// ---------------------------------------------------------------------------
// Small kernels
// ---------------------------------------------------------------------------
__global__ void wconv_k(const float* __restrict__ src, int ld, int trans,
                        long long total, int KK, __half* __restrict__ out)
{
    long long idx = (long long)blockIdx.x * 256 + threadIdx.x;
    if (idx >= total) return;
    int n = (int)(idx / KK), k = (int)(idx % KK);
    float v = trans ? src[(long long)k * ld + n] : src[(long long)n * ld + k];
    out[idx] = __float2half(v);
}

// Q region: emit Qs (b,448,768), Q^T (b,768,448), q2 partials; vectorized
// tile: 32 j x 64 d; threads 256 = 8 ty x 32 tx; d pair = d0 + 2*tx
__global__ void qboth_k(const float* __restrict__ x, const float* __restrict__ w2,
                        __half* __restrict__ qs, __half* __restrict__ qt,
                        float* __restrict__ qpart)
{
    __shared__ float sm[64][33];
    const int j0 = blockIdx.x * 32, d0 = blockIdx.y * 64, b = blockIdx.z;
    const int tx = threadIdx.x & 31, ty = threadIdx.x >> 5;
    const int d = d0 + tx * 2;
    const float w2a = w2[d], w2b = w2[d + 1];
    __half2* qsb = (__half2*)(qs + (long long)b * LQ * DIM);
#pragma unroll
    for (int r = 0; r < 4; r++) {
        int j = j0 + ty + r * 8;
        float2 v = reinterpret_cast<const float2*>(x)[((long long)b * SEQ + LC + j) * (DIM / 2) + (d >> 1)];
        sm[tx * 2][ty + r * 8]     = v.x;
        sm[tx * 2 + 1][ty + r * 8] = v.y;
        qsb[(long long)j * (DIM / 2) + (d >> 1)] = __floats2half2_rn(v.x, v.y);
        float s = v.x * w2a + v.y * w2b;
#pragma unroll
        for (int o = 16; o > 0; o >>= 1) s += __shfl_down_sync(0xffffffffu, s, o);
        if (tx == 0)
            qpart[(long long)blockIdx.y * (BATCH * LQ) + (long long)b * LQ + j] = s;
    }
    __syncthreads();
    __half2* qtb = (__half2*)(qt + (long long)b * DIM * LQ);
#pragma unroll
    for (int it = 0; it < 4; it++) {
        int idx = threadIdx.x + it * 256;     // 0..1023
        int dd = idx >> 4, j2 = idx & 15;
        qtb[(long long)(d0 + dd) * (LQ / 2) + (j0 >> 1) + j2] =
            __floats2half2_rn(sm[dd][j2 * 2], sm[dd][j2 * 2 + 1]);
    }
}

__global__ void q2red_k(const float* __restrict__ qpart, float* __restrict__ q2)
{
    int i = blockIdx.x * 256 + threadIdx.x;
    if (i >= BATCH * LQ) return;
    float s = 0.f;
#pragma unroll
    for (int c = 0; c < NCHUNK; c++)
        s += qpart[(long long)c * (BATCH * LQ) + i];
    q2[i] = s;
}

// C region: emit cw3 (b,64,768), C^T (b,768,64), c1 partials; vectorized
__global__ void cboth_k(const float* __restrict__ x, const float* __restrict__ w1,
                        const float* __restrict__ w3,
                        __half* __restrict__ cw3, __half* __restrict__ ct,
                        float* __restrict__ cpart)
{
    __shared__ float sm[64][33];
    const int l0 = blockIdx.x * 32, d0 = blockIdx.y * 64, b = blockIdx.z;
    const int tx = threadIdx.x & 31, ty = threadIdx.x >> 5;
    const int d = d0 + tx * 2;
    const float w1a = w1[d], w1b = w1[d + 1];
    const float w3a = w3[d], w3b = w3[d + 1];
    __half2* cwb = (__half2*)(cw3 + (long long)b * LC * DIM);
#pragma unroll
    for (int r = 0; r < 4; r++) {
        int l = l0 + ty + r * 8;
        float2 v = reinterpret_cast<const float2*>(x)[((long long)b * SEQ + l) * (DIM / 2) + (d >> 1)];
        sm[tx * 2][ty + r * 8]     = v.x;
        sm[tx * 2 + 1][ty + r * 8] = v.y;
        cwb[(long long)l * (DIM / 2) + (d >> 1)] = __floats2half2_rn(v.x * w3a, v.y * w3b);
        float s = v.x * w1a + v.y * w1b;
#pragma unroll
        for (int o = 16; o > 0; o >>= 1) s += __shfl_down_sync(0xffffffffu, s, o);
        if (tx == 0)
            cpart[(long long)blockIdx.y * (BATCH * LC) + (long long)b * LC + l] = s;
    }
    __syncthreads();
    __half2* ctb = (__half2*)(ct + (long long)b * SE);
#pragma unroll
    for (int it = 0; it < 4; it++) {
        int idx = threadIdx.x + it * 256;
        int dd = idx >> 4, l2 = idx & 15;
        ctb[(long long)(d0 + dd) * (LC / 2) + (l0 >> 1) + l2] =
            __floats2half2_rn(sm[dd][l2 * 2], sm[dd][l2 * 2 + 1]);
    }
}

__global__ void c1red_k(const float* __restrict__ cpart, float* __restrict__ c1)
{
    int i = blockIdx.x * 256 + threadIdx.x;
    if (i >= BATCH * LC) return;
    float s = 0.f;
#pragma unroll
    for (int c = 0; c < NCHUNK; c++)
        s += cpart[(long long)c * (BATCH * LC) + i];
    c1[i] = s;
}

// row softmax, float in -> fp16 out (front-end S, len=448)
__global__ void softmax_rows_f16_k(const float* __restrict__ in,
                                   __half* __restrict__ out, int len)
{
    long long base = (long long)blockIdx.x * len;
    int t = threadIdx.x;
    __shared__ float sh[128];
    float m = -1e30f;
    for (int i = t; i < len; i += 128) m = fmaxf(m, in[base + i]);
    sh[t] = m; __syncthreads();
    for (int o = 64; o > 0; o >>= 1) { if (t < o) sh[t] = fmaxf(sh[t], sh[t + o]); __syncthreads(); }
    m = sh[0]; __syncthreads();
    float s = 0.f;
    float loc[4];
    for (int i = t, c = 0; i < len; i += 128, c++) { float e = expf(in[base + i] - m); loc[c] = e; s += e; }
    sh[t] = s; __syncthreads();
    for (int o = 64; o > 0; o >>= 1) { if (t < o) sh[t] += sh[t + o]; __syncthreads(); }
    float inv = 1.f / sh[0];
    for (int i = t, c = 0; i < len; i += 128, c++)
        out[base + i] = __float2half(loc[c] * inv);
}

// column softmax over i of S (B,64,448) -> fp16
__global__ void softmax_cols_f16_k(const float* __restrict__ S, __half* __restrict__ out)
{
    int idx = blockIdx.x * blockDim.x + threadIdx.x;
    if (idx >= BATCH * LQ) return;
    int b = idx / LQ, j = idx % LQ;
    long long base = (long long)b * LC * LQ + j;
    float m = -1e30f;
#pragma unroll 4
    for (int i = 0; i < LC; i++) m = fmaxf(m, S[base + (long long)i * LQ]);
    float s = 0.f;
    float e[LC];
#pragma unroll 4
    for (int i = 0; i < LC; i++) { e[i] = expf(S[base + (long long)i * LQ] - m); s += e[i]; }
    float inv = 1.f / s;
#pragma unroll 4
    for (int i = 0; i < LC; i++)
        out[base + (long long)i * LQ] = __float2half(e[i] * inv);
}

// smem-tiled concat-gather + depthwise k=5 -> Y fp16 (b,l,c)
__global__ void __launch_bounds__(256) rz_dw_tile_k(
    const float* __restrict__ x, const float* __restrict__ Abuf,
    const float* __restrict__ Btbuf,
    const float* __restrict__ dww, const float* __restrict__ dwb,
    __half* __restrict__ Y)
{
    extern __shared__ float sb[];
    float* xs = sb;
    float* as = sb + 64 * 128;
    float* bs = sb + 2 * 64 * 128;

    const int d0 = blockIdx.x * 128;
    const int b  = blockIdx.y;
    const int tid = threadIdx.x;

    {
        const float4* xp = reinterpret_cast<const float4*>(x + ((long long)b * SEQ) * DIM);
        const float4* ap = reinterpret_cast<const float4*>(Abuf + (long long)b * LC * DIM);
        const float4* bp = reinterpret_cast<const float4*>(Btbuf + (long long)b * LC * DIM);
        const int d04 = d0 >> 2;
#pragma unroll
        for (int it = 0; it < 8; it++) {
            int idx = tid + it * 256;
            int l = idx >> 5, c4 = idx & 31;
            reinterpret_cast<float4*>(xs)[idx] = xp[(long long)l * (DIM / 4) + d04 + c4];
            reinterpret_cast<float4*>(as)[idx] = ap[(long long)l * (DIM / 4) + d04 + c4];
            reinterpret_cast<float4*>(bs)[idx] = bp[(long long)l * (DIM / 4) + d04 + c4];
        }
    }
    __syncthreads();

    const int dd = tid & 127;
    const int lbase = tid >> 7;
    __half* Yb = Y + (long long)b * LC * C4;

#pragma unroll
    for (int g = 0; g < 4; g++) {
        const int c = g * DIM + d0 + dd;
        const float bias = dwb[c];
        float wv[5];
#pragma unroll
        for (int t = 0; t < 5; t++) wv[t] = dww[c * 5 + t];

#pragma unroll
        for (int it = 0; it < 32; it++) {
            const int l = lbase + it * 2;
            float acc = bias;
#pragma unroll
            for (int t = 0; t < 5; t++) {
                int l2 = l + t - 2;
                if (l2 < 0 || l2 >= LC) continue;
                float v;
                int o = l2 * 128 + dd;
                if (g == 0)      v = xs[o];
                else if (g == 1) v = as[o];
                else if (g == 2) v = xs[o] * as[o];
                else             v = xs[o] * bs[o];
                acc = fmaf(v, wv[t], acc);
            }
            Yb[(long long)l * C4 + c] = __float2half(acc);
        }
    }
}

__global__ void pe_init_k(float* __restrict__ pe)
{
    int idx = blockIdx.x * 256 + threadIdx.x;
    if (idx >= DIM * LC) return;
    int d = idx / LC, l = idx % LC;
    float fd = (float)d;
    bool even = (d & 1) == 0;
    float freq = even ? powf(10000.f, -fd / 768.f)
                      : -powf(10000.f, (1.f - fd) / 768.f);
    float ph = even ? 0.f : 1.57079632679489662f;
    pe[idx] = sinf((float)l * freq + ph);
}

__global__ void final_head_k(const float* __restrict__ X, const float* __restrict__ w,
                             const float* __restrict__ bias, float* __restrict__ out)
{
    int b = blockIdx.x;
    const float* p = X + (long long)b * (DIM * LC);
    float s = 0.f;
    for (int i = threadIdx.x; i < DIM * LC; i += 256) s = fmaf(p[i], w[i], s);
    __shared__ float sh[256];
    sh[threadIdx.x] = s; __syncthreads();
    for (int o = 128; o > 0; o >>= 1) {
        if (threadIdx.x < o) sh[threadIdx.x] += sh[threadIdx.x + o];
        __syncthreads();
    }
    if (threadIdx.x == 0) out[b] = 1.f / (1.f + expf(-(sh[0] + bias[0])));
}

// ---------------------------------------------------------------------------
// Host-side helpers
// ---------------------------------------------------------------------------
template<int OMODE>
static inline void run_mgemm(const __half* Af, const __half* Bf,
                             float* O, __half* Oh, long long sO, int ldo,
                             const float* bias,
                             const float* R, long long sR,
                             const float* plane, float* psum,
                             int N, int K, int relu)
{
    cudaFuncSetAttribute((const void*)mgemm_k<OMODE>,
                         cudaFuncAttributeMaxDynamicSharedMemorySize, MT_SMEM);
    dim3 grid(N / 128, BATCH / 2);
    mgemm_k<OMODE><<<grid, 256, MT_SMEM>>>(Af, Bf, O, Oh, sO, ldo, bias, R, sR, plane, psum, K, relu);
}

static inline void run_pgemm(const __half* Af, long long sA, int lda,
                             const __half* Bf, long long sB, int ldb,
                             float* O, __half* Oh, long long sO, int ldo,
                             const float* bM, long long sbM,
                             const float* bN, long long sbN,
                             float alpha, int N, int K)
{
    cudaFuncSetAttribute((const void*)pgemm_k,
                         cudaFuncAttributeMaxDynamicSharedMemorySize, PG_SMEM);
    dim3 grid(N / 64, BATCH);
    pgemm_k<<<grid, 256, PG_SMEM>>>(Af, sA, lda, Bf, sB, ldb, O, Oh, sO, ldo,
                                    bM, sbM, bN, sbN, alpha, K);
}

static inline void run_pgemm_sm(const __half* Af, long long sA, int lda,
                                const __half* Bf, long long sB, int ldb,
                                __half* Oh, long long sO, float alpha, int K)
{
    cudaFuncSetAttribute((const void*)pgemm_sm_k,
                         cudaFuncAttributeMaxDynamicSharedMemorySize, PG_SMEM);
    dim3 grid(1, BATCH);
    pgemm_sm_k<<<grid, 256, PG_SMEM>>>(Af, sA, lda, Bf, sB, ldb, Oh, sO, alpha, K);
}

struct EncW {
    const float *c1dw, *c1db, *c1pw, *c1pb;
    const float *c2dw, *c2db, *c2pw, *c2pb;
    const float *wq, *wk, *wv, *wo;
    const float *fcw, *fcb;
    const float *nbw, *nbb, *n1w, *n1b, *n2w, *n2b, *nEw, *nEb;
};

struct HfW {
    __half *rz, *c1, *c2, *fc, *qkv, *wo;
};

// Xin's LN stats must already be in psum (written by the producing mgemm).
static void enc_block(const float* Xin,
                      float* t2, float* t3,
                      __half* qkf, __half* vT, __half* attnf,
                      float* Xout, const float* outPlane, float* outPsum,
                      float* mean, float* rstd, float* psum,
                      const EncW& w, const HfW& hw,
                      __half* a1, __half* a2)
{
    const float scale = 0.03608439182435161f; // 1/sqrt(768)
    const long long SQK = 64LL * 1536;
    const long long SAT = 64LL * 64;

    ln_fin_k<<<1, 128>>>(psum, mean, rstd);
    ln_conv_t_k<<<dim3(BATCH, 24), 256>>>(Xin, mean, rstd, w.nbw, w.nbb, w.c1dw, w.c1db, a1);
    run_mgemm<1>(a1, hw.c1, t2, nullptr, SE, 64, w.c1pb, Xin, SE, nullptr, psum, DIM, DIM, 1);
    ln_fin_k<<<1, 128>>>(psum, mean, rstd);
    ln_conv_t_k<<<dim3(BATCH, 24), 256>>>(t2, mean, rstd, w.n1w, w.n1b, w.c2dw, w.c2db, a1);
    run_mgemm<1>(a1, hw.c2, t3, nullptr, SE, 64, w.c2pb, t2, SE, nullptr, psum, DIM, DIM, 1);
    ln_fin_k<<<1, 128>>>(psum, mean, rstd);
    ln_apply_t_k<<<dim3(BATCH, 24), 256>>>(t3, mean, rstd, w.n2w, w.n2b, a1);
    run_mgemm<0>(a1, hw.qkv, nullptr, qkf, SQK, 1536, nullptr, nullptr, 0, nullptr, nullptr, 1536, DIM, 0);
    run_mgemm<1>(a1, hw.qkv + 2LL * DIM * DIM, nullptr, vT, SE, 64,
                 nullptr, nullptr, 0, nullptr, nullptr, DIM, DIM, 0);
    run_pgemm_sm(qkf, SQK, 1536, qkf + DIM, SQK, 1536, attnf, SAT, scale, DIM);
    run_pgemm(attnf, SAT, 64, vT, SE, 64,
              nullptr, a2, SE, DIM, nullptr, 0, nullptr, 0, 1.f, DIM, LC);
    run_mgemm<1>(a2, hw.wo, t2, nullptr, SE, 64, nullptr, t3, SE, nullptr, psum, DIM, DIM, 0);
    ln_fin_k<<<1, 128>>>(psum, mean, rstd);
    ln_apply_t_k<<<dim3(BATCH, 24), 256>>>(t2, mean, rstd, w.nEw, w.nEb, a1);
    run_mgemm<1>(a1, hw.fc, Xout, nullptr, SE, 64, w.fcb, t2, SE, outPlane, outPsum, DIM, DIM, 1);
}

// ---------------------------------------------------------------------------
// Entry point
// ---------------------------------------------------------------------------
extern "C" void kernel_launch(void* const* d_in, const int* in_sizes, int n_in,
                              void* d_out, int out_size)
{
    (void)in_sizes; (void)n_in; (void)out_size;
    const float* x       = (const float*)d_in[0];
    const float* Wv      = (const float*)d_in[1];
    const float* rz_dw_w = (const float*)d_in[2];
    const float* rz_dw_b = (const float*)d_in[3];
    const float* rz_pw_w = (const float*)d_in[4];
    const float* rz_pw_b = (const float*)d_in[5];
    EncW w;
    w.c1dw = (const float*)d_in[6];  w.c1db = (const float*)d_in[7];
    w.c1pw = (const float*)d_in[8];  w.c1pb = (const float*)d_in[9];
    w.c2dw = (const float*)d_in[10]; w.c2db = (const float*)d_in[11];
    w.c2pw = (const float*)d_in[12]; w.c2pb = (const float*)d_in[13];
    w.wq   = (const float*)d_in[14]; w.wk   = (const float*)d_in[15];
    w.wv   = (const float*)d_in[16]; w.wo   = (const float*)d_in[17];
    w.fcw  = (const float*)d_in[18]; w.fcb  = (const float*)d_in[19];
    w.nbw  = (const float*)d_in[20]; w.nbb  = (const float*)d_in[21];
    w.n1w  = (const float*)d_in[22]; w.n1b  = (const float*)d_in[23];
    w.n2w  = (const float*)d_in[24]; w.n2b  = (const float*)d_in[25];
    w.nEw  = (const float*)d_in[26]; w.nEb  = (const float*)d_in[27];
    const float* fcf_w = (const float*)d_in[28];
    const float* fcf_b = (const float*)d_in[29];

    float* pool = nullptr;
    cudaGetSymbolAddress((void**)&pool, g_pool);

    float* c1s  = pool + OFF_C1;
    float* q2s  = pool + OFF_Q2;
    float* S    = pool + OFF_S;
    float* Abuf = pool + OFF_A;
    float* Btb  = pool + OFF_BT;
    float* E[8];
    for (int i = 0; i < 8; i++) E[i] = pool + OFF_E0 + (long long)i * SZ_E;
    float* mean = pool + OFF_MEAN;
    float* rstd = pool + OFF_RSTD;
    float* pe   = pool + OFF_PE;
    float* psum = pool + OFF_PS;
    float* qpart = pool + OFF_Y;                              // 12 * B*LQ floats
    float* cpart = pool + OFF_Y + (long long)NCHUNK * BATCH * LQ;

    __half* cw3f  = (__half*)(pool + OFF_CW3);
    __half* S1f   = (__half*)(pool + OFF_S1);
    __half* S2f   = (__half*)(pool + OFF_S2);
    __half* Yf    = (__half*)(pool + OFF_Y);
    __half* Qsf   = (__half*)(pool + OFF_QS);
    __half* Qtf   = (__half*)(pool + OFF_QT);
    __half* a1    = (__half*)(pool + OFF_ACT);
    __half* a2    = a1 + SZ_BD;
    __half* qkf   = (__half*)E[4];
    __half* vT    = (__half*)E[5];
    __half* attnf = (__half*)E[6];
    __half* Tf    = (__half*)E[6];
    __half* cTf   = (__half*)E[1];

    HfW hw;
    {
        __half* p = (__half*)(pool + OFF_WB);
        hw.rz  = p; p += (long long)DIM * C4;
        hw.c1  = p; p += (long long)DIM * DIM;
        hw.c2  = p; p += (long long)DIM * DIM;
        hw.fc  = p; p += (long long)DIM * DIM;
        hw.qkv = p; p += 3LL * DIM * DIM;
        hw.wo  = p;
    }

    const long long WDD = (long long)DIM * DIM;

    pe_init_k<<<(DIM * LC + 255) / 256, 256>>>(pe);
    cboth_k<<<dim3(2, NCHUNK, BATCH), 256>>>(x, Wv, Wv + 2 * DIM, cw3f, cTf, cpart);
    c1red_k<<<(BATCH * LC + 255) / 256, 256>>>(cpart, c1s);
    qboth_k<<<dim3(LQ / 32, NCHUNK, BATCH), 256>>>(x, Wv + DIM, Qsf, Qtf, qpart);
    q2red_k<<<(BATCH * LQ + 255) / 256, 256>>>(qpart, q2s);

    // S = cw3 @ Q^T + c1[:,None] + q2[None,:]   (tensor, per-batch)
    run_pgemm(cw3f, 64LL * DIM, DIM, Qsf, (long long)LQ * DIM, DIM,
              S, nullptr, (long long)LC * LQ, LQ, c1s, LC, q2s, LQ, 1.f, LQ, DIM);

    softmax_rows_f16_k<<<BATCH * LC, 128>>>(S, S1f, LQ);
    softmax_cols_f16_k<<<(BATCH * LQ + 255) / 256, 256>>>(S, S2f);

    // A = S1 @ Q (tensor; B = Q^T) -> fp32
    run_pgemm(S1f, (long long)LC * LQ, LQ, Qtf, (long long)DIM * LQ, LQ,
              Abuf, nullptr, (long long)LC * DIM, DIM, nullptr, 0, nullptr, 0, 1.f, DIM, LQ);

    // T = S1 @ S2^T (tensor) -> fp16
    run_pgemm(S1f, (long long)LC * LQ, LQ, S2f, (long long)LC * LQ, LQ,
              nullptr, Tf, (long long)LC * LC, LC, nullptr, 0, nullptr, 0, 1.f, LC, LQ);

    // Bt = T @ C (tensor; B = C^T) -> fp32
    run_pgemm(Tf, (long long)LC * LC, LC, cTf, SE, LC,
              Btb, nullptr, (long long)LC * DIM, DIM, nullptr, 0, nullptr, 0, 1.f, DIM, LC);

    // smem-tiled concat-gather + depthwise k=5 -> Y fp16 (b,l,c)
    cudaFuncSetAttribute((const void*)rz_dw_tile_k,
                         cudaFuncAttributeMaxDynamicSharedMemorySize, RZ_SMEM);
    rz_dw_tile_k<<<dim3(DIM / 128, BATCH), 256, RZ_SMEM>>>(x, Abuf, Btb, rz_dw_w, rz_dw_b, Yf);

    // ---- weight conversion (fp16, n x k, k-contiguous) ----
    {
        long long trz = (long long)DIM * C4;
        int gs = (int)((WDD + 255) / 256);
        wconv_k<<<(int)((trz + 255) / 256), 256>>>(rz_pw_w, C4, 0, trz, C4, hw.rz);
        wconv_k<<<gs, 256>>>(w.c1pw, DIM, 0, WDD, DIM, hw.c1);
        wconv_k<<<gs, 256>>>(w.c2pw, DIM, 0, WDD, DIM, hw.c2);
        wconv_k<<<gs, 256>>>(w.fcw,  DIM, 0, WDD, DIM, hw.fc);
        wconv_k<<<gs, 256>>>(w.wq,   DIM, 1, WDD, DIM, hw.qkv);
        wconv_k<<<gs, 256>>>(w.wk,   DIM, 1, WDD, DIM, hw.qkv + WDD);
        wconv_k<<<gs, 256>>>(w.wv,   DIM, 1, WDD, DIM, hw.qkv + 2 * WDD);
        wconv_k<<<gs, 256>>>(w.wo,   DIM, 1, WDD, DIM, hw.wo);
    }

    // pointwise 3072 -> 768 (mma): +bias +pe -> E0 (b,d,l), + LN stats
    run_mgemm<1>(Yf, hw.rz, E[0], nullptr, SE, 64, rz_pw_b, nullptr, 0, pe, psum, DIM, C4, 0);

    // ---- two encoder blocks ----
    enc_block(E[0], E[2], E[3], qkf, vT, attnf, E[7], pe, psum, mean, rstd, psum, w, hw, a1, a2);
    enc_block(E[7], E[2], E[3], qkf, vT, attnf, E[0], nullptr, nullptr, mean, rstd, psum, w, hw, a1, a2);

    // ---- final sigmoid head ----
    final_head_k<<<BATCH, 256>>>(E[0], fcf_w, fcf_b, (float*)d_out);
}

// round 13
// speedup vs baseline: 2.2838x; 1.0307x over previous
#include <cuda_runtime.h>
#include <cuda_fp16.h>
#include <math.h>
#include <stdint.h>

// ---------------------------------------------------------------------------
// Problem constants
// ---------------------------------------------------------------------------
namespace {
constexpr int BATCH = 128;
constexpr int LC    = 64;
constexpr int LQ    = 448;
constexpr int DIM   = 768;
constexpr int SEQ   = 512;
constexpr int C4    = 3072;
constexpr int SEi   = DIM * LC;

constexpr long long SZ_C1 = (long long)BATCH * LC;
constexpr long long SZ_Q2 = (long long)BATCH * LQ;
constexpr long long SZ_BD = (long long)BATCH * LC * DIM;
constexpr long long SZ_S  = (long long)BATCH * LC * LQ;
constexpr long long SZ_Y  = (long long)BATCH * LC * C4;
constexpr long long SZ_E  = SZ_BD;
constexpr long long SZ_Q  = (long long)BATCH * LQ * DIM;
constexpr long long SE    = (long long)DIM * LC;

constexpr long long OFF_C1  = 0;
constexpr long long OFF_Q2  = OFF_C1 + SZ_C1;
constexpr long long OFF_CW3 = OFF_Q2 + SZ_Q2;
constexpr long long OFF_S   = OFF_CW3 + SZ_BD;
constexpr long long OFF_S1  = OFF_S  + SZ_S;
constexpr long long OFF_S2  = OFF_S1 + SZ_S;
constexpr long long OFF_A   = OFF_S2 + SZ_S;
constexpr long long OFF_T   = OFF_A  + SZ_BD;
constexpr long long OFF_BT  = OFF_T  + (long long)BATCH * LC * LC;
constexpr long long OFF_Y   = OFF_BT + SZ_BD;
constexpr long long OFF_E0  = OFF_Y  + SZ_Y;
constexpr long long OFF_PE   = OFF_E0 + 8 * SZ_E;
constexpr long long OFF_PS   = OFF_PE + (long long)DIM * LC;   // LN partials 128*6*2
constexpr long long OFF_ACT  = OFF_PS + 2048;
constexpr long long OFF_WB   = OFF_ACT + 2 * SZ_BD;
constexpr long long WB_FLOATS = ((long long)DIM * C4 + 7LL * DIM * DIM) / 2 + 64;
constexpr long long OFF_QS   = OFF_WB + WB_FLOATS;
constexpr long long OFF_QT   = OFF_QS + SZ_Q;
constexpr long long POOL_SZ  = OFF_QT + SZ_Q;

constexpr int NCHUNK = DIM / 64;   // 12 partial chunks (q2 / c1)
} // namespace

__device__ float g_pool[POOL_SZ];

// ---------------------------------------------------------------------------
// Family-portable tensor-core primitives
// ---------------------------------------------------------------------------
__device__ __forceinline__ uint32_t smem_u32(const void* p) {
    uint32_t a;
    asm("{ .reg .u64 t; cvta.to.shared.u64 t, %1; cvt.u32.u64 %0, t; }" : "=r"(a) : "l"(p));
    return a;
}
#define SW128(o) ((o) ^ (((o) >> 3) & 0x70))

__device__ __forceinline__ void cpa16(uint32_t dst, const void* src) {
    asm volatile("cp.async.cg.shared.global [%0], [%1], 16;" :: "r"(dst), "l"(src) : "memory");
}
__device__ __forceinline__ void cp_commit() {
    asm volatile("cp.async.commit_group;" ::: "memory");
}
__device__ __forceinline__ void cp_wait1() {
    asm volatile("cp.async.wait_group 1;" ::: "memory");
}
__device__ __forceinline__ void cp_wait0() {
    asm volatile("cp.async.wait_group 0;" ::: "memory");
}
__device__ __forceinline__ void ldsm4(uint32_t* r, uint32_t a) {
    asm volatile("ldmatrix.sync.aligned.m8n8.x4.shared.b16 {%0,%1,%2,%3}, [%4];"
        : "=r"(r[0]), "=r"(r[1]), "=r"(r[2]), "=r"(r[3]) : "r"(a));
}
__device__ __forceinline__ void mma_f16(float* d, const uint32_t* a, uint32_t b0, uint32_t b1) {
    asm volatile("mma.sync.aligned.m16n8k16.row.col.f32.f16.f16.f32 "
        "{%0,%1,%2,%3}, {%4,%5,%6,%7}, {%8,%9}, {%0,%1,%2,%3};"
        : "+f"(d[0]), "+f"(d[1]), "+f"(d[2]), "+f"(d[3])
        : "r"(a[0]), "r"(a[1]), "r"(a[2]), "r"(a[3]), "r"(b0), "r"(b1));
}

// ---------------------------------------------------------------------------
// mgemm: batch-shared-B tensor GEMM (fp16 in, fp32 accum), 2 CTA/SM
// Optional psum: per-(batch, blockIdx.x) [sum, sumsq] of stored outputs.
// ---------------------------------------------------------------------------
namespace {
constexpr int MT_TILE = 16384;
constexpr int MT_SMEM = 3 * 2 * MT_TILE + 1024;
constexpr int PG_TILE = 8192;
constexpr int PG_SMEM = 2 * 2 * PG_TILE + 1024;
constexpr int RZ_SMEM = 3 * 64 * 128 * 4 + 16;
}

template<int OMODE>
__global__ void __launch_bounds__(256, 2) mgemm_k(
    const __half* __restrict__ Af,
    const __half* __restrict__ Bf,
    float* __restrict__ O, __half* __restrict__ Oh, long long sO, int ldo,
    const float* __restrict__ bias,
    const float* __restrict__ R, long long sR,
    const float* __restrict__ plane,
    float* __restrict__ psum,
    int K, int relu)
{
    extern __shared__ char dsm[];
    const uint32_t tb = (smem_u32(dsm) + 1023u) & ~1023u;

    const int tid = threadIdx.x, lane = tid & 31, wid = tid >> 5;
    const int n0 = blockIdx.x * 128;
    const int rbase = blockIdx.y * 128;
    const int wm = wid & 1, wn = wid >> 1;

    float acc[4][4][4];
#pragma unroll
    for (int a = 0; a < 4; a++)
#pragma unroll
        for (int b = 0; b < 4; b++)
#pragma unroll
            for (int c = 0; c < 4; c++) acc[a][b][c] = 0.f;

    const int nch = K / 64;

    auto copy_chunk = [&](int ci, int s) {
        const int k0 = ci * 64;
        const uint32_t tA = tb + (s * 2 + 0) * MT_TILE;
        const uint32_t tB = tb + (s * 2 + 1) * MT_TILE;
#pragma unroll
        for (int it = 0; it < 4; it++) {
            int idx = tid + it * 256;
            int r = idx >> 3, c = idx & 7;
            uint32_t doff = SW128((uint32_t)(r * 128 + c * 16));
            cpa16(tA + doff, Af + (long long)(rbase + r) * K + k0 + c * 8);
            cpa16(tB + doff, Bf + (long long)(n0 + r) * K + k0 + c * 8);
        }
    };

    copy_chunk(0, 0); cp_commit();
    copy_chunk(1, 1); cp_commit();

    const int rl = lane & 15, chalf = lane >> 4;

    for (int i = 0; i < nch; i++) {
        if (i + 1 < nch) cp_wait1(); else cp_wait0();
        __syncthreads();
        if (i + 2 < nch) { copy_chunk(i + 2, (i + 2) % 3); cp_commit(); }

        const int s = i % 3;
        const uint32_t tA = tb + (s * 2 + 0) * MT_TILE;
        const uint32_t tB = tb + (s * 2 + 1) * MT_TILE;

#pragma unroll
        for (int ks = 0; ks < 4; ks++) {
            const uint32_t coff = (uint32_t)((ks * 2 + chalf) * 16);
            uint32_t af[4][4], bf[2][4];
#pragma unroll
            for (int mt = 0; mt < 4; mt++) {
                uint32_t off = SW128((uint32_t)((wm * 64 + mt * 16 + rl) * 128) + coff);
                ldsm4(af[mt], tA + off);
            }
#pragma unroll
            for (int np = 0; np < 2; np++) {
                uint32_t off = SW128((uint32_t)((wn * 32 + np * 16 + rl) * 128) + coff);
                ldsm4(bf[np], tB + off);
            }
#pragma unroll
            for (int mt = 0; mt < 4; mt++)
#pragma unroll
                for (int np = 0; np < 2; np++)
#pragma unroll
                    for (int j = 0; j < 2; j++)
                        mma_f16(acc[mt][np * 2 + j], af[mt], bf[np][j], bf[np][j + 2]);
        }
    }

    const int b0 = blockIdx.y * 2;
    float ls = 0.f, ls2 = 0.f;
#pragma unroll
    for (int mt = 0; mt < 4; mt++) {
        int row0 = wm * 64 + mt * 16 + (lane >> 2);
#pragma unroll
        for (int half = 0; half < 2; half++) {
            int row = row0 + half * 8;
            int bi = b0 + (row >> 6), l = row & 63;
            float* Ob = O ? O + (long long)bi * sO : nullptr;
            __half* Ohb = Oh ? Oh + (long long)bi * sO : nullptr;
            const float* Rb = R ? R + (long long)bi * sR : nullptr;
#pragma unroll
            for (int nn = 0; nn < 4; nn++) {
                int n = n0 + wn * 32 + nn * 8 + (lane & 3) * 2;
#pragma unroll
                for (int e = 0; e < 2; e++) {
                    float v = acc[mt][nn][half * 2 + e];
                    int nc = n + e;
                    if (bias) v += bias[nc];
                    if (relu) v = fmaxf(v, 0.f);
                    long long o = (OMODE == 1) ? ((long long)nc * 64 + l)
                                               : ((long long)l * ldo + nc);
                    if (Rb)    v += Rb[o];
                    if (plane) v += plane[o];
                    if (Ohb) Ohb[o] = __float2half(v);
                    else     Ob[o]  = v;
                    if (psum) { ls += v; ls2 += v * v; }
                }
            }
        }
    }

    if (psum) {
#pragma unroll
        for (int o = 16; o > 0; o >>= 1) {
            ls  += __shfl_down_sync(0xffffffffu, ls, o);
            ls2 += __shfl_down_sync(0xffffffffu, ls2, o);
        }
        __shared__ float wsum[8], wsum2[8];
        if (lane == 0) { wsum[wid] = ls; wsum2[wid] = ls2; }
        __syncthreads();
        if (tid < 2) {
            float a  = wsum[tid]  + wsum[tid + 2]  + wsum[tid + 4]  + wsum[tid + 6];
            float a2 = wsum2[tid] + wsum2[tid + 2] + wsum2[tid + 4] + wsum2[tid + 6];
            long long o = ((long long)(b0 + tid) * gridDim.x + blockIdx.x) * 2;
            psum[o] = a; psum[o + 1] = a2;
        }
    }
}

// ---------------------------------------------------------------------------
// pgemm: per-batch GEMM, fp16 in, fp32 accum. Optional fp16 out.
// ---------------------------------------------------------------------------
__global__ void __launch_bounds__(256) pgemm_k(
    const __half* __restrict__ Af, long long sA, int lda,
    const __half* __restrict__ Bf, long long sB, int ldb,
    float* __restrict__ O, __half* __restrict__ Oh, long long sO, int ldo,
    const float* __restrict__ bM, long long sbM,
    const float* __restrict__ bN, long long sbN,
    float alpha, int K)
{
    extern __shared__ char dsm[];
    const uint32_t tb = (smem_u32(dsm) + 1023u) & ~1023u;

    const int tid = threadIdx.x, lane = tid & 31, wid = tid >> 5;
    const int n0 = blockIdx.x * 64;
    const int b  = blockIdx.y;
    const int wm = wid >> 1, wn = wid & 1;

    const __half* Afb = Af + (long long)b * sA;
    const __half* Bfb = Bf + (long long)b * sB + (long long)n0 * ldb;

    float acc[4][4];
#pragma unroll
    for (int a = 0; a < 4; a++)
#pragma unroll
        for (int c = 0; c < 4; c++) acc[a][c] = 0.f;

    const int nch = K / 64;

    auto copy_chunk = [&](int ci, int s) {
        const int k0 = ci * 64;
        const uint32_t tA = tb + (s * 2 + 0) * PG_TILE;
        const uint32_t tB = tb + (s * 2 + 1) * PG_TILE;
#pragma unroll
        for (int it = 0; it < 2; it++) {
            int idx = tid + it * 256;
            int r = idx >> 3, c = idx & 7;
            uint32_t doff = SW128((uint32_t)(r * 128 + c * 16));
            cpa16(tA + doff, Afb + (long long)r * lda + k0 + c * 8);
            cpa16(tB + doff, Bfb + (long long)r * ldb + k0 + c * 8);
        }
    };

    copy_chunk(0, 0); cp_commit();

    const int rl = lane & 15, chalf = lane >> 4;

    for (int i = 0; i < nch; i++) {
        cp_wait0();
        __syncthreads();
        if (i + 1 < nch) { copy_chunk(i + 1, (i + 1) & 1); cp_commit(); }

        const int s = i & 1;
        const uint32_t tA = tb + (s * 2 + 0) * PG_TILE;
        const uint32_t tB = tb + (s * 2 + 1) * PG_TILE;

#pragma unroll
        for (int ks = 0; ks < 4; ks++) {
            const uint32_t coff = (uint32_t)((ks * 2 + chalf) * 16);
            uint32_t af[4], bf[2][4];
            {
                uint32_t off = SW128((uint32_t)((wm * 16 + rl) * 128) + coff);
                ldsm4(af, tA + off);
            }
#pragma unroll
            for (int np = 0; np < 2; np++) {
                uint32_t off = SW128((uint32_t)((wn * 32 + np * 16 + rl) * 128) + coff);
                ldsm4(bf[np], tB + off);
            }
#pragma unroll
            for (int np = 0; np < 2; np++)
#pragma unroll
                for (int j = 0; j < 2; j++)
                    mma_f16(acc[np * 2 + j], af, bf[np][j], bf[np][j + 2]);
        }
    }

    float* Ob = O ? O + (long long)b * sO : nullptr;
    __half* Ohb = Oh ? Oh + (long long)b * sO : nullptr;
    const float* bMp = bM ? bM + (long long)b * sbM : nullptr;
    const float* bNp = bN ? bN + (long long)b * sbN : nullptr;
#pragma unroll
    for (int half = 0; half < 2; half++) {
        int row = wm * 16 + (lane >> 2) + half * 8;
#pragma unroll
        for (int nn = 0; nn < 4; nn++) {
            int n = n0 + wn * 32 + nn * 8 + (lane & 3) * 2;
#pragma unroll
            for (int e = 0; e < 2; e++) {
                float v = acc[nn][half * 2 + e] * alpha;
                int nc = n + e;
                if (bMp) v += bMp[row];
                if (bNp) v += bNp[nc];
                long long o = (long long)row * ldo + nc;
                if (Ohb) Ohb[o] = __float2half(v);
                else     Ob[o]  = v;
            }
        }
    }
}

// ---------------------------------------------------------------------------
// pgemm_sm: per-batch 64x64 GEMM + fused row softmax -> fp16 attn
// ---------------------------------------------------------------------------
__global__ void __launch_bounds__(256) pgemm_sm_k(
    const __half* __restrict__ Af, long long sA, int lda,
    const __half* __restrict__ Bf, long long sB, int ldb,
    __half* __restrict__ Oh, long long sO,
    float alpha, int K)
{
    extern __shared__ char dsm[];
    const uint32_t tb = (smem_u32(dsm) + 1023u) & ~1023u;
    __shared__ float ss[64][65];
    __shared__ float rinv[64];

    const int tid = threadIdx.x, lane = tid & 31, wid = tid >> 5;
    const int b  = blockIdx.y;
    const int wm = wid >> 1, wn = wid & 1;

    const __half* Afb = Af + (long long)b * sA;
    const __half* Bfb = Bf + (long long)b * sB;

    float acc[4][4];
#pragma unroll
    for (int a = 0; a < 4; a++)
#pragma unroll
        for (int c = 0; c < 4; c++) acc[a][c] = 0.f;

    const int nch = K / 64;

    auto copy_chunk = [&](int ci, int s) {
        const int k0 = ci * 64;
        const uint32_t tA = tb + (s * 2 + 0) * PG_TILE;
        const uint32_t tB = tb + (s * 2 + 1) * PG_TILE;
#pragma unroll
        for (int it = 0; it < 2; it++) {
            int idx = tid + it * 256;
            int r = idx >> 3, c = idx & 7;
            uint32_t doff = SW128((uint32_t)(r * 128 + c * 16));
            cpa16(tA + doff, Afb + (long long)r * lda + k0 + c * 8);
            cpa16(tB + doff, Bfb + (long long)r * ldb + k0 + c * 8);
        }
    };

    copy_chunk(0, 0); cp_commit();

    const int rl = lane & 15, chalf = lane >> 4;

    for (int i = 0; i < nch; i++) {
        cp_wait0();
        __syncthreads();
        if (i + 1 < nch) { copy_chunk(i + 1, (i + 1) & 1); cp_commit(); }

        const int s = i & 1;
        const uint32_t tA = tb + (s * 2 + 0) * PG_TILE;
        const uint32_t tB = tb + (s * 2 + 1) * PG_TILE;

#pragma unroll
        for (int ks = 0; ks < 4; ks++) {
            const uint32_t coff = (uint32_t)((ks * 2 + chalf) * 16);
            uint32_t af[4], bf[2][4];
            {
                uint32_t off = SW128((uint32_t)((wm * 16 + rl) * 128) + coff);
                ldsm4(af, tA + off);
            }
#pragma unroll
            for (int np = 0; np < 2; np++) {
                uint32_t off = SW128((uint32_t)((wn * 32 + np * 16 + rl) * 128) + coff);
                ldsm4(bf[np], tB + off);
            }
#pragma unroll
            for (int np = 0; np < 2; np++)
#pragma unroll
                for (int j = 0; j < 2; j++)
                    mma_f16(acc[np * 2 + j], af, bf[np][j], bf[np][j + 2]);
        }
    }

#pragma unroll
    for (int half = 0; half < 2; half++) {
        int row = wm * 16 + (lane >> 2) + half * 8;
#pragma unroll
        for (int nn = 0; nn < 4; nn++) {
            int n = wn * 32 + nn * 8 + (lane & 3) * 2;
#pragma unroll
            for (int e = 0; e < 2; e++)
                ss[row][n + e] = acc[nn][half * 2 + e] * alpha;
        }
    }
    __syncthreads();

    if (tid < 64) {
        float m = -1e30f;
#pragma unroll 8
        for (int c = 0; c < 64; c++) m = fmaxf(m, ss[tid][c]);
        float s = 0.f;
#pragma unroll 8
        for (int c = 0; c < 64; c++) { float e = expf(ss[tid][c] - m); ss[tid][c] = e; s += e; }
        rinv[tid] = 1.f / s;
    }
    __syncthreads();

    __half* Ohb = Oh + (long long)b * sO;
#pragma unroll
    for (int it = 0; it < 16; it++) {
        int idx = tid + it * 256;
        int r = idx >> 6, c = idx & 63;
        Ohb[idx] = __float2half(ss[r][c] * rinv[r]);
    }
}

// ---------------------------------------------------------------------------
// LN apply kernels (stats finalized inline from mgemm psum partials)
// ---------------------------------------------------------------------------
__device__ __forceinline__ void ln_stats_from_psum(const float* ps, int b,
                                                   float& mu, float& rs)
{
    __shared__ float smu, srs;
    if (threadIdx.x == 0) {
        float s = 0.f, s2 = 0.f;
#pragma unroll
        for (int i = 0; i < 6; i++) {
            s  += ps[((long long)b * 6 + i) * 2];
            s2 += ps[((long long)b * 6 + i) * 2 + 1];
        }
        float m = s / (float)SEi;
        smu = m;
        srs = rsqrtf(s2 / (float)SEi - m * m + 1e-5f);
    }
    __syncthreads();
    mu = smu; rs = srs;
}

// fused ln + dwconv3 + transpose-convert: (b,d,l) float -> (b,l,d) fp16
__global__ void ln_conv_t_k(const float* __restrict__ in, const float* __restrict__ ps,
                            const float* __restrict__ lw,
                            const float* __restrict__ lb, const float* __restrict__ cw,
                            const float* __restrict__ cb,
                            __half* __restrict__ out)
{
    __shared__ float sm[32][65];
    int b = blockIdx.x, d0 = blockIdx.y * 32;
    float mu, rs;
    ln_stats_from_psum(ps, b, mu, rs);
    const float* ib = in + (long long)b * (DIM * LC);
#pragma unroll
    for (int it = 0; it < 8; it++) {
        int idx = threadIdx.x + it * 256;
        int dd = idx >> 6, l = idx & 63;
        int d = d0 + dd;
        const float* rowp = ib + (long long)d * 64;
        int wb = d * 64;
        float a = cb[d];
#pragma unroll
        for (int t = 0; t < 3; t++) {
            int l2 = l + t - 1;
            if (l2 < 0 || l2 >= 64) continue;
            float v = (rowp[l2] - mu) * rs * lw[wb + l2] + lb[wb + l2];
            a = fmaf(v, cw[d * 3 + t], a);
        }
        sm[dd][l] = a;
    }
    __syncthreads();
    __half* ob = out + (long long)b * 64 * 768;
#pragma unroll
    for (int it = 0; it < 8; it++) {
        int idx = threadIdx.x + it * 256;
        int l = idx >> 5, dd = idx & 31;
        ob[(long long)l * 768 + d0 + dd] = __float2half(sm[dd][l]);
    }
}

// fused ln + transpose-convert (no conv)
__global__ void ln_apply_t_k(const float* __restrict__ in, const float* __restrict__ ps,
                             const float* __restrict__ lw,
                             const float* __restrict__ lb,
                             __half* __restrict__ out)
{
    __shared__ float sm[32][65];
    int b = blockIdx.x, d0 = blockIdx.y * 32;
    float mu, rs;
    ln_stats_from_psum(ps, b, mu, rs);
    const float* ib = in + (long long)b * (DIM * LC);
#pragma unroll
    for (int it = 0; it < 8; it++) {
        int idx = threadIdx.x + it * 256;
        int dd = idx >> 6, l = idx & 63;
        int d = d0 + dd;
        float v = (ib[(long long)d * 64 + l] - mu) * rs * lw[d * 64 + l] + lb[d * 64 + l];
        sm[dd][l] = v;
    }
    __syncthreads();
    __half* ob = out + (long long)b * 64 * 768;
#pragma unroll
    for (int it = 0; it < 8; it++) {
        int idx = threadIdx.x + it * 256;
        int l = idx >> 5, dd = idx & 31;
        ob[(long long)l * 768 + d0 + dd] = __float2half(sm[dd][l]);
    }
}

// ---------------------------------------------------------------------------
// Small kernels
// ---------------------------------------------------------------------------
// rz weight (DIM x C4) conversion
__global__ void wconv_k(const float* __restrict__ src, int ld, int trans,
                        long long total, int KK, __half* __restrict__ out)
{
    long long idx = (long long)blockIdx.x * 256 + threadIdx.x;
    if (idx >= total) return;
    int n = (int)(idx / KK), k = (int)(idx % KK);
    float v = trans ? src[(long long)k * ld + n] : src[(long long)n * ld + k];
    out[idx] = __float2half(v);
}

// 7 DIM x DIM weights in one launch; blockIdx.y selects; dst contiguous
__global__ void wconv7_k(const float* __restrict__ s0, const float* __restrict__ s1,
                         const float* __restrict__ s2, const float* __restrict__ s3,
                         const float* __restrict__ s4, const float* __restrict__ s5,
                         const float* __restrict__ s6,
                         __half* __restrict__ dst)
{
    const int wi = blockIdx.y;
    const float* src = wi == 0 ? s0 : wi == 1 ? s1 : wi == 2 ? s2 : wi == 3 ? s3
                     : wi == 4 ? s4 : wi == 5 ? s5 : s6;
    const int trans = (wi >= 3);   // wq,wk,wv,wo stored k x n
    long long idx = (long long)blockIdx.x * 256 + threadIdx.x;
    if (idx >= (long long)DIM * DIM) return;
    int n = (int)(idx / DIM), k = (int)(idx % DIM);
    float v = trans ? src[(long long)k * DIM + n] : src[(long long)n * DIM + k];
    dst[(long long)wi * DIM * DIM + idx] = __float2half(v);
}

// Q region: emit Qs, Q^T, q2 partials; vectorized
__global__ void qboth_k(const float* __restrict__ x, const float* __restrict__ w2,
                        __half* __restrict__ qs, __half* __restrict__ qt,
                        float* __restrict__ qpart)
{
    __shared__ float sm[64][33];
    const int j0 = blockIdx.x * 32, d0 = blockIdx.y * 64, b = blockIdx.z;
    const int tx = threadIdx.x & 31, ty = threadIdx.x >> 5;
    const int d = d0 + tx * 2;
    const float w2a = w2[d], w2b = w2[d + 1];
    __half2* qsb = (__half2*)(qs + (long long)b * LQ * DIM);
#pragma unroll
    for (int r = 0; r < 4; r++) {
        int j = j0 + ty + r * 8;
        float2 v = reinterpret_cast<const float2*>(x)[((long long)b * SEQ + LC + j) * (DIM / 2) + (d >> 1)];
        sm[tx * 2][ty + r * 8]     = v.x;
        sm[tx * 2 + 1][ty + r * 8] = v.y;
        qsb[(long long)j * (DIM / 2) + (d >> 1)] = __floats2half2_rn(v.x, v.y);
        float s = v.x * w2a + v.y * w2b;
#pragma unroll
        for (int o = 16; o > 0; o >>= 1) s += __shfl_down_sync(0xffffffffu, s, o);
        if (tx == 0)
            qpart[(long long)blockIdx.y * (BATCH * LQ) + (long long)b * LQ + j] = s;
    }
    __syncthreads();
    __half2* qtb = (__half2*)(qt + (long long)b * DIM * LQ);
#pragma unroll
    for (int it = 0; it < 4; it++) {
        int idx = threadIdx.x + it * 256;
        int dd = idx >> 4, j2 = idx & 15;
        qtb[(long long)(d0 + dd) * (LQ / 2) + (j0 >> 1) + j2] =
            __floats2half2_rn(sm[dd][j2 * 2], sm[dd][j2 * 2 + 1]);
    }
}

__global__ void q2red_k(const float* __restrict__ qpart, float* __restrict__ q2)
{
    int i = blockIdx.x * 256 + threadIdx.x;
    if (i >= BATCH * LQ) return;
    float s = 0.f;
#pragma unroll
    for (int c = 0; c < NCHUNK; c++)
        s += qpart[(long long)c * (BATCH * LQ) + i];
    q2[i] = s;
}

// C region: emit cw3, C^T, c1 partials; vectorized
__global__ void cboth_k(const float* __restrict__ x, const float* __restrict__ w1,
                        const float* __restrict__ w3,
                        __half* __restrict__ cw3, __half* __restrict__ ct,
                        float* __restrict__ cpart)
{
    __shared__ float sm[64][33];
    const int l0 = blockIdx.x * 32, d0 = blockIdx.y * 64, b = blockIdx.z;
    const int tx = threadIdx.x & 31, ty = threadIdx.x >> 5;
    const int d = d0 + tx * 2;
    const float w1a = w1[d], w1b = w1[d + 1];
    const float w3a = w3[d], w3b = w3[d + 1];
    __half2* cwb = (__half2*)(cw3 + (long long)b * LC * DIM);
#pragma unroll
    for (int r = 0; r < 4; r++) {
        int l = l0 + ty + r * 8;
        float2 v = reinterpret_cast<const float2*>(x)[((long long)b * SEQ + l) * (DIM / 2) + (d >> 1)];
        sm[tx * 2][ty + r * 8]     = v.x;
        sm[tx * 2 + 1][ty + r * 8] = v.y;
        cwb[(long long)l * (DIM / 2) + (d >> 1)] = __floats2half2_rn(v.x * w3a, v.y * w3b);
        float s = v.x * w1a + v.y * w1b;
#pragma unroll
        for (int o = 16; o > 0; o >>= 1) s += __shfl_down_sync(0xffffffffu, s, o);
        if (tx == 0)
            cpart[(long long)blockIdx.y * (BATCH * LC) + (long long)b * LC + l] = s;
    }
    __syncthreads();
    __half2* ctb = (__half2*)(ct + (long long)b * SE);
#pragma unroll
    for (int it = 0; it < 4; it++) {
        int idx = threadIdx.x + it * 256;
        int dd = idx >> 4, l2 = idx & 15;
        ctb[(long long)(d0 + dd) * (LC / 2) + (l0 >> 1) + l2] =
            __floats2half2_rn(sm[dd][l2 * 2], sm[dd][l2 * 2 + 1]);
    }
}

__global__ void c1red_k(const float* __restrict__ cpart, float* __restrict__ c1)
{
    int i = blockIdx.x * 256 + threadIdx.x;
    if (i >= BATCH * LC) return;
    float s = 0.f;
#pragma unroll
    for (int c = 0; c < NCHUNK; c++)
        s += cpart[(long long)c * (BATCH * LC) + i];
    c1[i] = s;
}

// row softmax, float in -> fp16 out (front-end S, len=448)
__global__ void softmax_rows_f16_k(const float* __restrict__ in,
                                   __half* __restrict__ out, int len)
{
    long long base = (long long)blockIdx.x * len;
    int t = threadIdx.x;
    __shared__ float sh[128];
    float m = -1e30f;
    for (int i = t; i < len; i += 128) m = fmaxf(m, in[base + i]);
    sh[t] = m; __syncthreads();
    for (int o = 64; o > 0; o >>= 1) { if (t < o) sh[t] = fmaxf(sh[t], sh[t + o]); __syncthreads(); }
    m = sh[0]; __syncthreads();
    float s = 0.f;
    float loc[4];
    for (int i = t, c = 0; i < len; i += 128, c++) { float e = expf(in[base + i] - m); loc[c] = e; s += e; }
    sh[t] = s; __syncthreads();
    for (int o = 64; o > 0; o >>= 1) { if (t < o) sh[t] += sh[t + o]; __syncthreads(); }
    float inv = 1.f / sh[0];
    for (int i = t, c = 0; i < len; i += 128, c++)
        out[base + i] = __float2half(loc[c] * inv);
}

// tiled column softmax over i of S (B,64,448) -> fp16; coalesced
// grid (LQ/64, BATCH), 256 threads; tile 64 i x 64 j in smem
__global__ void softmax_cols_tile_k(const float* __restrict__ S, __half* __restrict__ out)
{
    __shared__ float sm[64][65];
    __shared__ float rinv[64];
    const int j0 = blockIdx.x * 64, b = blockIdx.y;
    const int tid = threadIdx.x;
    const float* Sb = S + (long long)b * LC * LQ;
#pragma unroll
    for (int it = 0; it < 16; it++) {
        int idx = tid + it * 256;
        int i = idx >> 6, j = idx & 63;
        sm[i][j] = Sb[(long long)i * LQ + j0 + j];
    }
    __syncthreads();
    if (tid < 64) {
        const int j = tid;
        float m = -1e30f;
#pragma unroll 8
        for (int i = 0; i < 64; i++) m = fmaxf(m, sm[i][j]);
        float s = 0.f;
#pragma unroll 8
        for (int i = 0; i < 64; i++) { float e = expf(sm[i][j] - m); sm[i][j] = e; s += e; }
        rinv[j] = 1.f / s;
    }
    __syncthreads();
    __half* ob = out + (long long)b * LC * LQ;
#pragma unroll
    for (int it = 0; it < 16; it++) {
        int idx = tid + it * 256;
        int i = idx >> 6, j = idx & 63;
        ob[(long long)i * LQ + j0 + j] = __float2half(sm[i][j] * rinv[j]);
    }
}

// smem-tiled concat-gather + depthwise k=5 -> Y fp16 (b,l,c)
__global__ void __launch_bounds__(256) rz_dw_tile_k(
    const float* __restrict__ x, const float* __restrict__ Abuf,
    const float* __restrict__ Btbuf,
    const float* __restrict__ dww, const float* __restrict__ dwb,
    __half* __restrict__ Y)
{
    extern __shared__ float sb[];
    float* xs = sb;
    float* as = sb + 64 * 128;
    float* bs = sb + 2 * 64 * 128;

    const int d0 = blockIdx.x * 128;
    const int b  = blockIdx.y;
    const int tid = threadIdx.x;

    {
        const float4* xp = reinterpret_cast<const float4*>(x + ((long long)b * SEQ) * DIM);
        const float4* ap = reinterpret_cast<const float4*>(Abuf + (long long)b * LC * DIM);
        const float4* bp = reinterpret_cast<const float4*>(Btbuf + (long long)b * LC * DIM);
        const int d04 = d0 >> 2;
#pragma unroll
        for (int it = 0; it < 8; it++) {
            int idx = tid + it * 256;
            int l = idx >> 5, c4 = idx & 31;
            reinterpret_cast<float4*>(xs)[idx] = xp[(long long)l * (DIM / 4) + d04 + c4];
            reinterpret_cast<float4*>(as)[idx] = ap[(long long)l * (DIM / 4) + d04 + c4];
            reinterpret_cast<float4*>(bs)[idx] = bp[(long long)l * (DIM / 4) + d04 + c4];
        }
    }
    __syncthreads();

    const int dd = tid & 127;
    const int lbase = tid >> 7;
    __half* Yb = Y + (long long)b * LC * C4;

#pragma unroll
    for (int g = 0; g < 4; g++) {
        const int c = g * DIM + d0 + dd;
        const float bias = dwb[c];
        float wv[5];
#pragma unroll
        for (int t = 0; t < 5; t++) wv[t] = dww[c * 5 + t];

#pragma unroll
        for (int it = 0; it < 32; it++) {
            const int l = lbase + it * 2;
            float acc = bias;
#pragma unroll
            for (int t = 0; t < 5; t++) {
                int l2 = l + t - 2;
                if (l2 < 0 || l2 >= LC) continue;
                float v;
                int o = l2 * 128 + dd;
                if (g == 0)      v = xs[o];
                else if (g == 1) v = as[o];
                else if (g == 2) v = xs[o] * as[o];
                else             v = xs[o] * bs[o];
                acc = fmaf(v, wv[t], acc);
            }
            Yb[(long long)l * C4 + c] = __float2half(acc);
        }
    }
}

__global__ void pe_init_k(float* __restrict__ pe)
{
    int idx = blockIdx.x * 256 + threadIdx.x;
    if (idx >= DIM * LC) return;
    int d = idx / LC, l = idx % LC;
    float fd = (float)d;
    bool even = (d & 1) == 0;
    float freq = even ? powf(10000.f, -fd / 768.f)
                      : -powf(10000.f, (1.f - fd) / 768.f);
    float ph = even ? 0.f : 1.57079632679489662f;
    pe[idx] = sinf((float)l * freq + ph);
}

__global__ void final_head_k(const float* __restrict__ X, const float* __restrict__ w,
                             const float* __restrict__ bias, float* __restrict__ out)
{
    int b = blockIdx.x;
    const float* p = X + (long long)b * (DIM * LC);
    float s = 0.f;
    for (int i = threadIdx.x; i < DIM * LC; i += 256) s = fmaf(p[i], w[i], s);
    __shared__ float sh[256];
    sh[threadIdx.x] = s; __syncthreads();
    for (int o = 128; o > 0; o >>= 1) {
        if (threadIdx.x < o) sh[threadIdx.x] += sh[threadIdx.x + o];
        __syncthreads();
    }
    if (threadIdx.x == 0) out[b] = 1.f / (1.f + expf(-(sh[0] + bias[0])));
}

// ---------------------------------------------------------------------------
// Host-side helpers
// ---------------------------------------------------------------------------
template<int OMODE>
static inline void run_mgemm(const __half* Af, const __half* Bf,
                             float* O, __half* Oh, long long sO, int ldo,
                             const float* bias,
                             const float* R, long long sR,
                             const float* plane, float* psum,
                             int N, int K, int relu)
{
    cudaFuncSetAttribute((const void*)mgemm_k<OMODE>,
                         cudaFuncAttributeMaxDynamicSharedMemorySize, MT_SMEM);
    dim3 grid(N / 128, BATCH / 2);
    mgemm_k<OMODE><<<grid, 256, MT_SMEM>>>(Af, Bf, O, Oh, sO, ldo, bias, R, sR, plane, psum, K, relu);
}

static inline void run_pgemm(const __half* Af, long long sA, int lda,
                             const __half* Bf, long long sB, int ldb,
                             float* O, __half* Oh, long long sO, int ldo,
                             const float* bM, long long sbM,
                             const float* bN, long long sbN,
                             float alpha, int N, int K)
{
    cudaFuncSetAttribute((const void*)pgemm_k,
                         cudaFuncAttributeMaxDynamicSharedMemorySize, PG_SMEM);
    dim3 grid(N / 64, BATCH);
    pgemm_k<<<grid, 256, PG_SMEM>>>(Af, sA, lda, Bf, sB, ldb, O, Oh, sO, ldo,
                                    bM, sbM, bN, sbN, alpha, K);
}

static inline void run_pgemm_sm(const __half* Af, long long sA, int lda,
                                const __half* Bf, long long sB, int ldb,
                                __half* Oh, long long sO, float alpha, int K)
{
    cudaFuncSetAttribute((const void*)pgemm_sm_k,
                         cudaFuncAttributeMaxDynamicSharedMemorySize, PG_SMEM);
    dim3 grid(1, BATCH);
    pgemm_sm_k<<<grid, 256, PG_SMEM>>>(Af, sA, lda, Bf, sB, ldb, Oh, sO, alpha, K);
}

struct EncW {
    const float *c1dw, *c1db, *c1pw, *c1pb;
    const float *c2dw, *c2db, *c2pw, *c2pb;
    const float *wq, *wk, *wv, *wo;
    const float *fcw, *fcb;
    const float *nbw, *nbb, *n1w, *n1b, *n2w, *n2b, *nEw, *nEb;
};

struct HfW {
    __half *rz, *c1, *c2, *fc, *qkv, *wo;
};

// Xin's LN stats must already be in psum (written by the producing mgemm).
static void enc_block(const float* Xin,
                      float* t2, float* t3,
                      __half* qkf, __half* vT, __half* attnf,
                      float* Xout, const float* outPlane, float* outPsum,
                      float* psum,
                      const EncW& w, const HfW& hw,
                      __half* a1, __half* a2)
{
    const float scale = 0.03608439182435161f; // 1/sqrt(768)
    const long long SQK = 64LL * 1536;
    const long long SAT = 64LL * 64;

    ln_conv_t_k<<<dim3(BATCH, 24), 256>>>(Xin, psum, w.nbw, w.nbb, w.c1dw, w.c1db, a1);
    run_mgemm<1>(a1, hw.c1, t2, nullptr, SE, 64, w.c1pb, Xin, SE, nullptr, psum, DIM, DIM, 1);
    ln_conv_t_k<<<dim3(BATCH, 24), 256>>>(t2, psum, w.n1w, w.n1b, w.c2dw, w.c2db, a1);
    run_mgemm<1>(a1, hw.c2, t3, nullptr, SE, 64, w.c2pb, t2, SE, nullptr, psum, DIM, DIM, 1);
    ln_apply_t_k<<<dim3(BATCH, 24), 256>>>(t3, psum, w.n2w, w.n2b, a1);
    run_mgemm<0>(a1, hw.qkv, nullptr, qkf, SQK, 1536, nullptr, nullptr, 0, nullptr, nullptr, 1536, DIM, 0);
    run_mgemm<1>(a1, hw.qkv + 2LL * DIM * DIM, nullptr, vT, SE, 64,
                 nullptr, nullptr, 0, nullptr, nullptr, DIM, DIM, 0);
    run_pgemm_sm(qkf, SQK, 1536, qkf + DIM, SQK, 1536, attnf, SAT, scale, DIM);
    run_pgemm(attnf, SAT, 64, vT, SE, 64,
              nullptr, a2, SE, DIM, nullptr, 0, nullptr, 0, 1.f, DIM, LC);
    run_mgemm<1>(a2, hw.wo, t2, nullptr, SE, 64, nullptr, t3, SE, nullptr, psum, DIM, DIM, 0);
    ln_apply_t_k<<<dim3(BATCH, 24), 256>>>(t2, psum, w.nEw, w.nEb, a1);
    run_mgemm<1>(a1, hw.fc, Xout, nullptr, SE, 64, w.fcb, t2, SE, outPlane, outPsum, DIM, DIM, 1);
}

// ---------------------------------------------------------------------------
// Entry point
// ---------------------------------------------------------------------------
extern "C" void kernel_launch(void* const* d_in, const int* in_sizes, int n_in,
                              void* d_out, int out_size)
{
    (void)in_sizes; (void)n_in; (void)out_size;
    const float* x       = (const float*)d_in[0];
    const float* Wv      = (const float*)d_in[1];
    const float* rz_dw_w = (const float*)d_in[2];
    const float* rz_dw_b = (const float*)d_in[3];
    const float* rz_pw_w = (const float*)d_in[4];
    const float* rz_pw_b = (const float*)d_in[5];
    EncW w;
    w.c1dw = (const float*)d_in[6];  w.c1db = (const float*)d_in[7];
    w.c1pw = (const float*)d_in[8];  w.c1pb = (const float*)d_in[9];
    w.c2dw = (const float*)d_in[10]; w.c2db = (const float*)d_in[11];
    w.c2pw = (const float*)d_in[12]; w.c2pb = (const float*)d_in[13];
    w.wq   = (const float*)d_in[14]; w.wk   = (const float*)d_in[15];
    w.wv   = (const float*)d_in[16]; w.wo   = (const float*)d_in[17];
    w.fcw  = (const float*)d_in[18]; w.fcb  = (const float*)d_in[19];
    w.nbw  = (const float*)d_in[20]; w.nbb  = (const float*)d_in[21];
    w.n1w  = (const float*)d_in[22]; w.n1b  = (const float*)d_in[23];
    w.n2w  = (const float*)d_in[24]; w.n2b  = (const float*)d_in[25];
    w.nEw  = (const float*)d_in[26]; w.nEb  = (const float*)d_in[27];
    const float* fcf_w = (const float*)d_in[28];
    const float* fcf_b = (const float*)d_in[29];

    float* pool = nullptr;
    cudaGetSymbolAddress((void**)&pool, g_pool);

    float* c1s  = pool + OFF_C1;
    float* q2s  = pool + OFF_Q2;
    float* S    = pool + OFF_S;
    float* Abuf = pool + OFF_A;
    float* Btb  = pool + OFF_BT;
    float* E[8];
    for (int i = 0; i < 8; i++) E[i] = pool + OFF_E0 + (long long)i * SZ_E;
    float* pe   = pool + OFF_PE;
    float* psum = pool + OFF_PS;
    float* qpart = pool + OFF_Y;
    float* cpart = pool + OFF_Y + (long long)NCHUNK * BATCH * LQ;

    __half* cw3f  = (__half*)(pool + OFF_CW3);
    __half* S1f   = (__half*)(pool + OFF_S1);
    __half* S2f   = (__half*)(pool + OFF_S2);
    __half* Yf    = (__half*)(pool + OFF_Y);
    __half* Qsf   = (__half*)(pool + OFF_QS);
    __half* Qtf   = (__half*)(pool + OFF_QT);
    __half* a1    = (__half*)(pool + OFF_ACT);
    __half* a2    = a1 + SZ_BD;
    __half* qkf   = (__half*)E[4];
    __half* vT    = (__half*)E[5];
    __half* attnf = (__half*)E[6];
    __half* Tf    = (__half*)E[6];
    __half* cTf   = (__half*)E[1];

    HfW hw;
    {
        __half* p = (__half*)(pool + OFF_WB);
        hw.rz  = p; p += (long long)DIM * C4;
        hw.c1  = p; p += (long long)DIM * DIM;
        hw.c2  = p; p += (long long)DIM * DIM;
        hw.fc  = p; p += (long long)DIM * DIM;
        hw.qkv = p; p += 3LL * DIM * DIM;
        hw.wo  = p;
    }

    const long long WDD = (long long)DIM * DIM;

    pe_init_k<<<(DIM * LC + 255) / 256, 256>>>(pe);
    cboth_k<<<dim3(2, NCHUNK, BATCH), 256>>>(x, Wv, Wv + 2 * DIM, cw3f, cTf, cpart);
    c1red_k<<<(BATCH * LC + 255) / 256, 256>>>(cpart, c1s);
    qboth_k<<<dim3(LQ / 32, NCHUNK, BATCH), 256>>>(x, Wv + DIM, Qsf, Qtf, qpart);
    q2red_k<<<(BATCH * LQ + 255) / 256, 256>>>(qpart, q2s);

    // S = cw3 @ Q^T + c1[:,None] + q2[None,:]   (tensor, per-batch)
    run_pgemm(cw3f, 64LL * DIM, DIM, Qsf, (long long)LQ * DIM, DIM,
              S, nullptr, (long long)LC * LQ, LQ, c1s, LC, q2s, LQ, 1.f, LQ, DIM);

    softmax_rows_f16_k<<<BATCH * LC, 128>>>(S, S1f, LQ);
    softmax_cols_tile_k<<<dim3(LQ / 64, BATCH), 256>>>(S, S2f);

    // A = S1 @ Q (tensor; B = Q^T) -> fp32
    run_pgemm(S1f, (long long)LC * LQ, LQ, Qtf, (long long)DIM * LQ, LQ,
              Abuf, nullptr, (long long)LC * DIM, DIM, nullptr, 0, nullptr, 0, 1.f, DIM, LQ);

    // T = S1 @ S2^T (tensor) -> fp16
    run_pgemm(S1f, (long long)LC * LQ, LQ, S2f, (long long)LC * LQ, LQ,
              nullptr, Tf, (long long)LC * LC, LC, nullptr, 0, nullptr, 0, 1.f, LC, LQ);

    // Bt = T @ C (tensor; B = C^T) -> fp32
    run_pgemm(Tf, (long long)LC * LC, LC, cTf, SE, LC,
              Btb, nullptr, (long long)LC * DIM, DIM, nullptr, 0, nullptr, 0, 1.f, DIM, LC);

    // smem-tiled concat-gather + depthwise k=5 -> Y fp16 (b,l,c)
    cudaFuncSetAttribute((const void*)rz_dw_tile_k,
                         cudaFuncAttributeMaxDynamicSharedMemorySize, RZ_SMEM);
    rz_dw_tile_k<<<dim3(DIM / 128, BATCH), 256, RZ_SMEM>>>(x, Abuf, Btb, rz_dw_w, rz_dw_b, Yf);

    // ---- weight conversion (fp16, n x k, k-contiguous) ----
    {
        long long trz = (long long)DIM * C4;
        wconv_k<<<(int)((trz + 255) / 256), 256>>>(rz_pw_w, C4, 0, trz, C4, hw.rz);
        int gs = (int)((WDD + 255) / 256);
        wconv7_k<<<dim3(gs, 7), 256>>>(w.c1pw, w.c2pw, w.fcw, w.wq, w.wk, w.wv, w.wo, hw.c1);
    }

    // pointwise 3072 -> 768 (mma): +bias +pe -> E0 (b,d,l), + LN stats
    run_mgemm<1>(Yf, hw.rz, E[0], nullptr, SE, 64, rz_pw_b, nullptr, 0, pe, psum, DIM, C4, 0);

    // ---- two encoder blocks ----
    enc_block(E[0], E[2], E[3], qkf, vT, attnf, E[7], pe, psum, psum, w, hw, a1, a2);
    enc_block(E[7], E[2], E[3], qkf, vT, attnf, E[0], nullptr, nullptr, psum, w, hw, a1, a2);

    // ---- final sigmoid head ----
    final_head_k<<<BATCH, 256>>>(E[0], fcf_w, fcf_b, (float*)d_out);
}